// round 1
// baseline (speedup 1.0000x reference)
#include <cuda_runtime.h>
#include <math.h>

#define D      768
#define T      1024
#define BATCH  8
#define M_TOT  (BATCH*T)   // 8192
#define NH     12
#define DH     64

// ---------------- scratch (device globals: alloc-free rule) ----------------
__device__ float g_xn[(size_t)M_TOT * D];
__device__ float g_q [(size_t)M_TOT * D];
__device__ float g_k [(size_t)M_TOT * D];
__device__ float g_v [(size_t)M_TOT * D];
__device__ float g_g [(size_t)M_TOT * D];
__device__ float g_y [(size_t)M_TOT * D];

// ---------------- LayerNorm + (B,C,H,W) -> (B*T, C) transpose --------------
// one block per token, 256 threads, 3 channels per thread
__global__ __launch_bounds__(256)
void ln_kernel(const float* __restrict__ x,
               const float* __restrict__ gamma,
               const float* __restrict__ beta)
{
    const int token = blockIdx.x;          // 0..8191
    const int b = token >> 10;
    const int t = token & 1023;
    const float* xp = x + (size_t)b * D * T + t;

    const int c0 = threadIdx.x;
    const float v0 = xp[(size_t)(c0       ) * T];
    const float v1 = xp[(size_t)(c0 + 256 ) * T];
    const float v2 = xp[(size_t)(c0 + 512 ) * T];

    float s  = v0 + v1 + v2;
    float ss = v0 * v0 + v1 * v1 + v2 * v2;

    #pragma unroll
    for (int o = 16; o > 0; o >>= 1) {
        s  += __shfl_xor_sync(0xffffffffu, s,  o);
        ss += __shfl_xor_sync(0xffffffffu, ss, o);
    }
    __shared__ float red_s[8], red_ss[8];
    const int wid = threadIdx.x >> 5, lane = threadIdx.x & 31;
    if (lane == 0) { red_s[wid] = s; red_ss[wid] = ss; }
    __syncthreads();
    float sum = 0.f, sumsq = 0.f;
    #pragma unroll
    for (int i = 0; i < 8; i++) { sum += red_s[i]; sumsq += red_ss[i]; }

    const float mu  = sum * (1.0f / (float)D);
    const float var = sumsq * (1.0f / (float)D) - mu * mu;
    const float rs  = rsqrtf(var + 1e-5f);

    float* o = g_xn + (size_t)token * D;
    o[c0      ] = (v0 - mu) * rs * gamma[c0      ] + beta[c0      ];
    o[c0 + 256] = (v1 - mu) * rs * gamma[c0 + 256] + beta[c0 + 256];
    o[c0 + 512] = (v2 - mu) * rs * gamma[c0 + 512] + beta[c0 + 512];
}

// ---------------- SGEMM: C = A(MxK) * W(NxK)^T + bias ----------------------
// 128x128 block tile, BK=16, 256 threads, 8x8 microtile
// ACT: 0 none, 1 sigmoid.  TRANS: 0 row-major C[m][n], 1 write (B,C,H,W).
template<int ACT, int TRANS>
__global__ __launch_bounds__(256)
void gemm_nt(const float* __restrict__ A,
             const float* __restrict__ Wt,
             const float* __restrict__ bias,
             float* __restrict__ Cout)
{
    __shared__ float As[16][128];
    __shared__ float Ws[16][128];

    const int tid = threadIdx.x;
    const int tx  = tid & 15;    // 0..15 (n)
    const int ty  = tid >> 4;    // 0..15 (m)
    const int m0  = blockIdx.y * 128;
    const int n0  = blockIdx.x * 128;

    float acc[8][8];
    #pragma unroll
    for (int i = 0; i < 8; i++)
        #pragma unroll
        for (int j = 0; j < 8; j++) acc[i][j] = 0.f;

    for (int kt = 0; kt < D; kt += 16) {
        #pragma unroll
        for (int s = tid; s < 512; s += 256) {
            const int r  = s >> 2;
            const int kq = (s & 3) * 4;
            const float4 av = *(const float4*)(A  + (size_t)(m0 + r) * D + kt + kq);
            As[kq + 0][r] = av.x; As[kq + 1][r] = av.y;
            As[kq + 2][r] = av.z; As[kq + 3][r] = av.w;
            const float4 wv = *(const float4*)(Wt + (size_t)(n0 + r) * D + kt + kq);
            Ws[kq + 0][r] = wv.x; Ws[kq + 1][r] = wv.y;
            Ws[kq + 2][r] = wv.z; Ws[kq + 3][r] = wv.w;
        }
        __syncthreads();

        #pragma unroll
        for (int k = 0; k < 16; k++) {
            const float4 a0 = *(const float4*)&As[k][ty * 8];
            const float4 a1 = *(const float4*)&As[k][ty * 8 + 4];
            const float4 w0 = *(const float4*)&Ws[k][tx * 8];
            const float4 w1 = *(const float4*)&Ws[k][tx * 8 + 4];
            const float a[8] = {a0.x, a0.y, a0.z, a0.w, a1.x, a1.y, a1.z, a1.w};
            const float w[8] = {w0.x, w0.y, w0.z, w0.w, w1.x, w1.y, w1.z, w1.w};
            #pragma unroll
            for (int i = 0; i < 8; i++)
                #pragma unroll
                for (int j = 0; j < 8; j++)
                    acc[i][j] += a[i] * w[j];
        }
        __syncthreads();
    }

    #pragma unroll
    for (int i = 0; i < 8; i++) {
        const int m = m0 + ty * 8 + i;
        #pragma unroll
        for (int j = 0; j < 8; j++) {
            const int n = n0 + tx * 8 + j;
            float v = acc[i][j] + bias[n];
            if (ACT == 1) v = 1.0f / (1.0f + __expf(-v));
            if (TRANS == 0) {
                Cout[(size_t)m * D + n] = v;
            } else {
                const int b = m >> 10, t = m & 1023;
                Cout[((size_t)b * D + n) * T + t] = v;
            }
        }
    }
}

// ---------------- Flash attention (fp32) + gate ----------------------------
// grid (qtile=8, head=12, batch=8), 128 threads, 1 query row per thread.
// dynamic smem: Ks[64][68] + Vs[64][68] + Ss[128][65] = 68096 B
#define KPAD 68
#define SPAD 65

__global__ __launch_bounds__(128)
void attn_kernel()
{
    extern __shared__ float sm[];
    float* Ks = sm;                       // 64*68
    float* Vs = sm + 64 * KPAD;           // 64*68
    float* Ss = sm + 2 * 64 * KPAD;       // 128*65

    const int r  = threadIdx.x;           // query row within tile
    const int qt = blockIdx.x;
    const int h  = blockIdx.y;
    const int b  = blockIdx.z;
    const int row = b * T + qt * 128 + r;
    const size_t coff = (size_t)row * D + h * DH;

    float q[DH];
    #pragma unroll
    for (int k = 0; k < DH; k += 4) {
        const float4 v = *(const float4*)(g_q + coff + k);
        q[k] = v.x; q[k + 1] = v.y; q[k + 2] = v.z; q[k + 3] = v.w;
    }

    float accv[DH];
    #pragma unroll
    for (int k = 0; k < DH; k++) accv[k] = 0.f;
    float mrun = -INFINITY, l = 0.f;

    for (int kt = 0; kt < 16; kt++) {
        const int krow0 = b * T + kt * 64;
        #pragma unroll
        for (int s = r; s < 1024; s += 128) {
            const int j  = s >> 4;
            const int kq = (s & 15) * 4;
            const size_t goff = (size_t)(krow0 + j) * D + h * DH + kq;
            *(float4*)&Ks[j * KPAD + kq] = *(const float4*)(g_k + goff);
            *(float4*)&Vs[j * KPAD + kq] = *(const float4*)(g_v + goff);
        }
        __syncthreads();

        float tmax = -INFINITY;
        #pragma unroll 4
        for (int j = 0; j < 64; j++) {
            float s = 0.f;
            #pragma unroll
            for (int k = 0; k < DH; k += 4) {
                const float4 kv = *(const float4*)&Ks[j * KPAD + k];
                s += q[k] * kv.x + q[k + 1] * kv.y + q[k + 2] * kv.z + q[k + 3] * kv.w;
            }
            s *= 0.125f;  // 1/sqrt(64)
            Ss[r * SPAD + j] = s;
            tmax = fmaxf(tmax, s);
        }

        const float mnew = fmaxf(mrun, tmax);
        const float corr = __expf(mrun - mnew);
        l *= corr;
        #pragma unroll
        for (int k = 0; k < DH; k++) accv[k] *= corr;

        #pragma unroll 2
        for (int j = 0; j < 64; j++) {
            const float p = __expf(Ss[r * SPAD + j] - mnew);
            l += p;
            #pragma unroll
            for (int k = 0; k < DH; k += 4) {
                const float4 vv = *(const float4*)&Vs[j * KPAD + k];
                accv[k]     += p * vv.x;
                accv[k + 1] += p * vv.y;
                accv[k + 2] += p * vv.z;
                accv[k + 3] += p * vv.w;
            }
        }
        mrun = mnew;
        __syncthreads();
    }

    const float inv = 1.0f / l;
    #pragma unroll
    for (int k = 0; k < DH; k += 4) {
        const float4 gv = *(const float4*)(g_g + coff + k);
        float4 ov;
        ov.x = accv[k]     * inv * gv.x;
        ov.y = accv[k + 1] * inv * gv.y;
        ov.z = accv[k + 2] * inv * gv.z;
        ov.w = accv[k + 3] * inv * gv.w;
        *(float4*)(g_y + coff + k) = ov;
    }
}

// ---------------- launch ---------------------------------------------------
extern "C" void kernel_launch(void* const* d_in, const int* in_sizes, int n_in,
                              void* d_out, int out_size)
{
    const float* x     = (const float*)d_in[0];
    const float* Wq    = (const float*)d_in[1];
    const float* bq    = (const float*)d_in[2];
    const float* Wk    = (const float*)d_in[3];
    const float* bk    = (const float*)d_in[4];
    const float* Wv    = (const float*)d_in[5];
    const float* bv    = (const float*)d_in[6];
    const float* Wo    = (const float*)d_in[7];
    const float* bo    = (const float*)d_in[8];
    const float* Wg    = (const float*)d_in[9];
    const float* bg    = (const float*)d_in[10];
    const float* gamma = (const float*)d_in[11];
    const float* beta  = (const float*)d_in[12];
    float* out = (float*)d_out;

    void *p_xn, *p_q, *p_k, *p_v, *p_g, *p_y;
    cudaGetSymbolAddress(&p_xn, g_xn);
    cudaGetSymbolAddress(&p_q,  g_q);
    cudaGetSymbolAddress(&p_k,  g_k);
    cudaGetSymbolAddress(&p_v,  g_v);
    cudaGetSymbolAddress(&p_g,  g_g);
    cudaGetSymbolAddress(&p_y,  g_y);
    float* xn = (float*)p_xn;
    float* qb = (float*)p_q;
    float* kb = (float*)p_k;
    float* vb = (float*)p_v;
    float* gb = (float*)p_g;
    float* yb = (float*)p_y;

    const int attn_smem = (2 * 64 * KPAD + 128 * SPAD) * (int)sizeof(float); // 68096
    cudaFuncSetAttribute(attn_kernel, cudaFuncAttributeMaxDynamicSharedMemorySize, attn_smem);

    // 1) LayerNorm + transpose
    ln_kernel<<<M_TOT, 256>>>(x, gamma, beta);

    // 2) Q/K/V/gate projections
    const dim3 ggrid(D / 128, M_TOT / 128);   // (6, 64)
    gemm_nt<0, 0><<<ggrid, 256>>>(xn, Wq, bq, qb);
    gemm_nt<0, 0><<<ggrid, 256>>>(xn, Wk, bk, kb);
    gemm_nt<0, 0><<<ggrid, 256>>>(xn, Wv, bv, vb);
    gemm_nt<1, 0><<<ggrid, 256>>>(xn, Wg, bg, gb);

    // 3) attention + gate
    attn_kernel<<<dim3(8, NH, BATCH), 128, attn_smem>>>();

    // 4) output projection + transpose back to (B,C,H,W)
    gemm_nt<0, 1><<<ggrid, 256>>>(yb, Wo, bo, out);
}

// round 2
// speedup vs baseline: 2.0427x; 2.0427x over previous
#include <cuda_runtime.h>
#include <math.h>

#define D      768
#define T      1024
#define BATCH  8
#define M_TOT  (BATCH*T)   // 8192
#define NH     12
#define DH     64

// ---------------- scratch (device globals: alloc-free rule) ----------------
__device__ float g_xn_hi[(size_t)M_TOT * D];
__device__ float g_xn_lo[(size_t)M_TOT * D];
__device__ float g_q [(size_t)M_TOT * D];
__device__ float g_k [(size_t)M_TOT * D];
__device__ float g_v [(size_t)M_TOT * D];
__device__ float g_g [(size_t)M_TOT * D];
__device__ float g_y_hi[(size_t)M_TOT * D];
__device__ float g_y_lo[(size_t)M_TOT * D];
// weight splits (hi/lo tf32)
__device__ float g_wq_hi[D*D], g_wq_lo[D*D];
__device__ float g_wk_hi[D*D], g_wk_lo[D*D];
__device__ float g_wv_hi[D*D], g_wv_lo[D*D];
__device__ float g_wg_hi[D*D], g_wg_lo[D*D];
__device__ float g_wo_hi[D*D], g_wo_lo[D*D];

__device__ __forceinline__ float f2tf32(float x) {
    float r;
    asm("cvt.rna.tf32.f32 %0, %1;" : "=f"(r) : "f"(x));
    return r;
}

// ---------------- weight split: w -> (hi, lo) tf32 pair --------------------
__global__ __launch_bounds__(256)
void split_w(const float* __restrict__ w, float* __restrict__ hi,
             float* __restrict__ lo, int n)
{
    int i = blockIdx.x * 256 + threadIdx.x;
    if (i < n) {
        float v = w[i];
        float h = f2tf32(v);
        hi[i] = h;
        lo[i] = f2tf32(v - h);
    }
}

// ---------------- LayerNorm + transpose + tf32 split -----------------------
__global__ __launch_bounds__(256)
void ln_kernel(const float* __restrict__ x,
               const float* __restrict__ gamma,
               const float* __restrict__ beta)
{
    const int token = blockIdx.x;
    const int b = token >> 10;
    const int t = token & 1023;
    const float* xp = x + (size_t)b * D * T + t;

    const int c0 = threadIdx.x;
    const float v0 = xp[(size_t)(c0      ) * T];
    const float v1 = xp[(size_t)(c0 + 256) * T];
    const float v2 = xp[(size_t)(c0 + 512) * T];

    float s  = v0 + v1 + v2;
    float ss = v0 * v0 + v1 * v1 + v2 * v2;
    #pragma unroll
    for (int o = 16; o > 0; o >>= 1) {
        s  += __shfl_xor_sync(0xffffffffu, s,  o);
        ss += __shfl_xor_sync(0xffffffffu, ss, o);
    }
    __shared__ float red_s[8], red_ss[8];
    const int wid = threadIdx.x >> 5, lane = threadIdx.x & 31;
    if (lane == 0) { red_s[wid] = s; red_ss[wid] = ss; }
    __syncthreads();
    float sum = 0.f, sumsq = 0.f;
    #pragma unroll
    for (int i = 0; i < 8; i++) { sum += red_s[i]; sumsq += red_ss[i]; }

    const float mu  = sum * (1.0f / (float)D);
    const float var = sumsq * (1.0f / (float)D) - mu * mu;
    const float rs  = rsqrtf(var + 1e-5f);

    float* oh = g_xn_hi + (size_t)token * D;
    float* ol = g_xn_lo + (size_t)token * D;
    #pragma unroll
    for (int j = 0; j < 3; j++) {
        const int c = c0 + j * 256;
        const float v = (j == 0 ? v0 : (j == 1 ? v1 : v2));
        const float y = (v - mu) * rs * gamma[c] + beta[c];
        const float h = f2tf32(y);
        oh[c] = h;
        ol[c] = f2tf32(y - h);
    }
}

// ---------------- tf32 tensor-core GEMM (3xTF32) ----------------------------
// C = A(MxK) * W(NxK)^T + bias ; A,W given as (hi,lo) tf32 splits.
// 128x128 block tile, BK=16, 256 threads, 2-stage cp.async pipeline.
// MODE 0: fused 4-region (region = blockIdx.x/6), sigmoid on region 3.
// MODE 1: single region, output written transposed to (B,C,H,W).

struct GemmArgs {
    const float* Bh[4];
    const float* Bl[4];
    const float* bias[4];
    float*       C[4];
};

__device__ __forceinline__ void mma_tf32(float* d, const unsigned* a, const unsigned* b) {
    asm volatile(
        "mma.sync.aligned.m16n8k8.row.col.f32.tf32.tf32.f32 "
        "{%0,%1,%2,%3}, {%4,%5,%6,%7}, {%8,%9}, {%0,%1,%2,%3};"
        : "+f"(d[0]), "+f"(d[1]), "+f"(d[2]), "+f"(d[3])
        : "r"(a[0]), "r"(a[1]), "r"(a[2]), "r"(a[3]), "r"(b[0]), "r"(b[1]));
}

#define SROW 20            // padded smem row stride (floats) -> conflict-free frags
#define STGF 10240         // floats per pipeline stage (4 matrices * 128*20)

template<int MODE>
__global__ __launch_bounds__(256, 2)
void gemm_mma(const float* __restrict__ Agh, const float* __restrict__ Agl,
              GemmArgs args)
{
    extern __shared__ float sm[];
    const int tid = threadIdx.x;
    const int m0  = blockIdx.y * 128;

    int region, nloc0;
    if (MODE == 0) { region = blockIdx.x / 6; nloc0 = (blockIdx.x % 6) * 128; }
    else           { region = 0;              nloc0 = blockIdx.x * 128; }
    const float* Bh   = args.Bh[region];
    const float* Bl   = args.Bl[region];
    const float* bias = args.bias[region];
    float*       C    = args.C[region];

    // -------- cooperative load setup (8 cp.async.16B per thread per stage) --
    const int ra = tid >> 2;            // 0..63
    const int kq = (tid & 3) * 4;       // 0,4,8,12
    const float* pAh = Agh + (size_t)(m0 + ra) * D + kq;
    const float* pAl = Agl + (size_t)(m0 + ra) * D + kq;
    const float* pBh = Bh  + (size_t)(nloc0 + ra) * D + kq;
    const float* pBl = Bl  + (size_t)(nloc0 + ra) * D + kq;
    const unsigned sbase = (unsigned)__cvta_generic_to_shared(sm);
    const unsigned soA = (unsigned)((ra * SROW + kq) * 4);

    #define CPASYNC(dst, src) \
        asm volatile("cp.async.cg.shared.global [%0], [%1], 16;" :: "r"(dst), "l"(src) : "memory")

    auto load_stage = [&](int kt, int buf) {
        const unsigned b0 = sbase + (unsigned)buf * (STGF * 4) + soA;
        CPASYNC(b0 +     0u, pAh + kt);
        CPASYNC(b0 +  5120u, pAh + 64 * D + kt);
        CPASYNC(b0 + 10240u, pAl + kt);
        CPASYNC(b0 + 15360u, pAl + 64 * D + kt);
        CPASYNC(b0 + 20480u, pBh + kt);
        CPASYNC(b0 + 25600u, pBh + 64 * D + kt);
        CPASYNC(b0 + 30720u, pBl + kt);
        CPASYNC(b0 + 35840u, pBl + 64 * D + kt);
        asm volatile("cp.async.commit_group;" ::: "memory");
    };

    // -------- per-warp tiling: warp grid 2(m) x 4(n), warp tile 64x32 -------
    const int w    = tid >> 5;
    const int lane = tid & 31;
    const int wm   = w >> 2;        // 0..1
    const int wn   = w & 3;         // 0..3
    const int lr   = lane >> 2;     // 0..7
    const int lc   = lane & 3;      // 0..3

    float acc[4][4][4];
    #pragma unroll
    for (int i = 0; i < 4; i++)
        #pragma unroll
        for (int j = 0; j < 4; j++)
            #pragma unroll
            for (int q = 0; q < 4; q++) acc[i][j][q] = 0.f;

    load_stage(0, 0);
    const int NIT = D / 16;   // 48
    for (int it = 0; it < NIT; ++it) {
        if (it + 1 < NIT) {
            load_stage((it + 1) * 16, (it + 1) & 1);
            asm volatile("cp.async.wait_group 1;" ::: "memory");
        } else {
            asm volatile("cp.async.wait_group 0;" ::: "memory");
        }
        __syncthreads();

        const float* sb  = sm + (it & 1) * STGF;
        const float* sAh = sb;
        const float* sAl = sb + 2560;
        const float* sBh = sb + 5120;
        const float* sBl = sb + 7680;

        #pragma unroll
        for (int ks = 0; ks < 2; ++ks) {
            unsigned ah[4][4], bh[4][2];
            #pragma unroll
            for (int mt = 0; mt < 4; ++mt) {
                const float* p = sAh + (wm * 64 + mt * 16 + lr) * SROW + ks * 8 + lc;
                ah[mt][0] = __float_as_uint(p[0]);
                ah[mt][1] = __float_as_uint(p[8 * SROW]);
                ah[mt][2] = __float_as_uint(p[4]);
                ah[mt][3] = __float_as_uint(p[8 * SROW + 4]);
            }
            #pragma unroll
            for (int nt = 0; nt < 4; ++nt) {
                const float* p = sBh + (wn * 32 + nt * 8 + lr) * SROW + ks * 8 + lc;
                bh[nt][0] = __float_as_uint(p[0]);
                bh[nt][1] = __float_as_uint(p[4]);
            }
            // pass 1: Ah * Bh
            #pragma unroll
            for (int mt = 0; mt < 4; ++mt)
                #pragma unroll
                for (int nt = 0; nt < 4; ++nt)
                    mma_tf32(acc[mt][nt], ah[mt], bh[nt]);

            // pass 2: Ah * Bl
            unsigned bl[4][2];
            #pragma unroll
            for (int nt = 0; nt < 4; ++nt) {
                const float* p = sBl + (wn * 32 + nt * 8 + lr) * SROW + ks * 8 + lc;
                bl[nt][0] = __float_as_uint(p[0]);
                bl[nt][1] = __float_as_uint(p[4]);
            }
            #pragma unroll
            for (int mt = 0; mt < 4; ++mt)
                #pragma unroll
                for (int nt = 0; nt < 4; ++nt)
                    mma_tf32(acc[mt][nt], ah[mt], bl[nt]);

            // pass 3: Al * Bh
            unsigned al[4][4];
            #pragma unroll
            for (int mt = 0; mt < 4; ++mt) {
                const float* p = sAl + (wm * 64 + mt * 16 + lr) * SROW + ks * 8 + lc;
                al[mt][0] = __float_as_uint(p[0]);
                al[mt][1] = __float_as_uint(p[8 * SROW]);
                al[mt][2] = __float_as_uint(p[4]);
                al[mt][3] = __float_as_uint(p[8 * SROW + 4]);
            }
            #pragma unroll
            for (int mt = 0; mt < 4; ++mt)
                #pragma unroll
                for (int nt = 0; nt < 4; ++nt)
                    mma_tf32(acc[mt][nt], al[mt], bh[nt]);
        }
        __syncthreads();
    }

    // -------- epilogue ------------------------------------------------------
    #pragma unroll
    for (int mt = 0; mt < 4; ++mt) {
        const int r = m0 + wm * 64 + mt * 16 + lr;
        #pragma unroll
        for (int nt = 0; nt < 4; ++nt) {
            const int n = nloc0 + wn * 32 + nt * 8 + lc * 2;
            float v00 = acc[mt][nt][0] + bias[n];
            float v01 = acc[mt][nt][1] + bias[n + 1];
            float v10 = acc[mt][nt][2] + bias[n];
            float v11 = acc[mt][nt][3] + bias[n + 1];
            if (MODE == 0 && region == 3) {
                v00 = 1.0f / (1.0f + __expf(-v00));
                v01 = 1.0f / (1.0f + __expf(-v01));
                v10 = 1.0f / (1.0f + __expf(-v10));
                v11 = 1.0f / (1.0f + __expf(-v11));
            }
            if (MODE == 0) {
                *(float2*)(C + (size_t)r * D + n)       = make_float2(v00, v01);
                *(float2*)(C + (size_t)(r + 8) * D + n) = make_float2(v10, v11);
            } else {
                const int b = r >> 10, t = r & 1023;
                C[((size_t)b * D + n    ) * T + t    ] = v00;
                C[((size_t)b * D + n + 1) * T + t    ] = v01;
                C[((size_t)b * D + n    ) * T + t + 8] = v10;
                C[((size_t)b * D + n + 1) * T + t + 8] = v11;
            }
        }
    }
}

// ---------------- Flash attention (fp32) + gate -----------------------------
#define KPAD 68
#define SPAD 65

__global__ __launch_bounds__(128)
void attn_kernel()
{
    extern __shared__ float smb[];
    float* Ks = smb;
    float* Vs = smb + 64 * KPAD;
    float* Ss = smb + 2 * 64 * KPAD;

    const int r  = threadIdx.x;
    const int qt = blockIdx.x;
    const int h  = blockIdx.y;
    const int b  = blockIdx.z;
    const int row = b * T + qt * 128 + r;
    const size_t coff = (size_t)row * D + h * DH;

    float q[DH];
    #pragma unroll
    for (int k = 0; k < DH; k += 4) {
        const float4 v = *(const float4*)(g_q + coff + k);
        q[k] = v.x; q[k + 1] = v.y; q[k + 2] = v.z; q[k + 3] = v.w;
    }

    float accv[DH];
    #pragma unroll
    for (int k = 0; k < DH; k++) accv[k] = 0.f;
    float mrun = -INFINITY, l = 0.f;

    for (int kt = 0; kt < 16; kt++) {
        const int krow0 = b * T + kt * 64;
        #pragma unroll
        for (int s = r; s < 1024; s += 128) {
            const int j  = s >> 4;
            const int kk = (s & 15) * 4;
            const size_t goff = (size_t)(krow0 + j) * D + h * DH + kk;
            *(float4*)&Ks[j * KPAD + kk] = *(const float4*)(g_k + goff);
            *(float4*)&Vs[j * KPAD + kk] = *(const float4*)(g_v + goff);
        }
        __syncthreads();

        float tmax = -INFINITY;
        #pragma unroll 4
        for (int j = 0; j < 64; j++) {
            float s = 0.f;
            #pragma unroll
            for (int k = 0; k < DH; k += 4) {
                const float4 kv = *(const float4*)&Ks[j * KPAD + k];
                s += q[k] * kv.x + q[k + 1] * kv.y + q[k + 2] * kv.z + q[k + 3] * kv.w;
            }
            s *= 0.125f;
            Ss[r * SPAD + j] = s;
            tmax = fmaxf(tmax, s);
        }

        const float mnew = fmaxf(mrun, tmax);
        const float corr = __expf(mrun - mnew);
        l *= corr;
        #pragma unroll
        for (int k = 0; k < DH; k++) accv[k] *= corr;

        #pragma unroll 2
        for (int j = 0; j < 64; j++) {
            const float p = __expf(Ss[r * SPAD + j] - mnew);
            l += p;
            #pragma unroll
            for (int k = 0; k < DH; k += 4) {
                const float4 vv = *(const float4*)&Vs[j * KPAD + k];
                accv[k]     += p * vv.x;
                accv[k + 1] += p * vv.y;
                accv[k + 2] += p * vv.z;
                accv[k + 3] += p * vv.w;
            }
        }
        mrun = mnew;
        __syncthreads();
    }

    const float inv = 1.0f / l;
    #pragma unroll
    for (int k = 0; k < DH; k += 4) {
        const float4 gv = *(const float4*)(g_g + coff + k);
        float4 oh, ol;
        float y0 = accv[k]     * inv * gv.x;
        float y1 = accv[k + 1] * inv * gv.y;
        float y2 = accv[k + 2] * inv * gv.z;
        float y3 = accv[k + 3] * inv * gv.w;
        oh.x = f2tf32(y0); ol.x = f2tf32(y0 - oh.x);
        oh.y = f2tf32(y1); ol.y = f2tf32(y1 - oh.y);
        oh.z = f2tf32(y2); ol.z = f2tf32(y2 - oh.z);
        oh.w = f2tf32(y3); ol.w = f2tf32(y3 - oh.w);
        *(float4*)(g_y_hi + coff + k) = oh;
        *(float4*)(g_y_lo + coff + k) = ol;
    }
}

// ---------------- launch -----------------------------------------------------
extern "C" void kernel_launch(void* const* d_in, const int* in_sizes, int n_in,
                              void* d_out, int out_size)
{
    const float* x     = (const float*)d_in[0];
    const float* Wq    = (const float*)d_in[1];
    const float* bq    = (const float*)d_in[2];
    const float* Wk    = (const float*)d_in[3];
    const float* bk    = (const float*)d_in[4];
    const float* Wv    = (const float*)d_in[5];
    const float* bv    = (const float*)d_in[6];
    const float* Wo    = (const float*)d_in[7];
    const float* bo    = (const float*)d_in[8];
    const float* Wg    = (const float*)d_in[9];
    const float* bg    = (const float*)d_in[10];
    const float* gamma = (const float*)d_in[11];
    const float* beta  = (const float*)d_in[12];
    float* out = (float*)d_out;

    void *p;
    float *xnh, *xnl, *qb, *kb, *vb, *gb, *yh, *yl;
    float *wqh,*wql,*wkh,*wkl,*wvh,*wvl,*wgh,*wgl,*woh,*wol;
    cudaGetSymbolAddress(&p, g_xn_hi); xnh = (float*)p;
    cudaGetSymbolAddress(&p, g_xn_lo); xnl = (float*)p;
    cudaGetSymbolAddress(&p, g_q);  qb = (float*)p;
    cudaGetSymbolAddress(&p, g_k);  kb = (float*)p;
    cudaGetSymbolAddress(&p, g_v);  vb = (float*)p;
    cudaGetSymbolAddress(&p, g_g);  gb = (float*)p;
    cudaGetSymbolAddress(&p, g_y_hi); yh = (float*)p;
    cudaGetSymbolAddress(&p, g_y_lo); yl = (float*)p;
    cudaGetSymbolAddress(&p, g_wq_hi); wqh = (float*)p;
    cudaGetSymbolAddress(&p, g_wq_lo); wql = (float*)p;
    cudaGetSymbolAddress(&p, g_wk_hi); wkh = (float*)p;
    cudaGetSymbolAddress(&p, g_wk_lo); wkl = (float*)p;
    cudaGetSymbolAddress(&p, g_wv_hi); wvh = (float*)p;
    cudaGetSymbolAddress(&p, g_wv_lo); wvl = (float*)p;
    cudaGetSymbolAddress(&p, g_wg_hi); wgh = (float*)p;
    cudaGetSymbolAddress(&p, g_wg_lo); wgl = (float*)p;
    cudaGetSymbolAddress(&p, g_wo_hi); woh = (float*)p;
    cudaGetSymbolAddress(&p, g_wo_lo); wol = (float*)p;

    const int gemm_smem = 2 * STGF * 4;   // 81920
    cudaFuncSetAttribute(gemm_mma<0>, cudaFuncAttributeMaxDynamicSharedMemorySize, gemm_smem);
    cudaFuncSetAttribute(gemm_mma<1>, cudaFuncAttributeMaxDynamicSharedMemorySize, gemm_smem);
    const int attn_smem = (2 * 64 * KPAD + 128 * SPAD) * (int)sizeof(float);
    cudaFuncSetAttribute(attn_kernel, cudaFuncAttributeMaxDynamicSharedMemorySize, attn_smem);

    // 0) split weights
    const int wn = D * D, wg_blocks = (wn + 255) / 256;
    split_w<<<wg_blocks, 256>>>(Wq, wqh, wql, wn);
    split_w<<<wg_blocks, 256>>>(Wk, wkh, wkl, wn);
    split_w<<<wg_blocks, 256>>>(Wv, wvh, wvl, wn);
    split_w<<<wg_blocks, 256>>>(Wg, wgh, wgl, wn);
    split_w<<<wg_blocks, 256>>>(Wo, woh, wol, wn);

    // 1) LayerNorm + transpose + split
    ln_kernel<<<M_TOT, 256>>>(x, gamma, beta);

    // 2) fused Q/K/V/G projections (tensor cores, 3xTF32)
    {
        GemmArgs a;
        a.Bh[0] = wqh; a.Bl[0] = wql; a.bias[0] = bq; a.C[0] = qb;
        a.Bh[1] = wkh; a.Bl[1] = wkl; a.bias[1] = bk; a.C[1] = kb;
        a.Bh[2] = wvh; a.Bl[2] = wvl; a.bias[2] = bv; a.C[2] = vb;
        a.Bh[3] = wgh; a.Bl[3] = wgl; a.bias[3] = bg; a.C[3] = gb;
        gemm_mma<0><<<dim3(24, 64), 256, gemm_smem>>>(xnh, xnl, a);
    }

    // 3) attention + gate (+ tf32 split of y)
    attn_kernel<<<dim3(8, NH, BATCH), 128, attn_smem>>>();

    // 4) output projection + transpose back
    {
        GemmArgs a;
        a.Bh[0] = woh; a.Bl[0] = wol; a.bias[0] = bo; a.C[0] = out;
        a.Bh[1] = a.Bh[2] = a.Bh[3] = woh;
        a.Bl[1] = a.Bl[2] = a.Bl[3] = wol;
        a.bias[1] = a.bias[2] = a.bias[3] = bo;
        a.C[1] = a.C[2] = a.C[3] = out;
        gemm_mma<1><<<dim3(6, 64), 256, gemm_smem>>>(yh, yl, a);
    }
}

// round 3
// speedup vs baseline: 2.6704x; 1.3073x over previous
#include <cuda_runtime.h>
#include <math.h>

#define D      768
#define T      1024
#define BATCH  8
#define M_TOT  (BATCH*T)   // 8192
#define NH     12
#define DH     64

// ---------------- scratch (device globals: alloc-free rule) ----------------
__device__ float g_xn_hi[(size_t)M_TOT * D];
__device__ float g_xn_lo[(size_t)M_TOT * D];
__device__ float g_q_hi[(size_t)M_TOT * D];
__device__ float g_q_lo[(size_t)M_TOT * D];
__device__ float g_k_hi[(size_t)M_TOT * D];
__device__ float g_k_lo[(size_t)M_TOT * D];
__device__ float g_v_hi[(size_t)M_TOT * D];
__device__ float g_v_lo[(size_t)M_TOT * D];
__device__ float g_g [(size_t)M_TOT * D];
__device__ float g_y_hi[(size_t)M_TOT * D];
__device__ float g_y_lo[(size_t)M_TOT * D];
__device__ float g_wq_hi[D*D], g_wq_lo[D*D];
__device__ float g_wk_hi[D*D], g_wk_lo[D*D];
__device__ float g_wv_hi[D*D], g_wv_lo[D*D];
__device__ float g_wg_hi[D*D], g_wg_lo[D*D];
__device__ float g_wo_hi[D*D], g_wo_lo[D*D];

__device__ __forceinline__ float f2tf32(float x) {
    float r;
    asm("cvt.rna.tf32.f32 %0, %1;" : "=f"(r) : "f"(x));
    return r;
}
__device__ __forceinline__ unsigned fu(float x) { return __float_as_uint(x); }

// ---------------- weight split -----------------------------------------------
__global__ __launch_bounds__(256)
void split_w(const float* __restrict__ w, float* __restrict__ hi,
             float* __restrict__ lo, int n)
{
    int i = blockIdx.x * 256 + threadIdx.x;
    if (i < n) {
        float v = w[i];
        float h = f2tf32(v);
        hi[i] = h;
        lo[i] = f2tf32(v - h);
    }
}

// ---------------- LayerNorm + transpose + tf32 split --------------------------
__global__ __launch_bounds__(256)
void ln_kernel(const float* __restrict__ x,
               const float* __restrict__ gamma,
               const float* __restrict__ beta)
{
    const int token = blockIdx.x;
    const int b = token >> 10;
    const int t = token & 1023;
    const float* xp = x + (size_t)b * D * T + t;

    const int c0 = threadIdx.x;
    const float v0 = xp[(size_t)(c0      ) * T];
    const float v1 = xp[(size_t)(c0 + 256) * T];
    const float v2 = xp[(size_t)(c0 + 512) * T];

    float s  = v0 + v1 + v2;
    float ss = v0 * v0 + v1 * v1 + v2 * v2;
    #pragma unroll
    for (int o = 16; o > 0; o >>= 1) {
        s  += __shfl_xor_sync(0xffffffffu, s,  o);
        ss += __shfl_xor_sync(0xffffffffu, ss, o);
    }
    __shared__ float red_s[8], red_ss[8];
    const int wid = threadIdx.x >> 5, lane = threadIdx.x & 31;
    if (lane == 0) { red_s[wid] = s; red_ss[wid] = ss; }
    __syncthreads();
    float sum = 0.f, sumsq = 0.f;
    #pragma unroll
    for (int i = 0; i < 8; i++) { sum += red_s[i]; sumsq += red_ss[i]; }

    const float mu  = sum * (1.0f / (float)D);
    const float var = sumsq * (1.0f / (float)D) - mu * mu;
    const float rs  = rsqrtf(var + 1e-5f);

    float* oh = g_xn_hi + (size_t)token * D;
    float* ol = g_xn_lo + (size_t)token * D;
    #pragma unroll
    for (int j = 0; j < 3; j++) {
        const int c = c0 + j * 256;
        const float v = (j == 0 ? v0 : (j == 1 ? v1 : v2));
        const float y = (v - mu) * rs * gamma[c] + beta[c];
        const float h = f2tf32(y);
        oh[c] = h;
        ol[c] = f2tf32(y - h);
    }
}

// ---------------- tf32 tensor-core GEMM (3xTF32) ------------------------------
struct GemmArgs {
    const float* Bh[4];
    const float* Bl[4];
    const float* bias[4];
    float*       C[4];
    float*       Clo[4];
};

__device__ __forceinline__ void mma_tf32(float* d, const unsigned* a, const unsigned* b) {
    asm volatile(
        "mma.sync.aligned.m16n8k8.row.col.f32.tf32.tf32.f32 "
        "{%0,%1,%2,%3}, {%4,%5,%6,%7}, {%8,%9}, {%0,%1,%2,%3};"
        : "+f"(d[0]), "+f"(d[1]), "+f"(d[2]), "+f"(d[3])
        : "r"(a[0]), "r"(a[1]), "r"(a[2]), "r"(a[3]), "r"(b[0]), "r"(b[1]));
}

#define SROW 20
#define STGF 10240

#define CPASYNC(dst, src) \
    asm volatile("cp.async.cg.shared.global [%0], [%1], 16;" :: "r"(dst), "l"(src) : "memory")
#define CP_COMMIT() asm volatile("cp.async.commit_group;" ::: "memory")
#define CP_WAIT(n)  asm volatile("cp.async.wait_group %0;" :: "n"(n) : "memory")

template<int MODE>
__global__ __launch_bounds__(256, 2)
void gemm_mma(const float* __restrict__ Agh, const float* __restrict__ Agl,
              GemmArgs args)
{
    extern __shared__ float sm[];
    const int tid = threadIdx.x;
    const int m0  = blockIdx.y * 128;

    int region, nloc0;
    if (MODE == 0) { region = blockIdx.x / 6; nloc0 = (blockIdx.x % 6) * 128; }
    else           { region = 0;              nloc0 = blockIdx.x * 128; }
    const float* Bh   = args.Bh[region];
    const float* Bl   = args.Bl[region];
    const float* bias = args.bias[region];
    float*       C    = args.C[region];
    float*       Clo  = args.Clo[region];

    const int ra = tid >> 2;
    const int kq = (tid & 3) * 4;
    const float* pAh = Agh + (size_t)(m0 + ra) * D + kq;
    const float* pAl = Agl + (size_t)(m0 + ra) * D + kq;
    const float* pBh = Bh  + (size_t)(nloc0 + ra) * D + kq;
    const float* pBl = Bl  + (size_t)(nloc0 + ra) * D + kq;
    const unsigned sbase = (unsigned)__cvta_generic_to_shared(sm);
    const unsigned soA = (unsigned)((ra * SROW + kq) * 4);

    auto load_stage = [&](int kt, int buf) {
        const unsigned b0 = sbase + (unsigned)buf * (STGF * 4) + soA;
        CPASYNC(b0 +     0u, pAh + kt);
        CPASYNC(b0 +  5120u, pAh + 64 * D + kt);
        CPASYNC(b0 + 10240u, pAl + kt);
        CPASYNC(b0 + 15360u, pAl + 64 * D + kt);
        CPASYNC(b0 + 20480u, pBh + kt);
        CPASYNC(b0 + 25600u, pBh + 64 * D + kt);
        CPASYNC(b0 + 30720u, pBl + kt);
        CPASYNC(b0 + 35840u, pBl + 64 * D + kt);
        CP_COMMIT();
    };

    const int w    = tid >> 5;
    const int lane = tid & 31;
    const int wm   = w >> 2;
    const int wn   = w & 3;
    const int lr   = lane >> 2;
    const int lc   = lane & 3;

    float acc[4][4][4];
    #pragma unroll
    for (int i = 0; i < 4; i++)
        #pragma unroll
        for (int j = 0; j < 4; j++)
            #pragma unroll
            for (int q = 0; q < 4; q++) acc[i][j][q] = 0.f;

    load_stage(0, 0);
    const int NIT = D / 16;
    for (int it = 0; it < NIT; ++it) {
        if (it + 1 < NIT) {
            load_stage((it + 1) * 16, (it + 1) & 1);
            CP_WAIT(1);
        } else {
            CP_WAIT(0);
        }
        __syncthreads();

        const float* sb  = sm + (it & 1) * STGF;
        const float* sAh = sb;
        const float* sAl = sb + 2560;
        const float* sBh = sb + 5120;
        const float* sBl = sb + 7680;

        #pragma unroll
        for (int ks = 0; ks < 2; ++ks) {
            unsigned ah[4][4], bh[4][2];
            #pragma unroll
            for (int mt = 0; mt < 4; ++mt) {
                const float* p = sAh + (wm * 64 + mt * 16 + lr) * SROW + ks * 8 + lc;
                ah[mt][0] = fu(p[0]);
                ah[mt][1] = fu(p[8 * SROW]);
                ah[mt][2] = fu(p[4]);
                ah[mt][3] = fu(p[8 * SROW + 4]);
            }
            #pragma unroll
            for (int nt = 0; nt < 4; ++nt) {
                const float* p = sBh + (wn * 32 + nt * 8 + lr) * SROW + ks * 8 + lc;
                bh[nt][0] = fu(p[0]);
                bh[nt][1] = fu(p[4]);
            }
            #pragma unroll
            for (int mt = 0; mt < 4; ++mt)
                #pragma unroll
                for (int nt = 0; nt < 4; ++nt)
                    mma_tf32(acc[mt][nt], ah[mt], bh[nt]);

            unsigned bl[4][2];
            #pragma unroll
            for (int nt = 0; nt < 4; ++nt) {
                const float* p = sBl + (wn * 32 + nt * 8 + lr) * SROW + ks * 8 + lc;
                bl[nt][0] = fu(p[0]);
                bl[nt][1] = fu(p[4]);
            }
            #pragma unroll
            for (int mt = 0; mt < 4; ++mt)
                #pragma unroll
                for (int nt = 0; nt < 4; ++nt)
                    mma_tf32(acc[mt][nt], ah[mt], bl[nt]);

            unsigned al[4][4];
            #pragma unroll
            for (int mt = 0; mt < 4; ++mt) {
                const float* p = sAl + (wm * 64 + mt * 16 + lr) * SROW + ks * 8 + lc;
                al[mt][0] = fu(p[0]);
                al[mt][1] = fu(p[8 * SROW]);
                al[mt][2] = fu(p[4]);
                al[mt][3] = fu(p[8 * SROW + 4]);
            }
            #pragma unroll
            for (int mt = 0; mt < 4; ++mt)
                #pragma unroll
                for (int nt = 0; nt < 4; ++nt)
                    mma_tf32(acc[mt][nt], al[mt], bh[nt]);
        }
        __syncthreads();
    }

    #pragma unroll
    for (int mt = 0; mt < 4; ++mt) {
        const int r = m0 + wm * 64 + mt * 16 + lr;
        #pragma unroll
        for (int nt = 0; nt < 4; ++nt) {
            const int n = nloc0 + wn * 32 + nt * 8 + lc * 2;
            float v00 = acc[mt][nt][0] + bias[n];
            float v01 = acc[mt][nt][1] + bias[n + 1];
            float v10 = acc[mt][nt][2] + bias[n];
            float v11 = acc[mt][nt][3] + bias[n + 1];
            if (MODE == 0) {
                if (region < 3) {
                    // write tf32 hi/lo split (consumed by attention mma)
                    float h00 = f2tf32(v00), h01 = f2tf32(v01);
                    float h10 = f2tf32(v10), h11 = f2tf32(v11);
                    *(float2*)(C   + (size_t)r * D + n)       = make_float2(h00, h01);
                    *(float2*)(C   + (size_t)(r + 8) * D + n) = make_float2(h10, h11);
                    *(float2*)(Clo + (size_t)r * D + n)       =
                        make_float2(f2tf32(v00 - h00), f2tf32(v01 - h01));
                    *(float2*)(Clo + (size_t)(r + 8) * D + n) =
                        make_float2(f2tf32(v10 - h10), f2tf32(v11 - h11));
                } else {
                    v00 = 1.0f / (1.0f + __expf(-v00));
                    v01 = 1.0f / (1.0f + __expf(-v01));
                    v10 = 1.0f / (1.0f + __expf(-v10));
                    v11 = 1.0f / (1.0f + __expf(-v11));
                    *(float2*)(C + (size_t)r * D + n)       = make_float2(v00, v01);
                    *(float2*)(C + (size_t)(r + 8) * D + n) = make_float2(v10, v11);
                }
            } else {
                const int b = r >> 10, t = r & 1023;
                C[((size_t)b * D + n    ) * T + t    ] = v00;
                C[((size_t)b * D + n + 1) * T + t    ] = v01;
                C[((size_t)b * D + n    ) * T + t + 8] = v10;
                C[((size_t)b * D + n + 1) * T + t + 8] = v11;
            }
        }
    }
}

// ---------------- tensor-core flash attention (3xTF32) ------------------------
// grid (8 qtiles, 12 heads, 8 batch); 256 threads = 8 warps; warp = 16 q-rows.
// smem (floats): Ph[128*68] | Pl[128*68] | K[2][2][64*68] | V[2][2][64*72]
#define OFF_PH 0
#define OFF_PL 8704
#define OFF_K  17408
#define OFF_V  34816
#define ATTN_SMEMF 53248   // floats -> 212992 bytes

__global__ __launch_bounds__(256, 1)
void attn_mma()
{
    extern __shared__ float sm[];
    const int tid  = threadIdx.x;
    const int w    = tid >> 5;
    const int lane = tid & 31;
    const int lr   = lane >> 2;
    const int lc   = lane & 3;

    const int qt = blockIdx.x;
    const int h  = blockIdx.y;
    const int b  = blockIdx.z;
    const int row0 = b * T + qt * 128;       // global token row of CTA row 0
    const int col0 = h * DH;

    const unsigned sb = (unsigned)__cvta_generic_to_shared(sm);

    // ---- stage Q hi/lo into P buffers (reused later for P) ----
    #pragma unroll
    for (int i = 0; i < 8; i++) {
        const int id = tid + i * 256;        // 0..2047
        const int r  = id >> 4;
        const int c  = (id & 15) * 4;
        const size_t go = (size_t)(row0 + r) * D + col0 + c;
        CPASYNC(sb + (OFF_PH + r * 68 + c) * 4u, g_q_hi + go);
        CPASYNC(sb + (OFF_PL + r * 68 + c) * 4u, g_q_lo + go);
    }
    CP_COMMIT();

    auto load_kv = [&](int kt, int stg) {
        #pragma unroll
        for (int i = 0; i < 4; i++) {
            const int id = tid + i * 256;    // 0..1023
            const int r  = id >> 4;
            const int c  = (id & 15) * 4;
            const size_t go = (size_t)(b * T + kt * 64 + r) * D + col0 + c;
            CPASYNC(sb + (OFF_K + stg * 8704 +        r * 68 + c) * 4u, g_k_hi + go);
            CPASYNC(sb + (OFF_K + stg * 8704 + 4352 + r * 68 + c) * 4u, g_k_lo + go);
            CPASYNC(sb + (OFF_V + stg * 9216 +        r * 72 + c) * 4u, g_v_hi + go);
            CPASYNC(sb + (OFF_V + stg * 9216 + 4608 + r * 72 + c) * 4u, g_v_lo + go);
        }
        CP_COMMIT();
    };
    load_kv(0, 0);

    CP_WAIT(1);              // Q staged
    __syncthreads();

    // ---- Q fragments in registers (scale 1/8 folded in, exact) ----
    unsigned qhf[8][4], qlf[8][4];
    {
        const int base = (w * 16 + lr) * 68;
        #pragma unroll
        for (int ks = 0; ks < 8; ++ks) {
            const int o = base + ks * 8 + lc;
            qhf[ks][0] = fu(0.125f * sm[OFF_PH + o]);
            qhf[ks][1] = fu(0.125f * sm[OFF_PH + o + 8 * 68]);
            qhf[ks][2] = fu(0.125f * sm[OFF_PH + o + 4]);
            qhf[ks][3] = fu(0.125f * sm[OFF_PH + o + 8 * 68 + 4]);
            qlf[ks][0] = fu(0.125f * sm[OFF_PL + o]);
            qlf[ks][1] = fu(0.125f * sm[OFF_PL + o + 8 * 68]);
            qlf[ks][2] = fu(0.125f * sm[OFF_PL + o + 4]);
            qlf[ks][3] = fu(0.125f * sm[OFF_PL + o + 8 * 68 + 4]);
        }
    }
    __syncwarp();

    float Oa[8][4];
    #pragma unroll
    for (int nt = 0; nt < 8; ++nt)
        #pragma unroll
        for (int q = 0; q < 4; q++) Oa[nt][q] = 0.f;
    float m0 = -1e30f, m1 = -1e30f, l0 = 0.f, l1 = 0.f;

    const int prow = (w * 16 + lr) * 68;

    for (int kt = 0; kt < 16; ++kt) {
        if (kt + 1 < 16) { load_kv(kt + 1, (kt + 1) & 1); CP_WAIT(1); }
        else             { CP_WAIT(0); }
        __syncthreads();

        const int stg = kt & 1;
        const float* sKh = sm + OFF_K + stg * 8704;
        const float* sKl = sKh + 4352;
        const float* sVh = sm + OFF_V + stg * 9216;
        const float* sVl = sVh + 4608;

        // ---- S = Q K^T (3xTF32) ----
        float sacc[8][4];
        #pragma unroll
        for (int nt = 0; nt < 8; ++nt)
            #pragma unroll
            for (int q = 0; q < 4; q++) sacc[nt][q] = 0.f;

        #pragma unroll
        for (int ks = 0; ks < 8; ++ks) {
            #pragma unroll
            for (int nt = 0; nt < 8; ++nt) {
                const int ko = (nt * 8 + lr) * 68 + ks * 8 + lc;
                unsigned kb[2]  = { fu(sKh[ko]), fu(sKh[ko + 4]) };
                unsigned klb[2] = { fu(sKl[ko]), fu(sKl[ko + 4]) };
                mma_tf32(sacc[nt], qhf[ks], kb);
                mma_tf32(sacc[nt], qhf[ks], klb);
                mma_tf32(sacc[nt], qlf[ks], kb);
            }
        }

        // ---- online softmax (rows lr, lr+8; quad holds one row) ----
        float tmax0 = -1e30f, tmax1 = -1e30f;
        #pragma unroll
        for (int nt = 0; nt < 8; ++nt) {
            tmax0 = fmaxf(tmax0, fmaxf(sacc[nt][0], sacc[nt][1]));
            tmax1 = fmaxf(tmax1, fmaxf(sacc[nt][2], sacc[nt][3]));
        }
        tmax0 = fmaxf(tmax0, __shfl_xor_sync(0xffffffffu, tmax0, 1));
        tmax0 = fmaxf(tmax0, __shfl_xor_sync(0xffffffffu, tmax0, 2));
        tmax1 = fmaxf(tmax1, __shfl_xor_sync(0xffffffffu, tmax1, 1));
        tmax1 = fmaxf(tmax1, __shfl_xor_sync(0xffffffffu, tmax1, 2));

        const float mn0 = fmaxf(m0, tmax0);
        const float mn1 = fmaxf(m1, tmax1);
        const float c0 = __expf(m0 - mn0);
        const float c1 = __expf(m1 - mn1);
        l0 *= c0; l1 *= c1;
        #pragma unroll
        for (int nt = 0; nt < 8; ++nt) {
            Oa[nt][0] *= c0; Oa[nt][1] *= c0;
            Oa[nt][2] *= c1; Oa[nt][3] *= c1;
        }

        float ls0 = 0.f, ls1 = 0.f;
        #pragma unroll
        for (int nt = 0; nt < 8; ++nt) {
            const float p0 = __expf(sacc[nt][0] - mn0);
            const float p1 = __expf(sacc[nt][1] - mn0);
            const float p2 = __expf(sacc[nt][2] - mn1);
            const float p3 = __expf(sacc[nt][3] - mn1);
            ls0 += p0 + p1; ls1 += p2 + p3;
            const float h0 = f2tf32(p0), h1 = f2tf32(p1);
            const float h2 = f2tf32(p2), h3 = f2tf32(p3);
            const int cidx = nt * 8 + 2 * lc;
            *(float2*)&sm[OFF_PH + prow + cidx]          = make_float2(h0, h1);
            *(float2*)&sm[OFF_PH + prow + 8 * 68 + cidx] = make_float2(h2, h3);
            *(float2*)&sm[OFF_PL + prow + cidx]          = make_float2(p0 - h0, p1 - h1);
            *(float2*)&sm[OFF_PL + prow + 8 * 68 + cidx] = make_float2(p2 - h2, p3 - h3);
        }
        ls0 += __shfl_xor_sync(0xffffffffu, ls0, 1);
        ls0 += __shfl_xor_sync(0xffffffffu, ls0, 2);
        ls1 += __shfl_xor_sync(0xffffffffu, ls1, 1);
        ls1 += __shfl_xor_sync(0xffffffffu, ls1, 2);
        l0 += ls0; l1 += ls1;
        m0 = mn0; m1 = mn1;
        __syncwarp();

        // ---- O += P V (3xTF32) ----
        #pragma unroll
        for (int ks = 0; ks < 8; ++ks) {
            const int po = prow + ks * 8 + lc;
            unsigned pa[4]  = { fu(sm[OFF_PH + po]), fu(sm[OFF_PH + po + 8 * 68]),
                                fu(sm[OFF_PH + po + 4]), fu(sm[OFF_PH + po + 8 * 68 + 4]) };
            unsigned pla[4] = { fu(sm[OFF_PL + po]), fu(sm[OFF_PL + po + 8 * 68]),
                                fu(sm[OFF_PL + po + 4]), fu(sm[OFF_PL + po + 8 * 68 + 4]) };
            #pragma unroll
            for (int nt = 0; nt < 8; ++nt) {
                const int vo = (ks * 8 + lc) * 72 + nt * 8 + lr;
                unsigned vb[2]  = { fu(sVh[vo]), fu(sVh[vo + 4 * 72]) };
                unsigned vlb[2] = { fu(sVl[vo]), fu(sVl[vo + 4 * 72]) };
                mma_tf32(Oa[nt], pa, vb);
                mma_tf32(Oa[nt], pa, vlb);
                mma_tf32(Oa[nt], pla, vb);
            }
        }
        __syncthreads();
    }

    // ---- epilogue: /l, gate, tf32 split, store ----
    const float inv0 = 1.0f / l0;
    const float inv1 = 1.0f / l1;
    const int gr0 = row0 + w * 16 + lr;
    const int gr1 = gr0 + 8;
    #pragma unroll
    for (int nt = 0; nt < 8; ++nt) {
        const int c = col0 + nt * 8 + 2 * lc;
        const float2 ga = *(const float2*)(g_g + (size_t)gr0 * D + c);
        const float2 gb = *(const float2*)(g_g + (size_t)gr1 * D + c);
        const float y00 = Oa[nt][0] * inv0 * ga.x;
        const float y01 = Oa[nt][1] * inv0 * ga.y;
        const float y10 = Oa[nt][2] * inv1 * gb.x;
        const float y11 = Oa[nt][3] * inv1 * gb.y;
        const float h00 = f2tf32(y00), h01 = f2tf32(y01);
        const float h10 = f2tf32(y10), h11 = f2tf32(y11);
        *(float2*)(g_y_hi + (size_t)gr0 * D + c) = make_float2(h00, h01);
        *(float2*)(g_y_hi + (size_t)gr1 * D + c) = make_float2(h10, h11);
        *(float2*)(g_y_lo + (size_t)gr0 * D + c) =
            make_float2(f2tf32(y00 - h00), f2tf32(y01 - h01));
        *(float2*)(g_y_lo + (size_t)gr1 * D + c) =
            make_float2(f2tf32(y10 - h10), f2tf32(y11 - h11));
    }
}

// ---------------- launch -------------------------------------------------------
extern "C" void kernel_launch(void* const* d_in, const int* in_sizes, int n_in,
                              void* d_out, int out_size)
{
    const float* x     = (const float*)d_in[0];
    const float* Wq    = (const float*)d_in[1];
    const float* bq    = (const float*)d_in[2];
    const float* Wk    = (const float*)d_in[3];
    const float* bk    = (const float*)d_in[4];
    const float* Wv    = (const float*)d_in[5];
    const float* bv    = (const float*)d_in[6];
    const float* Wo    = (const float*)d_in[7];
    const float* bo    = (const float*)d_in[8];
    const float* Wg    = (const float*)d_in[9];
    const float* bg    = (const float*)d_in[10];
    const float* gamma = (const float*)d_in[11];
    const float* beta  = (const float*)d_in[12];
    float* out = (float*)d_out;

    void *p;
    float *xnh, *xnl, *qh, *ql, *kh, *kl, *vh, *vl, *gb_, *yh, *yl;
    float *wqh,*wql,*wkh,*wkl,*wvh,*wvl,*wgh,*wgl,*woh,*wol;
    cudaGetSymbolAddress(&p, g_xn_hi); xnh = (float*)p;
    cudaGetSymbolAddress(&p, g_xn_lo); xnl = (float*)p;
    cudaGetSymbolAddress(&p, g_q_hi); qh = (float*)p;
    cudaGetSymbolAddress(&p, g_q_lo); ql = (float*)p;
    cudaGetSymbolAddress(&p, g_k_hi); kh = (float*)p;
    cudaGetSymbolAddress(&p, g_k_lo); kl = (float*)p;
    cudaGetSymbolAddress(&p, g_v_hi); vh = (float*)p;
    cudaGetSymbolAddress(&p, g_v_lo); vl = (float*)p;
    cudaGetSymbolAddress(&p, g_g);    gb_ = (float*)p;
    cudaGetSymbolAddress(&p, g_y_hi); yh = (float*)p;
    cudaGetSymbolAddress(&p, g_y_lo); yl = (float*)p;
    cudaGetSymbolAddress(&p, g_wq_hi); wqh = (float*)p;
    cudaGetSymbolAddress(&p, g_wq_lo); wql = (float*)p;
    cudaGetSymbolAddress(&p, g_wk_hi); wkh = (float*)p;
    cudaGetSymbolAddress(&p, g_wk_lo); wkl = (float*)p;
    cudaGetSymbolAddress(&p, g_wv_hi); wvh = (float*)p;
    cudaGetSymbolAddress(&p, g_wv_lo); wvl = (float*)p;
    cudaGetSymbolAddress(&p, g_wg_hi); wgh = (float*)p;
    cudaGetSymbolAddress(&p, g_wg_lo); wgl = (float*)p;
    cudaGetSymbolAddress(&p, g_wo_hi); woh = (float*)p;
    cudaGetSymbolAddress(&p, g_wo_lo); wol = (float*)p;

    const int gemm_smem = 2 * STGF * 4;
    cudaFuncSetAttribute(gemm_mma<0>, cudaFuncAttributeMaxDynamicSharedMemorySize, gemm_smem);
    cudaFuncSetAttribute(gemm_mma<1>, cudaFuncAttributeMaxDynamicSharedMemorySize, gemm_smem);
    const int attn_smem = ATTN_SMEMF * 4;   // 212992
    cudaFuncSetAttribute(attn_mma, cudaFuncAttributeMaxDynamicSharedMemorySize, attn_smem);

    const int wn = D * D, wblocks = (wn + 255) / 256;
    split_w<<<wblocks, 256>>>(Wq, wqh, wql, wn);
    split_w<<<wblocks, 256>>>(Wk, wkh, wkl, wn);
    split_w<<<wblocks, 256>>>(Wv, wvh, wvl, wn);
    split_w<<<wblocks, 256>>>(Wg, wgh, wgl, wn);
    split_w<<<wblocks, 256>>>(Wo, woh, wol, wn);

    ln_kernel<<<M_TOT, 256>>>(x, gamma, beta);

    {
        GemmArgs a;
        a.Bh[0] = wqh; a.Bl[0] = wql; a.bias[0] = bq; a.C[0] = qh; a.Clo[0] = ql;
        a.Bh[1] = wkh; a.Bl[1] = wkl; a.bias[1] = bk; a.C[1] = kh; a.Clo[1] = kl;
        a.Bh[2] = wvh; a.Bl[2] = wvl; a.bias[2] = bv; a.C[2] = vh; a.Clo[2] = vl;
        a.Bh[3] = wgh; a.Bl[3] = wgl; a.bias[3] = bg; a.C[3] = gb_; a.Clo[3] = gb_;
        gemm_mma<0><<<dim3(24, 64), 256, gemm_smem>>>(xnh, xnl, a);
    }

    attn_mma<<<dim3(8, NH, BATCH), 256, attn_smem>>>();

    {
        GemmArgs a;
        a.Bh[0] = woh; a.Bl[0] = wol; a.bias[0] = bo; a.C[0] = out; a.Clo[0] = out;
        a.Bh[1] = a.Bh[2] = a.Bh[3] = woh;
        a.Bl[1] = a.Bl[2] = a.Bl[3] = wol;
        a.bias[1] = a.bias[2] = a.bias[3] = bo;
        a.C[1] = a.C[2] = a.C[3] = out;
        a.Clo[1] = a.Clo[2] = a.Clo[3] = out;
        gemm_mma<1><<<dim3(6, 64), 256, gemm_smem>>>(yh, yl, a);
    }
}

// round 4
// speedup vs baseline: 2.9888x; 1.1192x over previous
#include <cuda_runtime.h>
#include <math.h>

#define D      768
#define T      1024
#define BATCH  8
#define M_TOT  (BATCH*T)   // 8192
#define NH     12
#define DH     64

// ---------------- scratch (device globals: alloc-free rule) ----------------
__device__ float g_xn_hi[(size_t)M_TOT * D];
__device__ float g_xn_lo[(size_t)M_TOT * D];
__device__ float g_q     [(size_t)M_TOT * D];          // tf32 hi only
__device__ float g_k_pack[(size_t)M_TOT * D * 2];      // interleaved (hi,lo)
__device__ float g_v_pack[(size_t)M_TOT * D * 2];      // interleaved (hi,lo)
__device__ float g_g [(size_t)M_TOT * D];
__device__ float g_y_hi[(size_t)M_TOT * D];
__device__ float g_y_lo[(size_t)M_TOT * D];
__device__ float g_wq_hi[D*D], g_wq_lo[D*D];
__device__ float g_wk_hi[D*D], g_wk_lo[D*D];
__device__ float g_wv_hi[D*D], g_wv_lo[D*D];
__device__ float g_wg_hi[D*D], g_wg_lo[D*D];
__device__ float g_wo_hi[D*D], g_wo_lo[D*D];

__device__ __forceinline__ float f2tf32(float x) {
    float r;
    asm("cvt.rna.tf32.f32 %0, %1;" : "=f"(r) : "f"(x));
    return r;
}
__device__ __forceinline__ unsigned fu(float x) { return __float_as_uint(x); }

// ---------------- weight splits (2 launches) --------------------------------
__global__ __launch_bounds__(256)
void split3(const float* __restrict__ w0, const float* __restrict__ w1,
            const float* __restrict__ w2,
            float* __restrict__ h0, float* __restrict__ l0,
            float* __restrict__ h1, float* __restrict__ l1,
            float* __restrict__ h2, float* __restrict__ l2)
{
    const int i = blockIdx.x * 256 + threadIdx.x;
    if (i >= D * D) return;
    const float* w = (blockIdx.y == 0) ? w0 : (blockIdx.y == 1) ? w1 : w2;
    float* hh      = (blockIdx.y == 0) ? h0 : (blockIdx.y == 1) ? h1 : h2;
    float* ll      = (blockIdx.y == 0) ? l0 : (blockIdx.y == 1) ? l1 : l2;
    const float v = w[i];
    const float h = f2tf32(v);
    hh[i] = h;
    ll[i] = f2tf32(v - h);
}

__global__ __launch_bounds__(256)
void split2(const float* __restrict__ w0, const float* __restrict__ w1,
            float* __restrict__ h0, float* __restrict__ l0,
            float* __restrict__ h1, float* __restrict__ l1)
{
    const int i = blockIdx.x * 256 + threadIdx.x;
    if (i >= D * D) return;
    const float* w = (blockIdx.y == 0) ? w0 : w1;
    float* hh      = (blockIdx.y == 0) ? h0 : h1;
    float* ll      = (blockIdx.y == 0) ? l0 : l1;
    const float v = w[i];
    const float h = f2tf32(v);
    hh[i] = h;
    ll[i] = f2tf32(v - h);
}

// ---------------- LayerNorm + transpose + tf32 split -------------------------
__global__ __launch_bounds__(256)
void ln_kernel(const float* __restrict__ x,
               const float* __restrict__ gamma,
               const float* __restrict__ beta)
{
    const int token = blockIdx.x;
    const int b = token >> 10;
    const int t = token & 1023;
    const float* xp = x + (size_t)b * D * T + t;

    const int c0 = threadIdx.x;
    const float v0 = xp[(size_t)(c0      ) * T];
    const float v1 = xp[(size_t)(c0 + 256) * T];
    const float v2 = xp[(size_t)(c0 + 512) * T];

    float s  = v0 + v1 + v2;
    float ss = v0 * v0 + v1 * v1 + v2 * v2;
    #pragma unroll
    for (int o = 16; o > 0; o >>= 1) {
        s  += __shfl_xor_sync(0xffffffffu, s,  o);
        ss += __shfl_xor_sync(0xffffffffu, ss, o);
    }
    __shared__ float red_s[8], red_ss[8];
    const int wid = threadIdx.x >> 5, lane = threadIdx.x & 31;
    if (lane == 0) { red_s[wid] = s; red_ss[wid] = ss; }
    __syncthreads();
    float sum = 0.f, sumsq = 0.f;
    #pragma unroll
    for (int i = 0; i < 8; i++) { sum += red_s[i]; sumsq += red_ss[i]; }

    const float mu  = sum * (1.0f / (float)D);
    const float var = sumsq * (1.0f / (float)D) - mu * mu;
    const float rs  = rsqrtf(var + 1e-5f);

    float* oh = g_xn_hi + (size_t)token * D;
    float* ol = g_xn_lo + (size_t)token * D;
    #pragma unroll
    for (int j = 0; j < 3; j++) {
        const int c = c0 + j * 256;
        const float v = (j == 0 ? v0 : (j == 1 ? v1 : v2));
        const float y = (v - mu) * rs * gamma[c] + beta[c];
        const float h = f2tf32(y);
        oh[c] = h;
        ol[c] = f2tf32(y - h);
    }
}

// ---------------- tf32 tensor-core GEMM (3xTF32) -----------------------------
struct GemmArgs {
    const float* Bh[4];
    const float* Bl[4];
    const float* bias[4];
    float*       C[4];
};

__device__ __forceinline__ void mma_tf32(float* d, const unsigned* a, const unsigned* b) {
    asm volatile(
        "mma.sync.aligned.m16n8k8.row.col.f32.tf32.tf32.f32 "
        "{%0,%1,%2,%3}, {%4,%5,%6,%7}, {%8,%9}, {%0,%1,%2,%3};"
        : "+f"(d[0]), "+f"(d[1]), "+f"(d[2]), "+f"(d[3])
        : "r"(a[0]), "r"(a[1]), "r"(a[2]), "r"(a[3]), "r"(b[0]), "r"(b[1]));
}

#define SROW 20
#define STGF 10240

#define CPASYNC(dst, src) \
    asm volatile("cp.async.cg.shared.global [%0], [%1], 16;" :: "r"(dst), "l"(src) : "memory")
#define CP_COMMIT() asm volatile("cp.async.commit_group;" ::: "memory")
#define CP_WAIT(n)  asm volatile("cp.async.wait_group %0;" :: "n"(n) : "memory")

template<int MODE>
__global__ __launch_bounds__(256, 2)
void gemm_mma(const float* __restrict__ Agh, const float* __restrict__ Agl,
              GemmArgs args)
{
    extern __shared__ float sm[];
    const int tid = threadIdx.x;
    const int m0  = blockIdx.y * 128;

    int region, nloc0;
    if (MODE == 0) { region = blockIdx.x / 6; nloc0 = (blockIdx.x % 6) * 128; }
    else           { region = 0;              nloc0 = blockIdx.x * 128; }
    const float* Bh   = args.Bh[region];
    const float* Bl   = args.Bl[region];
    const float* bias = args.bias[region];
    float*       C    = args.C[region];

    const int ra = tid >> 2;
    const int kq = (tid & 3) * 4;
    const float* pAh = Agh + (size_t)(m0 + ra) * D + kq;
    const float* pAl = Agl + (size_t)(m0 + ra) * D + kq;
    const float* pBh = Bh  + (size_t)(nloc0 + ra) * D + kq;
    const float* pBl = Bl  + (size_t)(nloc0 + ra) * D + kq;
    const unsigned sbase = (unsigned)__cvta_generic_to_shared(sm);
    const unsigned soA = (unsigned)((ra * SROW + kq) * 4);

    auto load_stage = [&](int kt, int buf) {
        const unsigned b0 = sbase + (unsigned)buf * (STGF * 4) + soA;
        CPASYNC(b0 +     0u, pAh + kt);
        CPASYNC(b0 +  5120u, pAh + 64 * D + kt);
        CPASYNC(b0 + 10240u, pAl + kt);
        CPASYNC(b0 + 15360u, pAl + 64 * D + kt);
        CPASYNC(b0 + 20480u, pBh + kt);
        CPASYNC(b0 + 25600u, pBh + 64 * D + kt);
        CPASYNC(b0 + 30720u, pBl + kt);
        CPASYNC(b0 + 35840u, pBl + 64 * D + kt);
        CP_COMMIT();
    };

    const int w    = tid >> 5;
    const int lane = tid & 31;
    const int wm   = w >> 2;
    const int wn   = w & 3;
    const int lr   = lane >> 2;
    const int lc   = lane & 3;

    float acc[4][4][4];
    #pragma unroll
    for (int i = 0; i < 4; i++)
        #pragma unroll
        for (int j = 0; j < 4; j++)
            #pragma unroll
            for (int q = 0; q < 4; q++) acc[i][j][q] = 0.f;

    load_stage(0, 0);
    const int NIT = D / 16;
    for (int it = 0; it < NIT; ++it) {
        if (it + 1 < NIT) {
            load_stage((it + 1) * 16, (it + 1) & 1);
            CP_WAIT(1);
        } else {
            CP_WAIT(0);
        }
        __syncthreads();

        const float* sb  = sm + (it & 1) * STGF;
        const float* sAh = sb;
        const float* sAl = sb + 2560;
        const float* sBh = sb + 5120;
        const float* sBl = sb + 7680;

        #pragma unroll
        for (int ks = 0; ks < 2; ++ks) {
            unsigned ah[4][4], bh[4][2];
            #pragma unroll
            for (int mt = 0; mt < 4; ++mt) {
                const float* p = sAh + (wm * 64 + mt * 16 + lr) * SROW + ks * 8 + lc;
                ah[mt][0] = fu(p[0]);
                ah[mt][1] = fu(p[8 * SROW]);
                ah[mt][2] = fu(p[4]);
                ah[mt][3] = fu(p[8 * SROW + 4]);
            }
            #pragma unroll
            for (int nt = 0; nt < 4; ++nt) {
                const float* p = sBh + (wn * 32 + nt * 8 + lr) * SROW + ks * 8 + lc;
                bh[nt][0] = fu(p[0]);
                bh[nt][1] = fu(p[4]);
            }
            #pragma unroll
            for (int mt = 0; mt < 4; ++mt)
                #pragma unroll
                for (int nt = 0; nt < 4; ++nt)
                    mma_tf32(acc[mt][nt], ah[mt], bh[nt]);

            unsigned bl[4][2];
            #pragma unroll
            for (int nt = 0; nt < 4; ++nt) {
                const float* p = sBl + (wn * 32 + nt * 8 + lr) * SROW + ks * 8 + lc;
                bl[nt][0] = fu(p[0]);
                bl[nt][1] = fu(p[4]);
            }
            #pragma unroll
            for (int mt = 0; mt < 4; ++mt)
                #pragma unroll
                for (int nt = 0; nt < 4; ++nt)
                    mma_tf32(acc[mt][nt], ah[mt], bl[nt]);

            unsigned al[4][4];
            #pragma unroll
            for (int mt = 0; mt < 4; ++mt) {
                const float* p = sAl + (wm * 64 + mt * 16 + lr) * SROW + ks * 8 + lc;
                al[mt][0] = fu(p[0]);
                al[mt][1] = fu(p[8 * SROW]);
                al[mt][2] = fu(p[4]);
                al[mt][3] = fu(p[8 * SROW + 4]);
            }
            #pragma unroll
            for (int mt = 0; mt < 4; ++mt)
                #pragma unroll
                for (int nt = 0; nt < 4; ++nt)
                    mma_tf32(acc[mt][nt], al[mt], bh[nt]);
        }
        __syncthreads();
    }

    #pragma unroll
    for (int mt = 0; mt < 4; ++mt) {
        const int r = m0 + wm * 64 + mt * 16 + lr;
        #pragma unroll
        for (int nt = 0; nt < 4; ++nt) {
            const int n = nloc0 + wn * 32 + nt * 8 + lc * 2;
            float v00 = acc[mt][nt][0] + bias[n];
            float v01 = acc[mt][nt][1] + bias[n + 1];
            float v10 = acc[mt][nt][2] + bias[n];
            float v11 = acc[mt][nt][3] + bias[n + 1];
            if (MODE == 0) {
                if (region == 0) {
                    // Q: tf32 hi only
                    *(float2*)(C + (size_t)r * D + n) =
                        make_float2(f2tf32(v00), f2tf32(v01));
                    *(float2*)(C + (size_t)(r + 8) * D + n) =
                        make_float2(f2tf32(v10), f2tf32(v11));
                } else if (region < 3) {
                    // K/V: interleaved (hi,lo) pairs
                    const float h00 = f2tf32(v00), h01 = f2tf32(v01);
                    const float h10 = f2tf32(v10), h11 = f2tf32(v11);
                    *(float4*)(C + ((size_t)r * D + n) * 2) =
                        make_float4(h00, f2tf32(v00 - h00), h01, f2tf32(v01 - h01));
                    *(float4*)(C + ((size_t)(r + 8) * D + n) * 2) =
                        make_float4(h10, f2tf32(v10 - h10), h11, f2tf32(v11 - h11));
                } else {
                    v00 = 1.0f / (1.0f + __expf(-v00));
                    v01 = 1.0f / (1.0f + __expf(-v01));
                    v10 = 1.0f / (1.0f + __expf(-v10));
                    v11 = 1.0f / (1.0f + __expf(-v11));
                    *(float2*)(C + (size_t)r * D + n)       = make_float2(v00, v01);
                    *(float2*)(C + (size_t)(r + 8) * D + n) = make_float2(v10, v11);
                }
            } else {
                const int b = r >> 10, t = r & 1023;
                C[((size_t)b * D + n    ) * T + t    ] = v00;
                C[((size_t)b * D + n + 1) * T + t    ] = v01;
                C[((size_t)b * D + n    ) * T + t + 8] = v10;
                C[((size_t)b * D + n + 1) * T + t + 8] = v11;
            }
        }
    }
}

// ---------------- tensor-core flash attention (packed hi/lo) ------------------
// grid (8 qtiles, 12 heads, 8 batch); 256 threads = 8 warps; warp = 16 q-rows.
// KT=32 double-buffered. QK = qh*kh + qh*kl ; PV = ph*vh + ph*vl.
// smem (floats): P 128*40 | K 2*32*136 | V 2*32*136  = 22528 (90112 B) -> 2 CTA/SM
#define KT      32
#define NITER   (T/KT)     // 32
#define KSTR    136
#define PSTR    40
#define OFF_P   0
#define OFF_K   5120
#define OFF_V   13824
#define ATTN_SMEMF 22528

__global__ __launch_bounds__(256, 2)
void attn_mma()
{
    extern __shared__ float sm[];
    const int tid  = threadIdx.x;
    const int w    = tid >> 5;
    const int lane = tid & 31;
    const int lr   = lane >> 2;
    const int lc   = lane & 3;

    const int qt = blockIdx.x;
    const int h  = blockIdx.y;
    const int b  = blockIdx.z;
    const int row0 = b * T + qt * 128;
    const int col0 = h * DH;
    const unsigned sb = (unsigned)__cvta_generic_to_shared(sm);

    auto load_kv = [&](int kt, int stg) {
        #pragma unroll
        for (int i = 0; i < 4; i++) {
            const int id = tid + i * 256;           // 0..1023
            const int tk = id >> 5;                  // token 0..31
            const int ch = (id & 31) * 4;            // float chunk 0..124
            const size_t gt = ((size_t)(b * T + kt * KT + tk) * D + col0) * 2 + ch;
            CPASYNC(sb + (OFF_K + stg * 4352 + tk * KSTR + ch) * 4u, g_k_pack + gt);
            CPASYNC(sb + (OFF_V + stg * 4352 + tk * KSTR + ch) * 4u, g_v_pack + gt);
        }
        CP_COMMIT();
    };
    load_kv(0, 0);

    // ---- Q fragments (hi only, 1/8 scale folded in — exact) ----
    unsigned qh[8][4];
    {
        const size_t ra = (size_t)(row0 + w * 16 + lr) * D;
        const size_t rb = ra + 8 * D;
        #pragma unroll
        for (int ks = 0; ks < 8; ++ks) {
            const int c = col0 + ks * 8 + lc;
            qh[ks][0] = fu(0.125f * g_q[ra + c]);
            qh[ks][1] = fu(0.125f * g_q[rb + c]);
            qh[ks][2] = fu(0.125f * g_q[ra + c + 4]);
            qh[ks][3] = fu(0.125f * g_q[rb + c + 4]);
        }
    }

    float Oa[8][4];
    #pragma unroll
    for (int nt = 0; nt < 8; ++nt)
        #pragma unroll
        for (int q = 0; q < 4; q++) Oa[nt][q] = 0.f;
    float m0 = -1e30f, m1 = -1e30f, l0 = 0.f, l1 = 0.f;

    const int prow = (w * 16 + lr) * PSTR;

    for (int kt = 0; kt < NITER; ++kt) {
        if (kt + 1 < NITER) { load_kv(kt + 1, (kt + 1) & 1); CP_WAIT(1); }
        else                { CP_WAIT(0); }
        __syncthreads();

        const float* sK = sm + OFF_K + (kt & 1) * 4352;
        const float* sV = sm + OFF_V + (kt & 1) * 4352;

        // ---- S = Q K^T (hi*hi + hi*lo) ----
        float sacc[4][4];
        #pragma unroll
        for (int nt = 0; nt < 4; ++nt)
            #pragma unroll
            for (int q = 0; q < 4; q++) sacc[nt][q] = 0.f;

        #pragma unroll
        for (int ks = 0; ks < 8; ++ks) {
            #pragma unroll
            for (int nt = 0; nt < 4; ++nt) {
                const int base = (nt * 8 + lr) * KSTR + (ks * 8 + lc) * 2;
                const float2 kA = *(const float2*)&sK[base];      // (hi,lo) at k
                const float2 kB = *(const float2*)&sK[base + 8];  // (hi,lo) at k+4
                unsigned kh2[2] = { fu(kA.x), fu(kB.x) };
                unsigned kl2[2] = { fu(kA.y), fu(kB.y) };
                mma_tf32(sacc[nt], qh[ks], kh2);
                mma_tf32(sacc[nt], qh[ks], kl2);
            }
        }

        // ---- online softmax ----
        float tmax0 = -1e30f, tmax1 = -1e30f;
        #pragma unroll
        for (int nt = 0; nt < 4; ++nt) {
            tmax0 = fmaxf(tmax0, fmaxf(sacc[nt][0], sacc[nt][1]));
            tmax1 = fmaxf(tmax1, fmaxf(sacc[nt][2], sacc[nt][3]));
        }
        tmax0 = fmaxf(tmax0, __shfl_xor_sync(0xffffffffu, tmax0, 1));
        tmax0 = fmaxf(tmax0, __shfl_xor_sync(0xffffffffu, tmax0, 2));
        tmax1 = fmaxf(tmax1, __shfl_xor_sync(0xffffffffu, tmax1, 1));
        tmax1 = fmaxf(tmax1, __shfl_xor_sync(0xffffffffu, tmax1, 2));

        const float mn0 = fmaxf(m0, tmax0);
        const float mn1 = fmaxf(m1, tmax1);
        const float c0 = __expf(m0 - mn0);
        const float c1 = __expf(m1 - mn1);
        l0 *= c0; l1 *= c1;
        #pragma unroll
        for (int nt = 0; nt < 8; ++nt) {
            Oa[nt][0] *= c0; Oa[nt][1] *= c0;
            Oa[nt][2] *= c1; Oa[nt][3] *= c1;
        }

        float ls0 = 0.f, ls1 = 0.f;
        #pragma unroll
        for (int nt = 0; nt < 4; ++nt) {
            const float p0 = __expf(sacc[nt][0] - mn0);
            const float p1 = __expf(sacc[nt][1] - mn0);
            const float p2 = __expf(sacc[nt][2] - mn1);
            const float p3 = __expf(sacc[nt][3] - mn1);
            ls0 += p0 + p1; ls1 += p2 + p3;
            const int cidx = nt * 8 + 2 * lc;
            *(float2*)&sm[OFF_P + prow + cidx] =
                make_float2(f2tf32(p0), f2tf32(p1));
            *(float2*)&sm[OFF_P + prow + 8 * PSTR + cidx] =
                make_float2(f2tf32(p2), f2tf32(p3));
        }
        ls0 += __shfl_xor_sync(0xffffffffu, ls0, 1);
        ls0 += __shfl_xor_sync(0xffffffffu, ls0, 2);
        ls1 += __shfl_xor_sync(0xffffffffu, ls1, 1);
        ls1 += __shfl_xor_sync(0xffffffffu, ls1, 2);
        l0 += ls0; l1 += ls1;
        m0 = mn0; m1 = mn1;
        __syncwarp();

        // ---- O += P V (ph*vh + ph*vl) ----
        #pragma unroll
        for (int ks = 0; ks < 4; ++ks) {
            const int po = OFF_P + prow + ks * 8 + lc;
            unsigned pa[4] = { fu(sm[po]), fu(sm[po + 8 * PSTR]),
                               fu(sm[po + 4]), fu(sm[po + 8 * PSTR + 4]) };
            #pragma unroll
            for (int nt = 0; nt < 8; ++nt) {
                const int base = (ks * 8 + lc) * KSTR + (nt * 8 + lr) * 2;
                const float2 vA = *(const float2*)&sV[base];             // (hi,lo) at k
                const float2 vB = *(const float2*)&sV[base + 4 * KSTR];  // (hi,lo) at k+4
                unsigned vh2[2] = { fu(vA.x), fu(vB.x) };
                unsigned vl2[2] = { fu(vA.y), fu(vB.y) };
                mma_tf32(Oa[nt], pa, vh2);
                mma_tf32(Oa[nt], pa, vl2);
            }
        }
        __syncthreads();   // release stage buffer for next prefetch
    }

    // ---- epilogue: /l, gate, tf32 split, store ----
    const float inv0 = 1.0f / l0;
    const float inv1 = 1.0f / l1;
    const int gr0 = row0 + w * 16 + lr;
    const int gr1 = gr0 + 8;
    #pragma unroll
    for (int nt = 0; nt < 8; ++nt) {
        const int c = col0 + nt * 8 + 2 * lc;
        const float2 ga = *(const float2*)(g_g + (size_t)gr0 * D + c);
        const float2 gb = *(const float2*)(g_g + (size_t)gr1 * D + c);
        const float y00 = Oa[nt][0] * inv0 * ga.x;
        const float y01 = Oa[nt][1] * inv0 * ga.y;
        const float y10 = Oa[nt][2] * inv1 * gb.x;
        const float y11 = Oa[nt][3] * inv1 * gb.y;
        const float h00 = f2tf32(y00), h01 = f2tf32(y01);
        const float h10 = f2tf32(y10), h11 = f2tf32(y11);
        *(float2*)(g_y_hi + (size_t)gr0 * D + c) = make_float2(h00, h01);
        *(float2*)(g_y_hi + (size_t)gr1 * D + c) = make_float2(h10, h11);
        *(float2*)(g_y_lo + (size_t)gr0 * D + c) =
            make_float2(f2tf32(y00 - h00), f2tf32(y01 - h01));
        *(float2*)(g_y_lo + (size_t)gr1 * D + c) =
            make_float2(f2tf32(y10 - h10), f2tf32(y11 - h11));
    }
}

// ---------------- launch --------------------------------------------------------
extern "C" void kernel_launch(void* const* d_in, const int* in_sizes, int n_in,
                              void* d_out, int out_size)
{
    const float* x     = (const float*)d_in[0];
    const float* Wq    = (const float*)d_in[1];
    const float* bq    = (const float*)d_in[2];
    const float* Wk    = (const float*)d_in[3];
    const float* bk    = (const float*)d_in[4];
    const float* Wv    = (const float*)d_in[5];
    const float* bv    = (const float*)d_in[6];
    const float* Wo    = (const float*)d_in[7];
    const float* bo    = (const float*)d_in[8];
    const float* Wg    = (const float*)d_in[9];
    const float* bg    = (const float*)d_in[10];
    const float* gamma = (const float*)d_in[11];
    const float* beta  = (const float*)d_in[12];
    float* out = (float*)d_out;

    void *p;
    float *xnh, *xnl, *qb, *kp, *vp, *gb_, *yh, *yl;
    float *wqh,*wql,*wkh,*wkl,*wvh,*wvl,*wgh,*wgl,*woh,*wol;
    cudaGetSymbolAddress(&p, g_xn_hi); xnh = (float*)p;
    cudaGetSymbolAddress(&p, g_xn_lo); xnl = (float*)p;
    cudaGetSymbolAddress(&p, g_q);      qb = (float*)p;
    cudaGetSymbolAddress(&p, g_k_pack); kp = (float*)p;
    cudaGetSymbolAddress(&p, g_v_pack); vp = (float*)p;
    cudaGetSymbolAddress(&p, g_g);     gb_ = (float*)p;
    cudaGetSymbolAddress(&p, g_y_hi);   yh = (float*)p;
    cudaGetSymbolAddress(&p, g_y_lo);   yl = (float*)p;
    cudaGetSymbolAddress(&p, g_wq_hi); wqh = (float*)p;
    cudaGetSymbolAddress(&p, g_wq_lo); wql = (float*)p;
    cudaGetSymbolAddress(&p, g_wk_hi); wkh = (float*)p;
    cudaGetSymbolAddress(&p, g_wk_lo); wkl = (float*)p;
    cudaGetSymbolAddress(&p, g_wv_hi); wvh = (float*)p;
    cudaGetSymbolAddress(&p, g_wv_lo); wvl = (float*)p;
    cudaGetSymbolAddress(&p, g_wg_hi); wgh = (float*)p;
    cudaGetSymbolAddress(&p, g_wg_lo); wgl = (float*)p;
    cudaGetSymbolAddress(&p, g_wo_hi); woh = (float*)p;
    cudaGetSymbolAddress(&p, g_wo_lo); wol = (float*)p;

    const int gemm_smem = 2 * STGF * 4;
    cudaFuncSetAttribute(gemm_mma<0>, cudaFuncAttributeMaxDynamicSharedMemorySize, gemm_smem);
    cudaFuncSetAttribute(gemm_mma<1>, cudaFuncAttributeMaxDynamicSharedMemorySize, gemm_smem);
    const int attn_smem = ATTN_SMEMF * 4;   // 90112
    cudaFuncSetAttribute(attn_mma, cudaFuncAttributeMaxDynamicSharedMemorySize, attn_smem);

    const int wblocks = (D * D + 255) / 256;
    split3<<<dim3(wblocks, 3), 256>>>(Wq, Wk, Wv, wqh, wql, wkh, wkl, wvh, wvl);
    split2<<<dim3(wblocks, 2), 256>>>(Wg, Wo, wgh, wgl, woh, wol);

    ln_kernel<<<M_TOT, 256>>>(x, gamma, beta);

    {
        GemmArgs a;
        a.Bh[0] = wqh; a.Bl[0] = wql; a.bias[0] = bq; a.C[0] = qb;
        a.Bh[1] = wkh; a.Bl[1] = wkl; a.bias[1] = bk; a.C[1] = kp;
        a.Bh[2] = wvh; a.Bl[2] = wvl; a.bias[2] = bv; a.C[2] = vp;
        a.Bh[3] = wgh; a.Bl[3] = wgl; a.bias[3] = bg; a.C[3] = gb_;
        gemm_mma<0><<<dim3(24, 64), 256, gemm_smem>>>(xnh, xnl, a);
    }

    attn_mma<<<dim3(8, NH, BATCH), 256, attn_smem>>>();

    {
        GemmArgs a;
        a.Bh[0] = woh; a.Bl[0] = wol; a.bias[0] = bo; a.C[0] = out;
        a.Bh[1] = a.Bh[2] = a.Bh[3] = woh;
        a.Bl[1] = a.Bl[2] = a.Bl[3] = wol;
        a.bias[1] = a.bias[2] = a.bias[3] = bo;
        a.C[1] = a.C[2] = a.C[3] = out;
        gemm_mma<1><<<dim3(6, 64), 256, gemm_smem>>>(yh, yl, a);
    }
}

// round 5
// speedup vs baseline: 4.0368x; 1.3506x over previous
#include <cuda_runtime.h>
#include <cuda_bf16.h>
#include <math.h>

#define D      768
#define T      1024
#define BATCH  8
#define M_TOT  (BATCH*T)   // 8192
#define NH     12
#define DH     64

// ---------------- scratch (device globals: alloc-free rule) ----------------
__device__ __nv_bfloat16 g_xn_hi[(size_t)M_TOT * D];
__device__ __nv_bfloat16 g_xn_lo[(size_t)M_TOT * D];
__device__ float g_q     [(size_t)M_TOT * D];          // tf32 hi only
__device__ float g_k_pack[(size_t)M_TOT * D * 2];      // interleaved (hi,lo) tf32
__device__ float g_v_pack[(size_t)M_TOT * D * 2];      // interleaved (hi,lo) tf32
__device__ float g_g [(size_t)M_TOT * D];
__device__ __nv_bfloat16 g_y_hi[(size_t)M_TOT * D];
__device__ __nv_bfloat16 g_y_lo[(size_t)M_TOT * D];
__device__ __nv_bfloat16 g_wq_hi[D*D], g_wq_lo[D*D];
__device__ __nv_bfloat16 g_wk_hi[D*D], g_wk_lo[D*D];
__device__ __nv_bfloat16 g_wv_hi[D*D], g_wv_lo[D*D];
__device__ __nv_bfloat16 g_wg_hi[D*D], g_wg_lo[D*D];
__device__ __nv_bfloat16 g_wo_hi[D*D], g_wo_lo[D*D];

__device__ __forceinline__ float f2tf32(float x) {
    float r;
    asm("cvt.rna.tf32.f32 %0, %1;" : "=f"(r) : "f"(x));
    return r;
}
__device__ __forceinline__ unsigned fu(float x) { return __float_as_uint(x); }

// ---------------- weight splits (bf16 hi/lo) ---------------------------------
__global__ __launch_bounds__(256)
void split3(const float* __restrict__ w0, const float* __restrict__ w1,
            const float* __restrict__ w2,
            __nv_bfloat16* __restrict__ h0, __nv_bfloat16* __restrict__ l0,
            __nv_bfloat16* __restrict__ h1, __nv_bfloat16* __restrict__ l1,
            __nv_bfloat16* __restrict__ h2, __nv_bfloat16* __restrict__ l2)
{
    const int i = blockIdx.x * 256 + threadIdx.x;
    if (i >= D * D) return;
    const float* w    = (blockIdx.y == 0) ? w0 : (blockIdx.y == 1) ? w1 : w2;
    __nv_bfloat16* hh = (blockIdx.y == 0) ? h0 : (blockIdx.y == 1) ? h1 : h2;
    __nv_bfloat16* ll = (blockIdx.y == 0) ? l0 : (blockIdx.y == 1) ? l1 : l2;
    const float v = w[i];
    const __nv_bfloat16 h = __float2bfloat16(v);
    hh[i] = h;
    ll[i] = __float2bfloat16(v - __bfloat162float(h));
}

__global__ __launch_bounds__(256)
void split2(const float* __restrict__ w0, const float* __restrict__ w1,
            __nv_bfloat16* __restrict__ h0, __nv_bfloat16* __restrict__ l0,
            __nv_bfloat16* __restrict__ h1, __nv_bfloat16* __restrict__ l1)
{
    const int i = blockIdx.x * 256 + threadIdx.x;
    if (i >= D * D) return;
    const float* w    = (blockIdx.y == 0) ? w0 : w1;
    __nv_bfloat16* hh = (blockIdx.y == 0) ? h0 : h1;
    __nv_bfloat16* ll = (blockIdx.y == 0) ? l0 : l1;
    const float v = w[i];
    const __nv_bfloat16 h = __float2bfloat16(v);
    hh[i] = h;
    ll[i] = __float2bfloat16(v - __bfloat162float(h));
}

// ---------------- LayerNorm + transpose + bf16 split --------------------------
__global__ __launch_bounds__(256)
void ln_kernel(const float* __restrict__ x,
               const float* __restrict__ gamma,
               const float* __restrict__ beta)
{
    const int token = blockIdx.x;
    const int b = token >> 10;
    const int t = token & 1023;
    const float* xp = x + (size_t)b * D * T + t;

    const int c0 = threadIdx.x;
    const float v0 = xp[(size_t)(c0      ) * T];
    const float v1 = xp[(size_t)(c0 + 256) * T];
    const float v2 = xp[(size_t)(c0 + 512) * T];

    float s  = v0 + v1 + v2;
    float ss = v0 * v0 + v1 * v1 + v2 * v2;
    #pragma unroll
    for (int o = 16; o > 0; o >>= 1) {
        s  += __shfl_xor_sync(0xffffffffu, s,  o);
        ss += __shfl_xor_sync(0xffffffffu, ss, o);
    }
    __shared__ float red_s[8], red_ss[8];
    const int wid = threadIdx.x >> 5, lane = threadIdx.x & 31;
    if (lane == 0) { red_s[wid] = s; red_ss[wid] = ss; }
    __syncthreads();
    float sum = 0.f, sumsq = 0.f;
    #pragma unroll
    for (int i = 0; i < 8; i++) { sum += red_s[i]; sumsq += red_ss[i]; }

    const float mu  = sum * (1.0f / (float)D);
    const float var = sumsq * (1.0f / (float)D) - mu * mu;
    const float rs  = rsqrtf(var + 1e-5f);

    __nv_bfloat16* oh = g_xn_hi + (size_t)token * D;
    __nv_bfloat16* ol = g_xn_lo + (size_t)token * D;
    #pragma unroll
    for (int j = 0; j < 3; j++) {
        const int c = c0 + j * 256;
        const float v = (j == 0 ? v0 : (j == 1 ? v1 : v2));
        const float y = (v - mu) * rs * gamma[c] + beta[c];
        const __nv_bfloat16 h = __float2bfloat16(y);
        oh[c] = h;
        ol[c] = __float2bfloat16(y - __bfloat162float(h));
    }
}

// ---------------- bf16 tensor-core GEMM (3xBF16) ------------------------------
// C = A(MxK)*W(NxK)^T + bias. A,W as bf16 (hi,lo). acc = Ah*Bh + Ah*Bl + Al*Bh.
// 128x128 tile, BK=16, 256 threads, 2-stage cp.async. smem rows: 12 uints.
struct GemmArgs {
    const __nv_bfloat16* Bh[4];
    const __nv_bfloat16* Bl[4];
    const float* bias[4];
    float*       C[4];
};

__device__ __forceinline__ void mma_bf16(float* d, const unsigned* a, const unsigned* b) {
    asm volatile(
        "mma.sync.aligned.m16n8k16.row.col.f32.bf16.bf16.f32 "
        "{%0,%1,%2,%3}, {%4,%5,%6,%7}, {%8,%9}, {%0,%1,%2,%3};"
        : "+f"(d[0]), "+f"(d[1]), "+f"(d[2]), "+f"(d[3])
        : "r"(a[0]), "r"(a[1]), "r"(a[2]), "r"(a[3]), "r"(b[0]), "r"(b[1]));
}

#define URO   12          // uints per smem row (8 data + 4 pad) -> conflict-free
#define CSTG  1536        // uints per component (128*12)
#define STGU  6144        // uints per stage (4 components)

#define CPASYNC(dst, src) \
    asm volatile("cp.async.cg.shared.global [%0], [%1], 16;" :: "r"(dst), "l"(src) : "memory")
#define CP_COMMIT() asm volatile("cp.async.commit_group;" ::: "memory")
#define CP_WAIT(n)  asm volatile("cp.async.wait_group %0;" :: "n"(n) : "memory")

template<int MODE>
__global__ __launch_bounds__(256, 2)
void gemm_mma(const __nv_bfloat16* __restrict__ Agh,
              const __nv_bfloat16* __restrict__ Agl, GemmArgs args)
{
    extern __shared__ unsigned smu[];
    const int tid = threadIdx.x;
    const int m0  = blockIdx.y * 128;

    int region, nloc0;
    if (MODE == 0) { region = blockIdx.x / 6; nloc0 = (blockIdx.x % 6) * 128; }
    else           { region = 0;              nloc0 = blockIdx.x * 128; }
    const __nv_bfloat16* Bh = args.Bh[region];
    const __nv_bfloat16* Bl = args.Bl[region];
    const float* bias = args.bias[region];
    float*       C    = args.C[region];

    // cooperative load: thread -> (row, 16B chunk); 4 cp.async per stage
    const int row = tid >> 1;
    const int chn = (tid & 1) * 8;      // halves offset within 16-half row
    const __nv_bfloat16* pAh = Agh + (size_t)(m0 + row) * D + chn;
    const __nv_bfloat16* pAl = Agl + (size_t)(m0 + row) * D + chn;
    const __nv_bfloat16* pBh = Bh  + (size_t)(nloc0 + row) * D + chn;
    const __nv_bfloat16* pBl = Bl  + (size_t)(nloc0 + row) * D + chn;
    const unsigned sbase = (unsigned)__cvta_generic_to_shared(smu);
    const unsigned so = (unsigned)((row * URO + (chn >> 1)) * 4);

    auto load_stage = [&](int kt, int buf) {
        const unsigned b0 = sbase + (unsigned)buf * (STGU * 4) + so;
        CPASYNC(b0,                pAh + kt);
        CPASYNC(b0 + CSTG * 4,     pAl + kt);
        CPASYNC(b0 + 2 * CSTG * 4, pBh + kt);
        CPASYNC(b0 + 3 * CSTG * 4, pBl + kt);
        CP_COMMIT();
    };

    const int w    = tid >> 5;
    const int lane = tid & 31;
    const int wm   = w >> 2;
    const int wn   = w & 3;
    const int lr   = lane >> 2;
    const int lc   = lane & 3;

    float acc[4][4][4];
    #pragma unroll
    for (int i = 0; i < 4; i++)
        #pragma unroll
        for (int j = 0; j < 4; j++)
            #pragma unroll
            for (int q = 0; q < 4; q++) acc[i][j][q] = 0.f;

    load_stage(0, 0);
    const int NIT = D / 16;   // 48
    for (int it = 0; it < NIT; ++it) {
        if (it + 1 < NIT) {
            load_stage((it + 1) * 16, (it + 1) & 1);
            CP_WAIT(1);
        } else {
            CP_WAIT(0);
        }
        __syncthreads();

        const unsigned* sb  = smu + (it & 1) * STGU;
        const unsigned* sAh = sb;
        const unsigned* sAl = sb + CSTG;
        const unsigned* sBh = sb + 2 * CSTG;
        const unsigned* sBl = sb + 3 * CSTG;

        unsigned ah[4][4], bh[4][2];
        #pragma unroll
        for (int mt = 0; mt < 4; ++mt) {
            const unsigned* p = sAh + (wm * 64 + mt * 16 + lr) * URO + lc;
            ah[mt][0] = p[0];
            ah[mt][1] = p[8 * URO];
            ah[mt][2] = p[4];
            ah[mt][3] = p[8 * URO + 4];
        }
        #pragma unroll
        for (int nt = 0; nt < 4; ++nt) {
            const unsigned* p = sBh + (wn * 32 + nt * 8 + lr) * URO + lc;
            bh[nt][0] = p[0];
            bh[nt][1] = p[4];
        }
        #pragma unroll
        for (int mt = 0; mt < 4; ++mt)
            #pragma unroll
            for (int nt = 0; nt < 4; ++nt)
                mma_bf16(acc[mt][nt], ah[mt], bh[nt]);

        unsigned bl[4][2];
        #pragma unroll
        for (int nt = 0; nt < 4; ++nt) {
            const unsigned* p = sBl + (wn * 32 + nt * 8 + lr) * URO + lc;
            bl[nt][0] = p[0];
            bl[nt][1] = p[4];
        }
        #pragma unroll
        for (int mt = 0; mt < 4; ++mt)
            #pragma unroll
            for (int nt = 0; nt < 4; ++nt)
                mma_bf16(acc[mt][nt], ah[mt], bl[nt]);

        unsigned al[4][4];
        #pragma unroll
        for (int mt = 0; mt < 4; ++mt) {
            const unsigned* p = sAl + (wm * 64 + mt * 16 + lr) * URO + lc;
            al[mt][0] = p[0];
            al[mt][1] = p[8 * URO];
            al[mt][2] = p[4];
            al[mt][3] = p[8 * URO + 4];
        }
        #pragma unroll
        for (int mt = 0; mt < 4; ++mt)
            #pragma unroll
            for (int nt = 0; nt < 4; ++nt)
                mma_bf16(acc[mt][nt], al[mt], bh[nt]);

        __syncthreads();
    }

    #pragma unroll
    for (int mt = 0; mt < 4; ++mt) {
        const int r = m0 + wm * 64 + mt * 16 + lr;
        #pragma unroll
        for (int nt = 0; nt < 4; ++nt) {
            const int n = nloc0 + wn * 32 + nt * 8 + lc * 2;
            float v00 = acc[mt][nt][0] + bias[n];
            float v01 = acc[mt][nt][1] + bias[n + 1];
            float v10 = acc[mt][nt][2] + bias[n];
            float v11 = acc[mt][nt][3] + bias[n + 1];
            if (MODE == 0) {
                if (region == 0) {
                    *(float2*)(C + (size_t)r * D + n) =
                        make_float2(f2tf32(v00), f2tf32(v01));
                    *(float2*)(C + (size_t)(r + 8) * D + n) =
                        make_float2(f2tf32(v10), f2tf32(v11));
                } else if (region < 3) {
                    const float h00 = f2tf32(v00), h01 = f2tf32(v01);
                    const float h10 = f2tf32(v10), h11 = f2tf32(v11);
                    *(float4*)(C + ((size_t)r * D + n) * 2) =
                        make_float4(h00, f2tf32(v00 - h00), h01, f2tf32(v01 - h01));
                    *(float4*)(C + ((size_t)(r + 8) * D + n) * 2) =
                        make_float4(h10, f2tf32(v10 - h10), h11, f2tf32(v11 - h11));
                } else {
                    v00 = 1.0f / (1.0f + __expf(-v00));
                    v01 = 1.0f / (1.0f + __expf(-v01));
                    v10 = 1.0f / (1.0f + __expf(-v10));
                    v11 = 1.0f / (1.0f + __expf(-v11));
                    *(float2*)(C + (size_t)r * D + n)       = make_float2(v00, v01);
                    *(float2*)(C + (size_t)(r + 8) * D + n) = make_float2(v10, v11);
                }
            } else {
                const int b = r >> 10, t = r & 1023;
                C[((size_t)b * D + n    ) * T + t    ] = v00;
                C[((size_t)b * D + n + 1) * T + t    ] = v01;
                C[((size_t)b * D + n    ) * T + t + 8] = v10;
                C[((size_t)b * D + n + 1) * T + t + 8] = v11;
            }
        }
    }
}

// ---------------- tensor-core flash attention (packed tf32 hi/lo) -------------
#define KT      32
#define NITER   (T/KT)     // 32
#define KSTR    136
#define PSTR    40
#define OFF_P   0
#define OFF_K   5120
#define OFF_V   13824
#define ATTN_SMEMF 22528

__device__ __forceinline__ void mma_tf32(float* d, const unsigned* a, const unsigned* b) {
    asm volatile(
        "mma.sync.aligned.m16n8k8.row.col.f32.tf32.tf32.f32 "
        "{%0,%1,%2,%3}, {%4,%5,%6,%7}, {%8,%9}, {%0,%1,%2,%3};"
        : "+f"(d[0]), "+f"(d[1]), "+f"(d[2]), "+f"(d[3])
        : "r"(a[0]), "r"(a[1]), "r"(a[2]), "r"(a[3]), "r"(b[0]), "r"(b[1]));
}

__global__ __launch_bounds__(256, 2)
void attn_mma()
{
    extern __shared__ float sm[];
    const int tid  = threadIdx.x;
    const int w    = tid >> 5;
    const int lane = tid & 31;
    const int lr   = lane >> 2;
    const int lc   = lane & 3;

    const int qt = blockIdx.x;
    const int h  = blockIdx.y;
    const int b  = blockIdx.z;
    const int row0 = b * T + qt * 128;
    const int col0 = h * DH;
    const unsigned sb = (unsigned)__cvta_generic_to_shared(sm);

    auto load_kv = [&](int kt, int stg) {
        #pragma unroll
        for (int i = 0; i < 4; i++) {
            const int id = tid + i * 256;
            const int tk = id >> 5;
            const int ch = (id & 31) * 4;
            const size_t gt = ((size_t)(b * T + kt * KT + tk) * D + col0) * 2 + ch;
            CPASYNC(sb + (OFF_K + stg * 4352 + tk * KSTR + ch) * 4u, g_k_pack + gt);
            CPASYNC(sb + (OFF_V + stg * 4352 + tk * KSTR + ch) * 4u, g_v_pack + gt);
        }
        CP_COMMIT();
    };
    load_kv(0, 0);

    unsigned qh[8][4];
    {
        const size_t ra = (size_t)(row0 + w * 16 + lr) * D;
        const size_t rb = ra + 8 * D;
        #pragma unroll
        for (int ks = 0; ks < 8; ++ks) {
            const int c = col0 + ks * 8 + lc;
            qh[ks][0] = fu(0.125f * g_q[ra + c]);
            qh[ks][1] = fu(0.125f * g_q[rb + c]);
            qh[ks][2] = fu(0.125f * g_q[ra + c + 4]);
            qh[ks][3] = fu(0.125f * g_q[rb + c + 4]);
        }
    }

    float Oa[8][4];
    #pragma unroll
    for (int nt = 0; nt < 8; ++nt)
        #pragma unroll
        for (int q = 0; q < 4; q++) Oa[nt][q] = 0.f;
    float m0 = -1e30f, m1 = -1e30f, l0 = 0.f, l1 = 0.f;

    const int prow = (w * 16 + lr) * PSTR;

    for (int kt = 0; kt < NITER; ++kt) {
        if (kt + 1 < NITER) { load_kv(kt + 1, (kt + 1) & 1); CP_WAIT(1); }
        else                { CP_WAIT(0); }
        __syncthreads();

        const float* sK = sm + OFF_K + (kt & 1) * 4352;
        const float* sV = sm + OFF_V + (kt & 1) * 4352;

        float sacc[4][4];
        #pragma unroll
        for (int nt = 0; nt < 4; ++nt)
            #pragma unroll
            for (int q = 0; q < 4; q++) sacc[nt][q] = 0.f;

        #pragma unroll
        for (int ks = 0; ks < 8; ++ks) {
            #pragma unroll
            for (int nt = 0; nt < 4; ++nt) {
                const int base = (nt * 8 + lr) * KSTR + (ks * 8 + lc) * 2;
                const float2 kA = *(const float2*)&sK[base];
                const float2 kB = *(const float2*)&sK[base + 8];
                unsigned kh2[2] = { fu(kA.x), fu(kB.x) };
                unsigned kl2[2] = { fu(kA.y), fu(kB.y) };
                mma_tf32(sacc[nt], qh[ks], kh2);
                mma_tf32(sacc[nt], qh[ks], kl2);
            }
        }

        float tmax0 = -1e30f, tmax1 = -1e30f;
        #pragma unroll
        for (int nt = 0; nt < 4; ++nt) {
            tmax0 = fmaxf(tmax0, fmaxf(sacc[nt][0], sacc[nt][1]));
            tmax1 = fmaxf(tmax1, fmaxf(sacc[nt][2], sacc[nt][3]));
        }
        tmax0 = fmaxf(tmax0, __shfl_xor_sync(0xffffffffu, tmax0, 1));
        tmax0 = fmaxf(tmax0, __shfl_xor_sync(0xffffffffu, tmax0, 2));
        tmax1 = fmaxf(tmax1, __shfl_xor_sync(0xffffffffu, tmax1, 1));
        tmax1 = fmaxf(tmax1, __shfl_xor_sync(0xffffffffu, tmax1, 2));

        const float mn0 = fmaxf(m0, tmax0);
        const float mn1 = fmaxf(m1, tmax1);
        const float c0 = __expf(m0 - mn0);
        const float c1 = __expf(m1 - mn1);
        l0 *= c0; l1 *= c1;
        #pragma unroll
        for (int nt = 0; nt < 8; ++nt) {
            Oa[nt][0] *= c0; Oa[nt][1] *= c0;
            Oa[nt][2] *= c1; Oa[nt][3] *= c1;
        }

        float ls0 = 0.f, ls1 = 0.f;
        #pragma unroll
        for (int nt = 0; nt < 4; ++nt) {
            const float p0 = __expf(sacc[nt][0] - mn0);
            const float p1 = __expf(sacc[nt][1] - mn0);
            const float p2 = __expf(sacc[nt][2] - mn1);
            const float p3 = __expf(sacc[nt][3] - mn1);
            ls0 += p0 + p1; ls1 += p2 + p3;
            const int cidx = nt * 8 + 2 * lc;
            *(float2*)&sm[OFF_P + prow + cidx] =
                make_float2(f2tf32(p0), f2tf32(p1));
            *(float2*)&sm[OFF_P + prow + 8 * PSTR + cidx] =
                make_float2(f2tf32(p2), f2tf32(p3));
        }
        ls0 += __shfl_xor_sync(0xffffffffu, ls0, 1);
        ls0 += __shfl_xor_sync(0xffffffffu, ls0, 2);
        ls1 += __shfl_xor_sync(0xffffffffu, ls1, 1);
        ls1 += __shfl_xor_sync(0xffffffffu, ls1, 2);
        l0 += ls0; l1 += ls1;
        m0 = mn0; m1 = mn1;
        __syncwarp();

        #pragma unroll
        for (int ks = 0; ks < 4; ++ks) {
            const int po = OFF_P + prow + ks * 8 + lc;
            unsigned pa[4] = { fu(sm[po]), fu(sm[po + 8 * PSTR]),
                               fu(sm[po + 4]), fu(sm[po + 8 * PSTR + 4]) };
            #pragma unroll
            for (int nt = 0; nt < 8; ++nt) {
                const int base = (ks * 8 + lc) * KSTR + (nt * 8 + lr) * 2;
                const float2 vA = *(const float2*)&sV[base];
                const float2 vB = *(const float2*)&sV[base + 4 * KSTR];
                unsigned vh2[2] = { fu(vA.x), fu(vB.x) };
                unsigned vl2[2] = { fu(vA.y), fu(vB.y) };
                mma_tf32(Oa[nt], pa, vh2);
                mma_tf32(Oa[nt], pa, vl2);
            }
        }
        __syncthreads();
    }

    // epilogue: /l, gate, bf16 split, store
    const float inv0 = 1.0f / l0;
    const float inv1 = 1.0f / l1;
    const int gr0 = row0 + w * 16 + lr;
    const int gr1 = gr0 + 8;
    #pragma unroll
    for (int nt = 0; nt < 8; ++nt) {
        const int c = col0 + nt * 8 + 2 * lc;
        const float2 ga = *(const float2*)(g_g + (size_t)gr0 * D + c);
        const float2 gb = *(const float2*)(g_g + (size_t)gr1 * D + c);
        const float y00 = Oa[nt][0] * inv0 * ga.x;
        const float y01 = Oa[nt][1] * inv0 * ga.y;
        const float y10 = Oa[nt][2] * inv1 * gb.x;
        const float y11 = Oa[nt][3] * inv1 * gb.y;
        const __nv_bfloat16 h00 = __float2bfloat16(y00);
        const __nv_bfloat16 h01 = __float2bfloat16(y01);
        const __nv_bfloat16 h10 = __float2bfloat16(y10);
        const __nv_bfloat16 h11 = __float2bfloat16(y11);
        *(__nv_bfloat162*)(g_y_hi + (size_t)gr0 * D + c) =
            __nv_bfloat162(h00, h01);
        *(__nv_bfloat162*)(g_y_hi + (size_t)gr1 * D + c) =
            __nv_bfloat162(h10, h11);
        *(__nv_bfloat162*)(g_y_lo + (size_t)gr0 * D + c) =
            __nv_bfloat162(__float2bfloat16(y00 - __bfloat162float(h00)),
                           __float2bfloat16(y01 - __bfloat162float(h01)));
        *(__nv_bfloat162*)(g_y_lo + (size_t)gr1 * D + c) =
            __nv_bfloat162(__float2bfloat16(y10 - __bfloat162float(h10)),
                           __float2bfloat16(y11 - __bfloat162float(h11)));
    }
}

// ---------------- launch --------------------------------------------------------
extern "C" void kernel_launch(void* const* d_in, const int* in_sizes, int n_in,
                              void* d_out, int out_size)
{
    const float* x     = (const float*)d_in[0];
    const float* Wq    = (const float*)d_in[1];
    const float* bq    = (const float*)d_in[2];
    const float* Wk    = (const float*)d_in[3];
    const float* bk    = (const float*)d_in[4];
    const float* Wv    = (const float*)d_in[5];
    const float* bv    = (const float*)d_in[6];
    const float* Wo    = (const float*)d_in[7];
    const float* bo    = (const float*)d_in[8];
    const float* Wg    = (const float*)d_in[9];
    const float* bg    = (const float*)d_in[10];
    const float* gamma = (const float*)d_in[11];
    const float* beta  = (const float*)d_in[12];
    float* out = (float*)d_out;

    void *p;
    __nv_bfloat16 *xnh, *xnl, *yh, *yl;
    __nv_bfloat16 *wqh,*wql,*wkh,*wkl,*wvh,*wvl,*wgh,*wgl,*woh,*wol;
    float *qb, *kp, *vp, *gb_;
    cudaGetSymbolAddress(&p, g_xn_hi); xnh = (__nv_bfloat16*)p;
    cudaGetSymbolAddress(&p, g_xn_lo); xnl = (__nv_bfloat16*)p;
    cudaGetSymbolAddress(&p, g_q);      qb = (float*)p;
    cudaGetSymbolAddress(&p, g_k_pack); kp = (float*)p;
    cudaGetSymbolAddress(&p, g_v_pack); vp = (float*)p;
    cudaGetSymbolAddress(&p, g_g);     gb_ = (float*)p;
    cudaGetSymbolAddress(&p, g_y_hi);   yh = (__nv_bfloat16*)p;
    cudaGetSymbolAddress(&p, g_y_lo);   yl = (__nv_bfloat16*)p;
    cudaGetSymbolAddress(&p, g_wq_hi); wqh = (__nv_bfloat16*)p;
    cudaGetSymbolAddress(&p, g_wq_lo); wql = (__nv_bfloat16*)p;
    cudaGetSymbolAddress(&p, g_wk_hi); wkh = (__nv_bfloat16*)p;
    cudaGetSymbolAddress(&p, g_wk_lo); wkl = (__nv_bfloat16*)p;
    cudaGetSymbolAddress(&p, g_wv_hi); wvh = (__nv_bfloat16*)p;
    cudaGetSymbolAddress(&p, g_wv_lo); wvl = (__nv_bfloat16*)p;
    cudaGetSymbolAddress(&p, g_wg_hi); wgh = (__nv_bfloat16*)p;
    cudaGetSymbolAddress(&p, g_wg_lo); wgl = (__nv_bfloat16*)p;
    cudaGetSymbolAddress(&p, g_wo_hi); woh = (__nv_bfloat16*)p;
    cudaGetSymbolAddress(&p, g_wo_lo); wol = (__nv_bfloat16*)p;

    const int gemm_smem = 2 * STGU * 4;   // 49152
    cudaFuncSetAttribute(gemm_mma<0>, cudaFuncAttributeMaxDynamicSharedMemorySize, gemm_smem);
    cudaFuncSetAttribute(gemm_mma<1>, cudaFuncAttributeMaxDynamicSharedMemorySize, gemm_smem);
    const int attn_smem = ATTN_SMEMF * 4;   // 90112
    cudaFuncSetAttribute(attn_mma, cudaFuncAttributeMaxDynamicSharedMemorySize, attn_smem);

    const int wblocks = (D * D + 255) / 256;
    split3<<<dim3(wblocks, 3), 256>>>(Wq, Wk, Wv, wqh, wql, wkh, wkl, wvh, wvl);
    split2<<<dim3(wblocks, 2), 256>>>(Wg, Wo, wgh, wgl, woh, wol);

    ln_kernel<<<M_TOT, 256>>>(x, gamma, beta);

    {
        GemmArgs a;
        a.Bh[0] = wqh; a.Bl[0] = wql; a.bias[0] = bq; a.C[0] = qb;
        a.Bh[1] = wkh; a.Bl[1] = wkl; a.bias[1] = bk; a.C[1] = kp;
        a.Bh[2] = wvh; a.Bl[2] = wvl; a.bias[2] = bv; a.C[2] = vp;
        a.Bh[3] = wgh; a.Bl[3] = wgl; a.bias[3] = bg; a.C[3] = gb_;
        gemm_mma<0><<<dim3(24, 64), 256, gemm_smem>>>(xnh, xnl, a);
    }

    attn_mma<<<dim3(8, NH, BATCH), 256, attn_smem>>>();

    {
        GemmArgs a;
        a.Bh[0] = woh; a.Bl[0] = wol; a.bias[0] = bo; a.C[0] = out;
        a.Bh[1] = a.Bh[2] = a.Bh[3] = woh;
        a.Bl[1] = a.Bl[2] = a.Bl[3] = wol;
        a.bias[1] = a.bias[2] = a.bias[3] = bo;
        a.C[1] = a.C[2] = a.C[3] = out;
        gemm_mma<1><<<dim3(6, 64), 256, gemm_smem>>>(yh, yl, a);
    }
}

// round 6
// speedup vs baseline: 5.0900x; 1.2609x over previous
#include <cuda_runtime.h>
#include <cuda_bf16.h>
#include <cuda_fp16.h>
#include <math.h>

#define D      768
#define T      1024
#define BATCH  8
#define M_TOT  (BATCH*T)   // 8192
#define NH     12
#define DH     64

// ---------------- scratch (device globals: alloc-free rule) ----------------
__device__ __nv_bfloat16 g_xn_hi[(size_t)M_TOT * D];
__device__ __nv_bfloat16 g_xn_lo[(size_t)M_TOT * D];
// q/k/v fp16: layout [token][head][128 halves: 64 hi | 64 lo]
__device__ __half g_q16[(size_t)M_TOT * NH * 128];
__device__ __half g_k16[(size_t)M_TOT * NH * 128];
__device__ __half g_v16[(size_t)M_TOT * NH * 128];
__device__ float  g_g  [(size_t)M_TOT * D];
__device__ __nv_bfloat16 g_y_hi[(size_t)M_TOT * D];
__device__ __nv_bfloat16 g_y_lo[(size_t)M_TOT * D];
__device__ __nv_bfloat16 g_wq_hi[D*D], g_wq_lo[D*D];
__device__ __nv_bfloat16 g_wk_hi[D*D], g_wk_lo[D*D];
__device__ __nv_bfloat16 g_wv_hi[D*D], g_wv_lo[D*D];
__device__ __nv_bfloat16 g_wg_hi[D*D], g_wg_lo[D*D];
__device__ __nv_bfloat16 g_wo_hi[D*D], g_wo_lo[D*D];

__device__ __forceinline__ unsigned pack_h2(float a, float b) {
    __half2 h = __floats2half2_rn(a, b);
    return *(unsigned*)&h;
}

// ---------------- PTX helpers -----------------------------------------------
#define CPASYNC(dst, src) \
    asm volatile("cp.async.cg.shared.global [%0], [%1], 16;" :: "r"(dst), "l"(src) : "memory")
#define CP_COMMIT() asm volatile("cp.async.commit_group;" ::: "memory")
#define CP_WAIT(n)  asm volatile("cp.async.wait_group %0;" :: "n"(n) : "memory")
#define LDSM4(R0,R1,R2,R3,A) \
    asm volatile("ldmatrix.sync.aligned.m8n8.x4.shared.b16 {%0,%1,%2,%3}, [%4];" \
                 : "=r"(R0), "=r"(R1), "=r"(R2), "=r"(R3) : "r"(A))
#define LDSM4T(R0,R1,R2,R3,A) \
    asm volatile("ldmatrix.sync.aligned.m8n8.x4.trans.shared.b16 {%0,%1,%2,%3}, [%4];" \
                 : "=r"(R0), "=r"(R1), "=r"(R2), "=r"(R3) : "r"(A))

__device__ __forceinline__ void mma_bf16(float* d, const unsigned* a, const unsigned* b) {
    asm volatile(
        "mma.sync.aligned.m16n8k16.row.col.f32.bf16.bf16.f32 "
        "{%0,%1,%2,%3}, {%4,%5,%6,%7}, {%8,%9}, {%0,%1,%2,%3};"
        : "+f"(d[0]), "+f"(d[1]), "+f"(d[2]), "+f"(d[3])
        : "r"(a[0]), "r"(a[1]), "r"(a[2]), "r"(a[3]), "r"(b[0]), "r"(b[1]));
}
__device__ __forceinline__ void mma_f16(float* d, const unsigned* a, const unsigned* b) {
    asm volatile(
        "mma.sync.aligned.m16n8k16.row.col.f32.f16.f16.f32 "
        "{%0,%1,%2,%3}, {%4,%5,%6,%7}, {%8,%9}, {%0,%1,%2,%3};"
        : "+f"(d[0]), "+f"(d[1]), "+f"(d[2]), "+f"(d[3])
        : "r"(a[0]), "r"(a[1]), "r"(a[2]), "r"(a[3]), "r"(b[0]), "r"(b[1]));
}

// ---------------- weight splits (bf16 hi/lo) ---------------------------------
__global__ __launch_bounds__(256)
void split3(const float* __restrict__ w0, const float* __restrict__ w1,
            const float* __restrict__ w2,
            __nv_bfloat16* __restrict__ h0, __nv_bfloat16* __restrict__ l0,
            __nv_bfloat16* __restrict__ h1, __nv_bfloat16* __restrict__ l1,
            __nv_bfloat16* __restrict__ h2, __nv_bfloat16* __restrict__ l2)
{
    const int i = blockIdx.x * 256 + threadIdx.x;
    if (i >= D * D) return;
    const float* w    = (blockIdx.y == 0) ? w0 : (blockIdx.y == 1) ? w1 : w2;
    __nv_bfloat16* hh = (blockIdx.y == 0) ? h0 : (blockIdx.y == 1) ? h1 : h2;
    __nv_bfloat16* ll = (blockIdx.y == 0) ? l0 : (blockIdx.y == 1) ? l1 : l2;
    const float v = w[i];
    const __nv_bfloat16 h = __float2bfloat16(v);
    hh[i] = h;
    ll[i] = __float2bfloat16(v - __bfloat162float(h));
}

__global__ __launch_bounds__(256)
void split2(const float* __restrict__ w0, const float* __restrict__ w1,
            __nv_bfloat16* __restrict__ h0, __nv_bfloat16* __restrict__ l0,
            __nv_bfloat16* __restrict__ h1, __nv_bfloat16* __restrict__ l1)
{
    const int i = blockIdx.x * 256 + threadIdx.x;
    if (i >= D * D) return;
    const float* w    = (blockIdx.y == 0) ? w0 : w1;
    __nv_bfloat16* hh = (blockIdx.y == 0) ? h0 : h1;
    __nv_bfloat16* ll = (blockIdx.y == 0) ? l0 : l1;
    const float v = w[i];
    const __nv_bfloat16 h = __float2bfloat16(v);
    hh[i] = h;
    ll[i] = __float2bfloat16(v - __bfloat162float(h));
}

// ---------------- LayerNorm + transpose + bf16 split --------------------------
__global__ __launch_bounds__(256)
void ln_kernel(const float* __restrict__ x,
               const float* __restrict__ gamma,
               const float* __restrict__ beta)
{
    const int token = blockIdx.x;
    const int b = token >> 10;
    const int t = token & 1023;
    const float* xp = x + (size_t)b * D * T + t;

    const int c0 = threadIdx.x;
    const float v0 = xp[(size_t)(c0      ) * T];
    const float v1 = xp[(size_t)(c0 + 256) * T];
    const float v2 = xp[(size_t)(c0 + 512) * T];

    float s  = v0 + v1 + v2;
    float ss = v0 * v0 + v1 * v1 + v2 * v2;
    #pragma unroll
    for (int o = 16; o > 0; o >>= 1) {
        s  += __shfl_xor_sync(0xffffffffu, s,  o);
        ss += __shfl_xor_sync(0xffffffffu, ss, o);
    }
    __shared__ float red_s[8], red_ss[8];
    const int wid = threadIdx.x >> 5, lane = threadIdx.x & 31;
    if (lane == 0) { red_s[wid] = s; red_ss[wid] = ss; }
    __syncthreads();
    float sum = 0.f, sumsq = 0.f;
    #pragma unroll
    for (int i = 0; i < 8; i++) { sum += red_s[i]; sumsq += red_ss[i]; }

    const float mu  = sum * (1.0f / (float)D);
    const float var = sumsq * (1.0f / (float)D) - mu * mu;
    const float rs  = rsqrtf(var + 1e-5f);

    __nv_bfloat16* oh = g_xn_hi + (size_t)token * D;
    __nv_bfloat16* ol = g_xn_lo + (size_t)token * D;
    #pragma unroll
    for (int j = 0; j < 3; j++) {
        const int c = c0 + j * 256;
        const float v = (j == 0 ? v0 : (j == 1 ? v1 : v2));
        const float y = (v - mu) * rs * gamma[c] + beta[c];
        const __nv_bfloat16 h = __float2bfloat16(y);
        oh[c] = h;
        ol[c] = __float2bfloat16(y - __bfloat162float(h));
    }
}

// ---------------- bf16 tensor-core GEMM (3xBF16, ldmatrix, 3-stage) -----------
struct GemmArgs {
    const __nv_bfloat16* Bh[4];
    const __nv_bfloat16* Bl[4];
    const float* bias[4];
    float*       C[4];
};

#define URO   12          // uints per smem row (8 data + 4 pad)
#define CSTG  1536        // uints per component (128*12)
#define STGU  6144        // uints per stage (4 components)
#define GSTAGES 3

template<int MODE>
__global__ __launch_bounds__(256, 2)
void gemm_mma(const __nv_bfloat16* __restrict__ Agh,
              const __nv_bfloat16* __restrict__ Agl, GemmArgs args)
{
    extern __shared__ unsigned smu[];
    const int tid = threadIdx.x;
    const int m0  = blockIdx.y * 128;

    int region, nloc0;
    if (MODE == 0) { region = blockIdx.x / 6; nloc0 = (blockIdx.x % 6) * 128; }
    else           { region = 0;              nloc0 = blockIdx.x * 128; }
    const __nv_bfloat16* Bh = args.Bh[region];
    const __nv_bfloat16* Bl = args.Bl[region];
    const float* bias = args.bias[region];
    float*       C    = args.C[region];

    const int row = tid >> 1;
    const int chn = (tid & 1) * 8;
    const __nv_bfloat16* pAh = Agh + (size_t)(m0 + row) * D + chn;
    const __nv_bfloat16* pAl = Agl + (size_t)(m0 + row) * D + chn;
    const __nv_bfloat16* pBh = Bh  + (size_t)(nloc0 + row) * D + chn;
    const __nv_bfloat16* pBl = Bl  + (size_t)(nloc0 + row) * D + chn;
    const unsigned sbase = (unsigned)__cvta_generic_to_shared(smu);
    const unsigned so = (unsigned)((row * URO + (chn >> 1)) * 4);

    auto load_stage = [&](int kt, int buf) {
        const unsigned b0 = sbase + (unsigned)buf * (STGU * 4) + so;
        CPASYNC(b0,                pAh + kt);
        CPASYNC(b0 + CSTG * 4,     pAl + kt);
        CPASYNC(b0 + 2 * CSTG * 4, pBh + kt);
        CPASYNC(b0 + 3 * CSTG * 4, pBl + kt);
        CP_COMMIT();
    };

    const int w    = tid >> 5;
    const int lane = tid & 31;
    const int wm   = w >> 2;
    const int wn   = w & 3;
    const int lr   = lane >> 2;
    const int lc   = lane & 3;

    // ldmatrix lane address components
    const int aRow  = (lane & 7) + ((lane & 8) ? 8 : 0);
    const int aColU = (lane & 16) ? 4 : 0;
    const int bRow  = (lane & 7) + ((lane & 16) ? 8 : 0);
    const int bColU = (lane & 8) ? 4 : 0;
    const unsigned aOff = (unsigned)(((wm * 64 + aRow) * URO + aColU) * 4);
    const unsigned bOff = (unsigned)(((wn * 32 + bRow) * URO + bColU) * 4);

    float acc[4][4][4];
    #pragma unroll
    for (int i = 0; i < 4; i++)
        #pragma unroll
        for (int j = 0; j < 4; j++)
            #pragma unroll
            for (int q = 0; q < 4; q++) acc[i][j][q] = 0.f;

    const int NIT = D / 16;   // 48
    load_stage(0, 0);
    load_stage(16, 1);

    for (int it = 0; it < NIT; ++it) {
        if (it + 1 < NIT) { CP_WAIT(1); } else { CP_WAIT(0); }
        __syncthreads();
        if (it + 2 < NIT) load_stage((it + 2) * 16, (it + 2) % GSTAGES);

        const unsigned stgb = sbase + (unsigned)((it % GSTAGES) * STGU * 4);
        const unsigned aH = stgb + aOff;
        const unsigned aL = aH + CSTG * 4;
        const unsigned bH = stgb + 2 * CSTG * 4 + bOff;
        const unsigned bL = bH + CSTG * 4;

        unsigned ah[4][4];
        #pragma unroll
        for (int mt = 0; mt < 4; ++mt)
            LDSM4(ah[mt][0], ah[mt][1], ah[mt][2], ah[mt][3],
                  aH + (unsigned)(mt * 16 * URO * 4));

        unsigned bh[4][2];
        {
            unsigned r0, r1, r2, r3;
            LDSM4(r0, r1, r2, r3, bH);
            bh[0][0] = r0; bh[0][1] = r1; bh[1][0] = r2; bh[1][1] = r3;
            LDSM4(r0, r1, r2, r3, bH + (unsigned)(16 * URO * 4));
            bh[2][0] = r0; bh[2][1] = r1; bh[3][0] = r2; bh[3][1] = r3;
        }
        #pragma unroll
        for (int mt = 0; mt < 4; ++mt)
            #pragma unroll
            for (int nt = 0; nt < 4; ++nt)
                mma_bf16(acc[mt][nt], ah[mt], bh[nt]);

        unsigned bl[4][2];
        {
            unsigned r0, r1, r2, r3;
            LDSM4(r0, r1, r2, r3, bL);
            bl[0][0] = r0; bl[0][1] = r1; bl[1][0] = r2; bl[1][1] = r3;
            LDSM4(r0, r1, r2, r3, bL + (unsigned)(16 * URO * 4));
            bl[2][0] = r0; bl[2][1] = r1; bl[3][0] = r2; bl[3][1] = r3;
        }
        #pragma unroll
        for (int mt = 0; mt < 4; ++mt)
            #pragma unroll
            for (int nt = 0; nt < 4; ++nt)
                mma_bf16(acc[mt][nt], ah[mt], bl[nt]);

        unsigned al[4][4];
        #pragma unroll
        for (int mt = 0; mt < 4; ++mt)
            LDSM4(al[mt][0], al[mt][1], al[mt][2], al[mt][3],
                  aL + (unsigned)(mt * 16 * URO * 4));
        #pragma unroll
        for (int mt = 0; mt < 4; ++mt)
            #pragma unroll
            for (int nt = 0; nt < 4; ++nt)
                mma_bf16(acc[mt][nt], al[mt], bh[nt]);
    }

    #pragma unroll
    for (int mt = 0; mt < 4; ++mt) {
        const int r = m0 + wm * 64 + mt * 16 + lr;
        #pragma unroll
        for (int nt = 0; nt < 4; ++nt) {
            const int n = nloc0 + wn * 32 + nt * 8 + lc * 2;
            float v00 = acc[mt][nt][0] + bias[n];
            float v01 = acc[mt][nt][1] + bias[n + 1];
            float v10 = acc[mt][nt][2] + bias[n];
            float v11 = acc[mt][nt][3] + bias[n + 1];
            if (MODE == 0) {
                if (region < 3) {
                    // q/k/v: fp16 hi/lo in head-block layout; 1/8 folded into q
                    const float sc = (region == 0) ? 0.125f : 1.0f;
                    __half* dst = (__half*)C;
                    const int head = n >> 6, wi = n & 63;
                    const float a00 = v00 * sc, a01 = v01 * sc;
                    const float a10 = v10 * sc, a11 = v11 * sc;
                    const __half h00 = __float2half_rn(a00);
                    const __half h01 = __float2half_rn(a01);
                    const __half h10 = __float2half_rn(a10);
                    const __half h11 = __float2half_rn(a11);
                    const size_t b0 = ((size_t)r * NH + head) * 128 + wi;
                    const size_t b1 = ((size_t)(r + 8) * NH + head) * 128 + wi;
                    *(__half2*)(dst + b0)      = __halves2half2(h00, h01);
                    *(__half2*)(dst + b0 + 64) = __halves2half2(
                        __float2half_rn(a00 - __half2float(h00)),
                        __float2half_rn(a01 - __half2float(h01)));
                    *(__half2*)(dst + b1)      = __halves2half2(h10, h11);
                    *(__half2*)(dst + b1 + 64) = __halves2half2(
                        __float2half_rn(a10 - __half2float(h10)),
                        __float2half_rn(a11 - __half2float(h11)));
                } else {
                    v00 = 1.0f / (1.0f + __expf(-v00));
                    v01 = 1.0f / (1.0f + __expf(-v01));
                    v10 = 1.0f / (1.0f + __expf(-v10));
                    v11 = 1.0f / (1.0f + __expf(-v11));
                    *(float2*)(C + (size_t)r * D + n)       = make_float2(v00, v01);
                    *(float2*)(C + (size_t)(r + 8) * D + n) = make_float2(v10, v11);
                }
            } else {
                const int b = r >> 10, t = r & 1023;
                C[((size_t)b * D + n    ) * T + t    ] = v00;
                C[((size_t)b * D + n + 1) * T + t    ] = v01;
                C[((size_t)b * D + n    ) * T + t + 8] = v10;
                C[((size_t)b * D + n + 1) * T + t + 8] = v11;
            }
        }
    }
}

// ---------------- fp16 tensor-core flash attention ----------------------------
// grid (8,12,8); 256 threads = 8 warps; warp = 16 q-rows × all 32 keys/tile.
// QK = qh*kh + qh*kl + ql*kh ; PV = p*vh + p*vl (p fp16 hi, register-resident).
// smem: 3 stages × (K 32x136 + V 32x136 halves) = 52224 B -> 2 CTA/SM
#define KT      32
#define NITER   (T/KT)     // 32
#define KROWH   136        // halves per smem row (128 data + 8 pad)
#define STG_B   17408      // bytes per stage (K 8704 + V 8704)
#define ATTN_SMEMB (3 * STG_B)

__global__ __launch_bounds__(256, 2)
void attn_mma()
{
    extern __shared__ __half smh[];
    const int tid  = threadIdx.x;
    const int w    = tid >> 5;
    const int lane = tid & 31;
    const int lr   = lane >> 2;
    const int lc   = lane & 3;

    const int qt = blockIdx.x;
    const int h  = blockIdx.y;
    const int b  = blockIdx.z;
    const int row0 = b * T + qt * 128;
    const unsigned sb = (unsigned)__cvta_generic_to_shared(smh);

    auto load_kv = [&](int kt, int stg) {
        #pragma unroll
        for (int i = 0; i < 2; i++) {
            const int id = tid + i * 256;          // 0..511
            const int tk = id >> 4;                 // token 0..31
            const int c  = (id & 15) * 8;           // half offset 0..120
            const size_t g = ((size_t)(b * T + kt * KT + tk) * NH + h) * 128 + c;
            const unsigned d = sb + (unsigned)(stg * STG_B) +
                               (unsigned)((tk * KROWH + c) * 2);
            CPASYNC(d,        g_k16 + g);
            CPASYNC(d + 8704, g_v16 + g);
        }
        CP_COMMIT();
    };
    load_kv(0, 0);
    load_kv(1, 1);

    // ---- Q fragments (hi+lo fp16; 1/8 already folded in) ----
    unsigned qh[4][4], ql[4][4];
    {
        const __half* r0p = g_q16 + ((size_t)(row0 + w * 16 + lr) * NH + h) * 128;
        const __half* r1p = r0p + (size_t)8 * NH * 128;
        #pragma unroll
        for (int ks = 0; ks < 4; ++ks) {
            const int c = ks * 16 + 2 * lc;
            qh[ks][0] = *(const unsigned*)(r0p + c);
            qh[ks][1] = *(const unsigned*)(r1p + c);
            qh[ks][2] = *(const unsigned*)(r0p + c + 8);
            qh[ks][3] = *(const unsigned*)(r1p + c + 8);
            ql[ks][0] = *(const unsigned*)(r0p + c + 64);
            ql[ks][1] = *(const unsigned*)(r1p + c + 64);
            ql[ks][2] = *(const unsigned*)(r0p + c + 72);
            ql[ks][3] = *(const unsigned*)(r1p + c + 72);
        }
    }

    float Oa[8][4];
    #pragma unroll
    for (int nt = 0; nt < 8; ++nt)
        #pragma unroll
        for (int q = 0; q < 4; q++) Oa[nt][q] = 0.f;
    float m0 = -1e30f, m1 = -1e30f, l0 = 0.f, l1 = 0.f;

    // ldmatrix lane address components
    const int kRow  = (lane & 7) + ((lane & 16) ? 8 : 0);   // key row (B, no-trans)
    const int kColH = (lane & 8) ? 8 : 0;
    const int vRow  = (lane & 7) + ((lane & 8) ? 8 : 0);    // token row (B, trans)
    const int vColH = (lane & 16) ? 8 : 0;

    for (int kt = 0; kt < NITER; ++kt) {
        if (kt + 1 < NITER) { CP_WAIT(1); } else { CP_WAIT(0); }
        __syncthreads();
        if (kt + 2 < NITER) load_kv(kt + 2, (kt + 2) % 3);

        const unsigned sK = sb + (unsigned)((kt % 3) * STG_B);
        const unsigned sV = sK + 8704;

        // ---- S = Q K^T ----
        float sacc[4][4];
        #pragma unroll
        for (int nt = 0; nt < 4; ++nt)
            #pragma unroll
            for (int q = 0; q < 4; q++) sacc[nt][q] = 0.f;

        #pragma unroll
        for (int ks = 0; ks < 4; ++ks) {
            unsigned kh[4][2], kl[4][2];
            {
                const unsigned a0 = sK + (unsigned)(((kRow) * KROWH + ks * 16 + kColH) * 2);
                unsigned r0, r1, r2, r3;
                LDSM4(r0, r1, r2, r3, a0);
                kh[0][0] = r0; kh[0][1] = r1; kh[1][0] = r2; kh[1][1] = r3;
                LDSM4(r0, r1, r2, r3, a0 + (unsigned)(16 * KROWH * 2));
                kh[2][0] = r0; kh[2][1] = r1; kh[3][0] = r2; kh[3][1] = r3;
                LDSM4(r0, r1, r2, r3, a0 + 128u);
                kl[0][0] = r0; kl[0][1] = r1; kl[1][0] = r2; kl[1][1] = r3;
                LDSM4(r0, r1, r2, r3, a0 + 128u + (unsigned)(16 * KROWH * 2));
                kl[2][0] = r0; kl[2][1] = r1; kl[3][0] = r2; kl[3][1] = r3;
            }
            #pragma unroll
            for (int nt = 0; nt < 4; ++nt) {
                mma_f16(sacc[nt], qh[ks], kh[nt]);
                mma_f16(sacc[nt], qh[ks], kl[nt]);
                mma_f16(sacc[nt], ql[ks], kh[nt]);
            }
        }

        // ---- online softmax ----
        float tmax0 = -1e30f, tmax1 = -1e30f;
        #pragma unroll
        for (int nt = 0; nt < 4; ++nt) {
            tmax0 = fmaxf(tmax0, fmaxf(sacc[nt][0], sacc[nt][1]));
            tmax1 = fmaxf(tmax1, fmaxf(sacc[nt][2], sacc[nt][3]));
        }
        tmax0 = fmaxf(tmax0, __shfl_xor_sync(0xffffffffu, tmax0, 1));
        tmax0 = fmaxf(tmax0, __shfl_xor_sync(0xffffffffu, tmax0, 2));
        tmax1 = fmaxf(tmax1, __shfl_xor_sync(0xffffffffu, tmax1, 1));
        tmax1 = fmaxf(tmax1, __shfl_xor_sync(0xffffffffu, tmax1, 2));

        const float mn0 = fmaxf(m0, tmax0);
        const float mn1 = fmaxf(m1, tmax1);
        const float c0 = __expf(m0 - mn0);
        const float c1 = __expf(m1 - mn1);
        l0 *= c0; l1 *= c1;
        #pragma unroll
        for (int nt = 0; nt < 8; ++nt) {
            Oa[nt][0] *= c0; Oa[nt][1] *= c0;
            Oa[nt][2] *= c1; Oa[nt][3] *= c1;
        }

        float ls0 = 0.f, ls1 = 0.f;
        #pragma unroll
        for (int nt = 0; nt < 4; ++nt) {
            sacc[nt][0] = __expf(sacc[nt][0] - mn0);
            sacc[nt][1] = __expf(sacc[nt][1] - mn0);
            sacc[nt][2] = __expf(sacc[nt][2] - mn1);
            sacc[nt][3] = __expf(sacc[nt][3] - mn1);
            ls0 += sacc[nt][0] + sacc[nt][1];
            ls1 += sacc[nt][2] + sacc[nt][3];
        }
        ls0 += __shfl_xor_sync(0xffffffffu, ls0, 1);
        ls0 += __shfl_xor_sync(0xffffffffu, ls0, 2);
        ls1 += __shfl_xor_sync(0xffffffffu, ls1, 1);
        ls1 += __shfl_xor_sync(0xffffffffu, ls1, 2);
        l0 += ls0; l1 += ls1;
        m0 = mn0; m1 = mn1;

        // ---- O += P V (P register-resident fp16) ----
        #pragma unroll
        for (int g = 0; g < 2; ++g) {
            unsigned pa[4];
            pa[0] = pack_h2(sacc[2*g][0],     sacc[2*g][1]);
            pa[1] = pack_h2(sacc[2*g][2],     sacc[2*g][3]);
            pa[2] = pack_h2(sacc[2*g+1][0],   sacc[2*g+1][1]);
            pa[3] = pack_h2(sacc[2*g+1][2],   sacc[2*g+1][3]);
            #pragma unroll
            for (int p = 0; p < 4; ++p) {
                const unsigned a0 = sV +
                    (unsigned)(((g * 16 + vRow) * KROWH + p * 16 + vColH) * 2);
                unsigned vh[2][2], vl[2][2];
                unsigned r0, r1, r2, r3;
                LDSM4T(r0, r1, r2, r3, a0);
                vh[0][0] = r0; vh[0][1] = r1; vh[1][0] = r2; vh[1][1] = r3;
                LDSM4T(r0, r1, r2, r3, a0 + 128u);
                vl[0][0] = r0; vl[0][1] = r1; vl[1][0] = r2; vl[1][1] = r3;
                mma_f16(Oa[2*p],     pa, vh[0]);
                mma_f16(Oa[2*p],     pa, vl[0]);
                mma_f16(Oa[2*p + 1], pa, vh[1]);
                mma_f16(Oa[2*p + 1], pa, vl[1]);
            }
        }
    }

    // ---- epilogue: /l, gate, bf16 split, store ----
    const float inv0 = 1.0f / l0;
    const float inv1 = 1.0f / l1;
    const int gr0 = row0 + w * 16 + lr;
    const int gr1 = gr0 + 8;
    const int col0 = h * DH;
    #pragma unroll
    for (int nt = 0; nt < 8; ++nt) {
        const int c = col0 + nt * 8 + 2 * lc;
        const float2 ga = *(const float2*)(g_g + (size_t)gr0 * D + c);
        const float2 gb = *(const float2*)(g_g + (size_t)gr1 * D + c);
        const float y00 = Oa[nt][0] * inv0 * ga.x;
        const float y01 = Oa[nt][1] * inv0 * ga.y;
        const float y10 = Oa[nt][2] * inv1 * gb.x;
        const float y11 = Oa[nt][3] * inv1 * gb.y;
        const __nv_bfloat16 h00 = __float2bfloat16(y00);
        const __nv_bfloat16 h01 = __float2bfloat16(y01);
        const __nv_bfloat16 h10 = __float2bfloat16(y10);
        const __nv_bfloat16 h11 = __float2bfloat16(y11);
        *(__nv_bfloat162*)(g_y_hi + (size_t)gr0 * D + c) = __nv_bfloat162(h00, h01);
        *(__nv_bfloat162*)(g_y_hi + (size_t)gr1 * D + c) = __nv_bfloat162(h10, h11);
        *(__nv_bfloat162*)(g_y_lo + (size_t)gr0 * D + c) =
            __nv_bfloat162(__float2bfloat16(y00 - __bfloat162float(h00)),
                           __float2bfloat16(y01 - __bfloat162float(h01)));
        *(__nv_bfloat162*)(g_y_lo + (size_t)gr1 * D + c) =
            __nv_bfloat162(__float2bfloat16(y10 - __bfloat162float(h10)),
                           __float2bfloat16(y11 - __bfloat162float(h11)));
    }
}

// ---------------- launch --------------------------------------------------------
extern "C" void kernel_launch(void* const* d_in, const int* in_sizes, int n_in,
                              void* d_out, int out_size)
{
    const float* x     = (const float*)d_in[0];
    const float* Wq    = (const float*)d_in[1];
    const float* bq    = (const float*)d_in[2];
    const float* Wk    = (const float*)d_in[3];
    const float* bk    = (const float*)d_in[4];
    const float* Wv    = (const float*)d_in[5];
    const float* bv    = (const float*)d_in[6];
    const float* Wo    = (const float*)d_in[7];
    const float* bo    = (const float*)d_in[8];
    const float* Wg    = (const float*)d_in[9];
    const float* bg    = (const float*)d_in[10];
    const float* gamma = (const float*)d_in[11];
    const float* beta  = (const float*)d_in[12];
    float* out = (float*)d_out;

    void *p;
    __nv_bfloat16 *xnh, *xnl, *yh, *yl;
    __nv_bfloat16 *wqh,*wql,*wkh,*wkl,*wvh,*wvl,*wgh,*wgl,*woh,*wol;
    __half *q16, *k16, *v16;
    float *gb_;
    cudaGetSymbolAddress(&p, g_xn_hi); xnh = (__nv_bfloat16*)p;
    cudaGetSymbolAddress(&p, g_xn_lo); xnl = (__nv_bfloat16*)p;
    cudaGetSymbolAddress(&p, g_q16);  q16 = (__half*)p;
    cudaGetSymbolAddress(&p, g_k16);  k16 = (__half*)p;
    cudaGetSymbolAddress(&p, g_v16);  v16 = (__half*)p;
    cudaGetSymbolAddress(&p, g_g);    gb_ = (float*)p;
    cudaGetSymbolAddress(&p, g_y_hi);  yh = (__nv_bfloat16*)p;
    cudaGetSymbolAddress(&p, g_y_lo);  yl = (__nv_bfloat16*)p;
    cudaGetSymbolAddress(&p, g_wq_hi); wqh = (__nv_bfloat16*)p;
    cudaGetSymbolAddress(&p, g_wq_lo); wql = (__nv_bfloat16*)p;
    cudaGetSymbolAddress(&p, g_wk_hi); wkh = (__nv_bfloat16*)p;
    cudaGetSymbolAddress(&p, g_wk_lo); wkl = (__nv_bfloat16*)p;
    cudaGetSymbolAddress(&p, g_wv_hi); wvh = (__nv_bfloat16*)p;
    cudaGetSymbolAddress(&p, g_wv_lo); wvl = (__nv_bfloat16*)p;
    cudaGetSymbolAddress(&p, g_wg_hi); wgh = (__nv_bfloat16*)p;
    cudaGetSymbolAddress(&p, g_wg_lo); wgl = (__nv_bfloat16*)p;
    cudaGetSymbolAddress(&p, g_wo_hi); woh = (__nv_bfloat16*)p;
    cudaGetSymbolAddress(&p, g_wo_lo); wol = (__nv_bfloat16*)p;

    const int gemm_smem = GSTAGES * STGU * 4;   // 73728
    cudaFuncSetAttribute(gemm_mma<0>, cudaFuncAttributeMaxDynamicSharedMemorySize, gemm_smem);
    cudaFuncSetAttribute(gemm_mma<1>, cudaFuncAttributeMaxDynamicSharedMemorySize, gemm_smem);
    cudaFuncSetAttribute(attn_mma, cudaFuncAttributeMaxDynamicSharedMemorySize, ATTN_SMEMB);

    const int wblocks = (D * D + 255) / 256;
    split3<<<dim3(wblocks, 3), 256>>>(Wq, Wk, Wv, wqh, wql, wkh, wkl, wvh, wvl);
    split2<<<dim3(wblocks, 2), 256>>>(Wg, Wo, wgh, wgl, woh, wol);

    ln_kernel<<<M_TOT, 256>>>(x, gamma, beta);

    {
        GemmArgs a;
        a.Bh[0] = wqh; a.Bl[0] = wql; a.bias[0] = bq; a.C[0] = (float*)q16;
        a.Bh[1] = wkh; a.Bl[1] = wkl; a.bias[1] = bk; a.C[1] = (float*)k16;
        a.Bh[2] = wvh; a.Bl[2] = wvl; a.bias[2] = bv; a.C[2] = (float*)v16;
        a.Bh[3] = wgh; a.Bl[3] = wgl; a.bias[3] = bg; a.C[3] = gb_;
        gemm_mma<0><<<dim3(24, 64), 256, gemm_smem>>>(xnh, xnl, a);
    }

    attn_mma<<<dim3(8, NH, BATCH), 256, ATTN_SMEMB>>>();

    {
        GemmArgs a;
        a.Bh[0] = woh; a.Bl[0] = wol; a.bias[0] = bo; a.C[0] = out;
        a.Bh[1] = a.Bh[2] = a.Bh[3] = woh;
        a.Bl[1] = a.Bl[2] = a.Bl[3] = wol;
        a.bias[1] = a.bias[2] = a.bias[3] = bo;
        a.C[1] = a.C[2] = a.C[3] = out;
        gemm_mma<1><<<dim3(6, 64), 256, gemm_smem>>>(yh, yl, a);
    }
}

// round 8
// speedup vs baseline: 6.3856x; 1.2545x over previous
#include <cuda_runtime.h>
#include <cuda_bf16.h>
#include <cuda_fp16.h>
#include <math.h>

#define D      768
#define T      1024
#define BATCH  8
#define M_TOT  (BATCH*T)   // 8192
#define NH     12
#define DH     64

// ---------------- scratch (device globals: alloc-free rule) ----------------
__device__ __half g_xn [(size_t)M_TOT * D];            // fp16 single
// q/k/v fp16: layout [token][head][128 halves: 64 hi | 64 lo]
__device__ __half g_q16[(size_t)M_TOT * NH * 128];
__device__ __half g_k16[(size_t)M_TOT * NH * 128];
__device__ __half g_v16[(size_t)M_TOT * NH * 128];
__device__ float  g_g  [(size_t)M_TOT * D];
__device__ __half g_y16[(size_t)M_TOT * D];            // fp16 single
// weights fp16 hi/lo
__device__ __half g_wq_hi[D*D], g_wq_lo[D*D];
__device__ __half g_wk_hi[D*D], g_wk_lo[D*D];
__device__ __half g_wv_hi[D*D], g_wv_lo[D*D];
__device__ __half g_wg_hi[D*D], g_wg_lo[D*D];
__device__ __half g_wo_hi[D*D], g_wo_lo[D*D];

__device__ __forceinline__ unsigned pack_h2(float a, float b) {
    __half2 h = __floats2half2_rn(a, b);
    return *(unsigned*)&h;
}

// ---------------- PTX helpers -----------------------------------------------
#define CPASYNC(dst, src) \
    asm volatile("cp.async.cg.shared.global [%0], [%1], 16;" :: "r"(dst), "l"(src) : "memory")
#define CP_COMMIT() asm volatile("cp.async.commit_group;" ::: "memory")
#define CP_WAIT(n)  asm volatile("cp.async.wait_group %0;" :: "n"(n) : "memory")
#define LDSM4(R0,R1,R2,R3,A) \
    asm volatile("ldmatrix.sync.aligned.m8n8.x4.shared.b16 {%0,%1,%2,%3}, [%4];" \
                 : "=r"(R0), "=r"(R1), "=r"(R2), "=r"(R3) : "r"(A))
#define LDSM4T(R0,R1,R2,R3,A) \
    asm volatile("ldmatrix.sync.aligned.m8n8.x4.trans.shared.b16 {%0,%1,%2,%3}, [%4];" \
                 : "=r"(R0), "=r"(R1), "=r"(R2), "=r"(R3) : "r"(A))

__device__ __forceinline__ void mma_f16(float* d, const unsigned* a, const unsigned* b) {
    asm volatile(
        "mma.sync.aligned.m16n8k16.row.col.f32.f16.f16.f32 "
        "{%0,%1,%2,%3}, {%4,%5,%6,%7}, {%8,%9}, {%0,%1,%2,%3};"
        : "+f"(d[0]), "+f"(d[1]), "+f"(d[2]), "+f"(d[3])
        : "r"(a[0]), "r"(a[1]), "r"(a[2]), "r"(a[3]), "r"(b[0]), "r"(b[1]));
}

// ---------------- weight splits (fp16 hi/lo, all 5 weights) -------------------
struct SplitArgs {
    const float* w[5];
    __half* h[5];
    __half* l[5];
};

__global__ __launch_bounds__(256)
void split5(SplitArgs a)
{
    const int i = blockIdx.x * 256 + threadIdx.x;
    if (i >= D * D) return;
    const int m = blockIdx.y;
    const float v = a.w[m][i];
    const __half h = __float2half_rn(v);
    a.h[m][i] = h;
    a.l[m][i] = __float2half_rn(v - __half2float(h));
}

// ---------------- LayerNorm + transpose + fp16 store --------------------------
__global__ __launch_bounds__(256)
void ln_kernel(const float* __restrict__ x,
               const float* __restrict__ gamma,
               const float* __restrict__ beta)
{
    const int token = blockIdx.x;
    const int b = token >> 10;
    const int t = token & 1023;
    const float* xp = x + (size_t)b * D * T + t;

    const int c0 = threadIdx.x;
    const float v0 = xp[(size_t)(c0      ) * T];
    const float v1 = xp[(size_t)(c0 + 256) * T];
    const float v2 = xp[(size_t)(c0 + 512) * T];

    float s  = v0 + v1 + v2;
    float ss = v0 * v0 + v1 * v1 + v2 * v2;
    #pragma unroll
    for (int o = 16; o > 0; o >>= 1) {
        s  += __shfl_xor_sync(0xffffffffu, s,  o);
        ss += __shfl_xor_sync(0xffffffffu, ss, o);
    }
    __shared__ float red_s[8], red_ss[8];
    const int wid = threadIdx.x >> 5, lane = threadIdx.x & 31;
    if (lane == 0) { red_s[wid] = s; red_ss[wid] = ss; }
    __syncthreads();
    float sum = 0.f, sumsq = 0.f;
    #pragma unroll
    for (int i = 0; i < 8; i++) { sum += red_s[i]; sumsq += red_ss[i]; }

    const float mu  = sum * (1.0f / (float)D);
    const float var = sumsq * (1.0f / (float)D) - mu * mu;
    const float rs  = rsqrtf(var + 1e-5f);

    __half* o = g_xn + (size_t)token * D;
    #pragma unroll
    for (int j = 0; j < 3; j++) {
        const int c = c0 + j * 256;
        const float v = (j == 0 ? v0 : (j == 1 ? v1 : v2));
        o[c] = __float2half_rn((v - mu) * rs * gamma[c] + beta[c]);
    }
}

// ---------------- fp16 tensor-core GEMM (2-pass: Ah*Bh + Ah*Bl) ---------------
// C = A(MxK)*W(NxK)^T + bias. A fp16 single, W fp16 (hi,lo).
// 128x128 tile, BK=16, 256 threads, 3-stage cp.async, ldmatrix.
struct GemmArgs {
    const __half* Bh[4];
    const __half* Bl[4];
    const float* bias[4];
    float*       C[4];
};

#define URO   12          // uints per smem row (8 data + 4 pad)
#define CSTG  1536        // uints per component (128*12)
#define STGU  4608        // uints per stage (3 components: A, Bh, Bl)
#define GSTAGES 3

template<int MODE>
__global__ __launch_bounds__(256, 2)
void gemm_mma(const __half* __restrict__ Ag, GemmArgs args)
{
    extern __shared__ unsigned smu[];
    const int tid = threadIdx.x;
    const int m0  = blockIdx.y * 128;

    int region, nloc0;
    if (MODE == 0) { region = blockIdx.x / 6; nloc0 = (blockIdx.x % 6) * 128; }
    else           { region = 0;              nloc0 = blockIdx.x * 128; }
    const __half* Bh = args.Bh[region];
    const __half* Bl = args.Bl[region];
    const float* bias = args.bias[region];
    float*       C    = args.C[region];

    const int row = tid >> 1;
    const int chn = (tid & 1) * 8;
    const __half* pA  = Ag + (size_t)(m0 + row) * D + chn;
    const __half* pBh = Bh + (size_t)(nloc0 + row) * D + chn;
    const __half* pBl = Bl + (size_t)(nloc0 + row) * D + chn;
    const unsigned sbase = (unsigned)__cvta_generic_to_shared(smu);
    const unsigned so = (unsigned)((row * URO + (chn >> 1)) * 4);

    auto load_stage = [&](int kt, int buf) {
        const unsigned b0 = sbase + (unsigned)buf * (STGU * 4) + so;
        CPASYNC(b0,                pA  + kt);
        CPASYNC(b0 + CSTG * 4,     pBh + kt);
        CPASYNC(b0 + 2 * CSTG * 4, pBl + kt);
        CP_COMMIT();
    };

    const int w    = tid >> 5;
    const int lane = tid & 31;
    const int wm   = w >> 2;
    const int wn   = w & 3;
    const int lr   = lane >> 2;
    const int lc   = lane & 3;

    const int aRow  = (lane & 7) + ((lane & 8) ? 8 : 0);
    const int aColU = (lane & 16) ? 4 : 0;
    const int bRow  = (lane & 7) + ((lane & 16) ? 8 : 0);
    const int bColU = (lane & 8) ? 4 : 0;
    const unsigned aOff = (unsigned)(((wm * 64 + aRow) * URO + aColU) * 4);
    const unsigned bOff = (unsigned)(((wn * 32 + bRow) * URO + bColU) * 4);

    float acc[4][4][4];
    #pragma unroll
    for (int i = 0; i < 4; i++)
        #pragma unroll
        for (int j = 0; j < 4; j++)
            #pragma unroll
            for (int q = 0; q < 4; q++) acc[i][j][q] = 0.f;

    const int NIT = D / 16;   // 48
    load_stage(0, 0);
    load_stage(16, 1);

    for (int it = 0; it < NIT; ++it) {
        if (it + 1 < NIT) { CP_WAIT(1); } else { CP_WAIT(0); }
        __syncthreads();
        if (it + 2 < NIT) load_stage((it + 2) * 16, (it + 2) % GSTAGES);

        const unsigned stgb = sbase + (unsigned)((it % GSTAGES) * STGU * 4);
        const unsigned aA = stgb + aOff;
        const unsigned bH = stgb + CSTG * 4 + bOff;
        const unsigned bL = stgb + 2 * CSTG * 4 + bOff;

        unsigned ah[4][4];
        #pragma unroll
        for (int mt = 0; mt < 4; ++mt)
            LDSM4(ah[mt][0], ah[mt][1], ah[mt][2], ah[mt][3],
                  aA + (unsigned)(mt * 16 * URO * 4));

        unsigned bh[4][2];
        {
            unsigned r0, r1, r2, r3;
            LDSM4(r0, r1, r2, r3, bH);
            bh[0][0] = r0; bh[0][1] = r1; bh[1][0] = r2; bh[1][1] = r3;
            LDSM4(r0, r1, r2, r3, bH + (unsigned)(16 * URO * 4));
            bh[2][0] = r0; bh[2][1] = r1; bh[3][0] = r2; bh[3][1] = r3;
        }
        #pragma unroll
        for (int mt = 0; mt < 4; ++mt)
            #pragma unroll
            for (int nt = 0; nt < 4; ++nt)
                mma_f16(acc[mt][nt], ah[mt], bh[nt]);

        unsigned bl[4][2];
        {
            unsigned r0, r1, r2, r3;
            LDSM4(r0, r1, r2, r3, bL);
            bl[0][0] = r0; bl[0][1] = r1; bl[1][0] = r2; bl[1][1] = r3;
            LDSM4(r0, r1, r2, r3, bL + (unsigned)(16 * URO * 4));
            bl[2][0] = r0; bl[2][1] = r1; bl[3][0] = r2; bl[3][1] = r3;
        }
        #pragma unroll
        for (int mt = 0; mt < 4; ++mt)
            #pragma unroll
            for (int nt = 0; nt < 4; ++nt)
                mma_f16(acc[mt][nt], ah[mt], bl[nt]);
    }

    #pragma unroll
    for (int mt = 0; mt < 4; ++mt) {
        const int r = m0 + wm * 64 + mt * 16 + lr;
        #pragma unroll
        for (int nt = 0; nt < 4; ++nt) {
            const int n = nloc0 + wn * 32 + nt * 8 + lc * 2;
            float v00 = acc[mt][nt][0] + bias[n];
            float v01 = acc[mt][nt][1] + bias[n + 1];
            float v10 = acc[mt][nt][2] + bias[n];
            float v11 = acc[mt][nt][3] + bias[n + 1];
            if (MODE == 0) {
                if (region < 3) {
                    // q/k/v: fp16 hi/lo in head-block layout; 1/8 folded into q
                    const float sc = (region == 0) ? 0.125f : 1.0f;
                    __half* dst = (region == 0) ? g_q16 : (region == 1) ? g_k16 : g_v16;
                    const int head = n >> 6, wi = n & 63;
                    const float a00 = v00 * sc, a01 = v01 * sc;
                    const float a10 = v10 * sc, a11 = v11 * sc;
                    const __half h00 = __float2half_rn(a00);
                    const __half h01 = __float2half_rn(a01);
                    const __half h10 = __float2half_rn(a10);
                    const __half h11 = __float2half_rn(a11);
                    const size_t b0 = ((size_t)r * NH + head) * 128 + wi;
                    const size_t b1 = ((size_t)(r + 8) * NH + head) * 128 + wi;
                    *(__half2*)(dst + b0)      = __halves2half2(h00, h01);
                    *(__half2*)(dst + b0 + 64) = __halves2half2(
                        __float2half_rn(a00 - __half2float(h00)),
                        __float2half_rn(a01 - __half2float(h01)));
                    *(__half2*)(dst + b1)      = __halves2half2(h10, h11);
                    *(__half2*)(dst + b1 + 64) = __halves2half2(
                        __float2half_rn(a10 - __half2float(h10)),
                        __float2half_rn(a11 - __half2float(h11)));
                } else {
                    v00 = 1.0f / (1.0f + __expf(-v00));
                    v01 = 1.0f / (1.0f + __expf(-v01));
                    v10 = 1.0f / (1.0f + __expf(-v10));
                    v11 = 1.0f / (1.0f + __expf(-v11));
                    *(float2*)(C + (size_t)r * D + n)       = make_float2(v00, v01);
                    *(float2*)(C + (size_t)(r + 8) * D + n) = make_float2(v10, v11);
                }
            } else {
                const int b = r >> 10, t = r & 1023;
                C[((size_t)b * D + n    ) * T + t    ] = v00;
                C[((size_t)b * D + n + 1) * T + t    ] = v01;
                C[((size_t)b * D + n    ) * T + t + 8] = v10;
                C[((size_t)b * D + n + 1) * T + t + 8] = v11;
            }
        }
    }
}

// ---------------- fp16 tensor-core flash attention ----------------------------
#define KT      32
#define NITER   (T/KT)
#define KROWH   136
#define STG_B   17408
#define ATTN_SMEMB (3 * STG_B)

__global__ __launch_bounds__(256, 2)
void attn_mma()
{
    extern __shared__ __half smh[];
    const int tid  = threadIdx.x;
    const int w    = tid >> 5;
    const int lane = tid & 31;
    const int lr   = lane >> 2;
    const int lc   = lane & 3;

    const int qt = blockIdx.x;
    const int h  = blockIdx.y;
    const int b  = blockIdx.z;
    const int row0 = b * T + qt * 128;
    const unsigned sb = (unsigned)__cvta_generic_to_shared(smh);

    auto load_kv = [&](int kt, int stg) {
        #pragma unroll
        for (int i = 0; i < 2; i++) {
            const int id = tid + i * 256;
            const int tk = id >> 4;
            const int c  = (id & 15) * 8;
            const size_t g = ((size_t)(b * T + kt * KT + tk) * NH + h) * 128 + c;
            const unsigned d = sb + (unsigned)(stg * STG_B) +
                               (unsigned)((tk * KROWH + c) * 2);
            CPASYNC(d,        g_k16 + g);
            CPASYNC(d + 8704, g_v16 + g);
        }
        CP_COMMIT();
    };
    load_kv(0, 0);
    load_kv(1, 1);

    unsigned qh[4][4], ql[4][4];
    {
        const __half* r0p = g_q16 + ((size_t)(row0 + w * 16 + lr) * NH + h) * 128;
        const __half* r1p = r0p + (size_t)8 * NH * 128;
        #pragma unroll
        for (int ks = 0; ks < 4; ++ks) {
            const int c = ks * 16 + 2 * lc;
            qh[ks][0] = *(const unsigned*)(r0p + c);
            qh[ks][1] = *(const unsigned*)(r1p + c);
            qh[ks][2] = *(const unsigned*)(r0p + c + 8);
            qh[ks][3] = *(const unsigned*)(r1p + c + 8);
            ql[ks][0] = *(const unsigned*)(r0p + c + 64);
            ql[ks][1] = *(const unsigned*)(r1p + c + 64);
            ql[ks][2] = *(const unsigned*)(r0p + c + 72);
            ql[ks][3] = *(const unsigned*)(r1p + c + 72);
        }
    }

    float Oa[8][4];
    #pragma unroll
    for (int nt = 0; nt < 8; ++nt)
        #pragma unroll
        for (int q = 0; q < 4; q++) Oa[nt][q] = 0.f;
    float m0 = -1e30f, m1 = -1e30f, l0 = 0.f, l1 = 0.f;

    const int kRow  = (lane & 7) + ((lane & 16) ? 8 : 0);
    const int kColH = (lane & 8) ? 8 : 0;
    const int vRow  = (lane & 7) + ((lane & 8) ? 8 : 0);
    const int vColH = (lane & 16) ? 8 : 0;

    for (int kt = 0; kt < NITER; ++kt) {
        if (kt + 1 < NITER) { CP_WAIT(1); } else { CP_WAIT(0); }
        __syncthreads();
        if (kt + 2 < NITER) load_kv(kt + 2, (kt + 2) % 3);

        const unsigned sK = sb + (unsigned)((kt % 3) * STG_B);
        const unsigned sV = sK + 8704;

        float sacc[4][4];
        #pragma unroll
        for (int nt = 0; nt < 4; ++nt)
            #pragma unroll
            for (int q = 0; q < 4; q++) sacc[nt][q] = 0.f;

        #pragma unroll
        for (int ks = 0; ks < 4; ++ks) {
            unsigned kh[4][2], kl[4][2];
            {
                const unsigned a0 = sK + (unsigned)(((kRow) * KROWH + ks * 16 + kColH) * 2);
                unsigned r0, r1, r2, r3;
                LDSM4(r0, r1, r2, r3, a0);
                kh[0][0] = r0; kh[0][1] = r1; kh[1][0] = r2; kh[1][1] = r3;
                LDSM4(r0, r1, r2, r3, a0 + (unsigned)(16 * KROWH * 2));
                kh[2][0] = r0; kh[2][1] = r1; kh[3][0] = r2; kh[3][1] = r3;
                LDSM4(r0, r1, r2, r3, a0 + 128u);
                kl[0][0] = r0; kl[0][1] = r1; kl[1][0] = r2; kl[1][1] = r3;
                LDSM4(r0, r1, r2, r3, a0 + 128u + (unsigned)(16 * KROWH * 2));
                kl[2][0] = r0; kl[2][1] = r1; kl[3][0] = r2; kl[3][1] = r3;
            }
            #pragma unroll
            for (int nt = 0; nt < 4; ++nt) {
                mma_f16(sacc[nt], qh[ks], kh[nt]);
                mma_f16(sacc[nt], qh[ks], kl[nt]);
                mma_f16(sacc[nt], ql[ks], kh[nt]);
            }
        }

        float tmax0 = -1e30f, tmax1 = -1e30f;
        #pragma unroll
        for (int nt = 0; nt < 4; ++nt) {
            tmax0 = fmaxf(tmax0, fmaxf(sacc[nt][0], sacc[nt][1]));
            tmax1 = fmaxf(tmax1, fmaxf(sacc[nt][2], sacc[nt][3]));
        }
        tmax0 = fmaxf(tmax0, __shfl_xor_sync(0xffffffffu, tmax0, 1));
        tmax0 = fmaxf(tmax0, __shfl_xor_sync(0xffffffffu, tmax0, 2));
        tmax1 = fmaxf(tmax1, __shfl_xor_sync(0xffffffffu, tmax1, 1));
        tmax1 = fmaxf(tmax1, __shfl_xor_sync(0xffffffffu, tmax1, 2));

        const float mn0 = fmaxf(m0, tmax0);
        const float mn1 = fmaxf(m1, tmax1);
        const float c0 = __expf(m0 - mn0);
        const float c1 = __expf(m1 - mn1);
        l0 *= c0; l1 *= c1;
        #pragma unroll
        for (int nt = 0; nt < 8; ++nt) {
            Oa[nt][0] *= c0; Oa[nt][1] *= c0;
            Oa[nt][2] *= c1; Oa[nt][3] *= c1;
        }

        float ls0 = 0.f, ls1 = 0.f;
        #pragma unroll
        for (int nt = 0; nt < 4; ++nt) {
            sacc[nt][0] = __expf(sacc[nt][0] - mn0);
            sacc[nt][1] = __expf(sacc[nt][1] - mn0);
            sacc[nt][2] = __expf(sacc[nt][2] - mn1);
            sacc[nt][3] = __expf(sacc[nt][3] - mn1);
            ls0 += sacc[nt][0] + sacc[nt][1];
            ls1 += sacc[nt][2] + sacc[nt][3];
        }
        ls0 += __shfl_xor_sync(0xffffffffu, ls0, 1);
        ls0 += __shfl_xor_sync(0xffffffffu, ls0, 2);
        ls1 += __shfl_xor_sync(0xffffffffu, ls1, 1);
        ls1 += __shfl_xor_sync(0xffffffffu, ls1, 2);
        l0 += ls0; l1 += ls1;
        m0 = mn0; m1 = mn1;

        #pragma unroll
        for (int g = 0; g < 2; ++g) {
            unsigned pa[4];
            pa[0] = pack_h2(sacc[2*g][0],   sacc[2*g][1]);
            pa[1] = pack_h2(sacc[2*g][2],   sacc[2*g][3]);
            pa[2] = pack_h2(sacc[2*g+1][0], sacc[2*g+1][1]);
            pa[3] = pack_h2(sacc[2*g+1][2], sacc[2*g+1][3]);
            #pragma unroll
            for (int p = 0; p < 4; ++p) {
                const unsigned a0 = sV +
                    (unsigned)(((g * 16 + vRow) * KROWH + p * 16 + vColH) * 2);
                unsigned vh[2][2], vl[2][2];
                unsigned r0, r1, r2, r3;
                LDSM4T(r0, r1, r2, r3, a0);
                vh[0][0] = r0; vh[0][1] = r1; vh[1][0] = r2; vh[1][1] = r3;
                LDSM4T(r0, r1, r2, r3, a0 + 128u);
                vl[0][0] = r0; vl[0][1] = r1; vl[1][0] = r2; vl[1][1] = r3;
                mma_f16(Oa[2*p],     pa, vh[0]);
                mma_f16(Oa[2*p],     pa, vl[0]);
                mma_f16(Oa[2*p + 1], pa, vh[1]);
                mma_f16(Oa[2*p + 1], pa, vl[1]);
            }
        }
    }

    // epilogue: /l, gate, fp16 store (single plane)
    const float inv0 = 1.0f / l0;
    const float inv1 = 1.0f / l1;
    const int gr0 = row0 + w * 16 + lr;
    const int gr1 = gr0 + 8;
    const int col0 = h * DH;
    #pragma unroll
    for (int nt = 0; nt < 8; ++nt) {
        const int c = col0 + nt * 8 + 2 * lc;
        const float2 ga = *(const float2*)(g_g + (size_t)gr0 * D + c);
        const float2 gb = *(const float2*)(g_g + (size_t)gr1 * D + c);
        *(__half2*)(g_y16 + (size_t)gr0 * D + c) =
            __floats2half2_rn(Oa[nt][0] * inv0 * ga.x, Oa[nt][1] * inv0 * ga.y);
        *(__half2*)(g_y16 + (size_t)gr1 * D + c) =
            __floats2half2_rn(Oa[nt][2] * inv1 * gb.x, Oa[nt][3] * inv1 * gb.y);
    }
}

// ---------------- launch --------------------------------------------------------
extern "C" void kernel_launch(void* const* d_in, const int* in_sizes, int n_in,
                              void* d_out, int out_size)
{
    const float* x     = (const float*)d_in[0];
    const float* Wq    = (const float*)d_in[1];
    const float* bq    = (const float*)d_in[2];
    const float* Wk    = (const float*)d_in[3];
    const float* bk    = (const float*)d_in[4];
    const float* Wv    = (const float*)d_in[5];
    const float* bv    = (const float*)d_in[6];
    const float* Wo    = (const float*)d_in[7];
    const float* bo    = (const float*)d_in[8];
    const float* Wg    = (const float*)d_in[9];
    const float* bg    = (const float*)d_in[10];
    const float* gamma = (const float*)d_in[11];
    const float* beta  = (const float*)d_in[12];
    float* out = (float*)d_out;

    void *p;
    __half *xn, *y16, *gq, *gk, *gv;
    __half *wqh,*wql,*wkh,*wkl,*wvh,*wvl,*wgh,*wgl,*woh,*wol;
    float *gb_;
    cudaGetSymbolAddress(&p, g_xn);    xn = (__half*)p;
    cudaGetSymbolAddress(&p, g_y16);  y16 = (__half*)p;
    cudaGetSymbolAddress(&p, g_q16);   gq = (__half*)p;
    cudaGetSymbolAddress(&p, g_k16);   gk = (__half*)p;
    cudaGetSymbolAddress(&p, g_v16);   gv = (__half*)p;
    cudaGetSymbolAddress(&p, g_g);    gb_ = (float*)p;
    cudaGetSymbolAddress(&p, g_wq_hi); wqh = (__half*)p;
    cudaGetSymbolAddress(&p, g_wq_lo); wql = (__half*)p;
    cudaGetSymbolAddress(&p, g_wk_hi); wkh = (__half*)p;
    cudaGetSymbolAddress(&p, g_wk_lo); wkl = (__half*)p;
    cudaGetSymbolAddress(&p, g_wv_hi); wvh = (__half*)p;
    cudaGetSymbolAddress(&p, g_wv_lo); wvl = (__half*)p;
    cudaGetSymbolAddress(&p, g_wg_hi); wgh = (__half*)p;
    cudaGetSymbolAddress(&p, g_wg_lo); wgl = (__half*)p;
    cudaGetSymbolAddress(&p, g_wo_hi); woh = (__half*)p;
    cudaGetSymbolAddress(&p, g_wo_lo); wol = (__half*)p;

    const int gemm_smem = GSTAGES * STGU * 4;   // 55296
    cudaFuncSetAttribute(gemm_mma<0>, cudaFuncAttributeMaxDynamicSharedMemorySize, gemm_smem);
    cudaFuncSetAttribute(gemm_mma<1>, cudaFuncAttributeMaxDynamicSharedMemorySize, gemm_smem);
    cudaFuncSetAttribute(attn_mma, cudaFuncAttributeMaxDynamicSharedMemorySize, ATTN_SMEMB);

    const int wblocks = (D * D + 255) / 256;
    {
        SplitArgs sa;
        sa.w[0] = Wq; sa.h[0] = wqh; sa.l[0] = wql;
        sa.w[1] = Wk; sa.h[1] = wkh; sa.l[1] = wkl;
        sa.w[2] = Wv; sa.h[2] = wvh; sa.l[2] = wvl;
        sa.w[3] = Wg; sa.h[3] = wgh; sa.l[3] = wgl;
        sa.w[4] = Wo; sa.h[4] = woh; sa.l[4] = wol;
        split5<<<dim3(wblocks, 5), 256>>>(sa);
    }

    ln_kernel<<<M_TOT, 256>>>(x, gamma, beta);

    {
        GemmArgs a;
        a.Bh[0] = wqh; a.Bl[0] = wql; a.bias[0] = bq; a.C[0] = nullptr;
        a.Bh[1] = wkh; a.Bl[1] = wkl; a.bias[1] = bk; a.C[1] = nullptr;
        a.Bh[2] = wvh; a.Bl[2] = wvl; a.bias[2] = bv; a.C[2] = nullptr;
        a.Bh[3] = wgh; a.Bl[3] = wgl; a.bias[3] = bg; a.C[3] = gb_;
        gemm_mma<0><<<dim3(24, 64), 256, gemm_smem>>>(xn, a);
    }

    attn_mma<<<dim3(8, NH, BATCH), 256, ATTN_SMEMB>>>();

    {
        GemmArgs a;
        a.Bh[0] = woh; a.Bl[0] = wol; a.bias[0] = bo; a.C[0] = out;
        a.Bh[1] = a.Bh[2] = a.Bh[3] = woh;
        a.Bl[1] = a.Bl[2] = a.Bl[3] = wol;
        a.bias[1] = a.bias[2] = a.bias[3] = bo;
        a.C[1] = a.C[2] = a.C[3] = out;
        gemm_mma<1><<<dim3(6, 64), 256, gemm_smem>>>(y16, a);
    }
}

// round 9
// speedup vs baseline: 7.0849x; 1.1095x over previous
#include <cuda_runtime.h>
#include <cuda_fp16.h>
#include <math.h>

#define D      768
#define T      1024
#define BATCH  8
#define M_TOT  (BATCH*T)   // 8192
#define NH     12
#define DH     64

// ---------------- scratch (device globals: alloc-free rule) ----------------
__device__ __half g_xn [(size_t)M_TOT * D];            // fp16 single
__device__ __half g_q16[(size_t)M_TOT * NH * 128];     // [tok][head][64 hi | 64 lo]
__device__ __half g_k16[(size_t)M_TOT * NH * 64];      // [tok][head][64] single
__device__ __half g_v16[(size_t)M_TOT * NH * 64];      // [tok][head][64] single
__device__ float  g_g  [(size_t)M_TOT * D];
__device__ __half g_y16[(size_t)M_TOT * D];            // fp16 single
__device__ __half g_wq_hi[D*D], g_wq_lo[D*D];
__device__ __half g_wk_hi[D*D], g_wk_lo[D*D];
__device__ __half g_wv_hi[D*D], g_wv_lo[D*D];
__device__ __half g_wg_hi[D*D], g_wg_lo[D*D];
__device__ __half g_wo_hi[D*D], g_wo_lo[D*D];

__device__ __forceinline__ unsigned pack_h2(float a, float b) {
    __half2 h = __floats2half2_rn(a, b);
    return *(unsigned*)&h;
}

// ---------------- PTX helpers -----------------------------------------------
#define CPASYNC(dst, src) \
    asm volatile("cp.async.cg.shared.global [%0], [%1], 16;" :: "r"(dst), "l"(src) : "memory")
#define CP_COMMIT() asm volatile("cp.async.commit_group;" ::: "memory")
#define CP_WAIT(n)  asm volatile("cp.async.wait_group %0;" :: "n"(n) : "memory")
#define LDSM4(R0,R1,R2,R3,A) \
    asm volatile("ldmatrix.sync.aligned.m8n8.x4.shared.b16 {%0,%1,%2,%3}, [%4];" \
                 : "=r"(R0), "=r"(R1), "=r"(R2), "=r"(R3) : "r"(A))
#define LDSM4T(R0,R1,R2,R3,A) \
    asm volatile("ldmatrix.sync.aligned.m8n8.x4.trans.shared.b16 {%0,%1,%2,%3}, [%4];" \
                 : "=r"(R0), "=r"(R1), "=r"(R2), "=r"(R3) : "r"(A))

__device__ __forceinline__ void mma_f16(float* d, const unsigned* a, const unsigned* b) {
    asm volatile(
        "mma.sync.aligned.m16n8k16.row.col.f32.f16.f16.f32 "
        "{%0,%1,%2,%3}, {%4,%5,%6,%7}, {%8,%9}, {%0,%1,%2,%3};"
        : "+f"(d[0]), "+f"(d[1]), "+f"(d[2]), "+f"(d[3])
        : "r"(a[0]), "r"(a[1]), "r"(a[2]), "r"(a[3]), "r"(b[0]), "r"(b[1]));
}

// ---------------- weight splits (fp16 hi/lo, all 5 weights) -------------------
struct SplitArgs {
    const float* w[5];
    __half* h[5];
    __half* l[5];
};

__global__ __launch_bounds__(256)
void split5(SplitArgs a)
{
    const int i = blockIdx.x * 256 + threadIdx.x;
    if (i >= D * D) return;
    const int m = blockIdx.y;
    const float v = a.w[m][i];
    const __half h = __float2half_rn(v);
    a.h[m][i] = h;
    a.l[m][i] = __float2half_rn(v - __half2float(h));
}

// ---------------- LayerNorm: coalesced transpose-tile ------------------------
// 32 tokens per block; smem tile st[c*33+tt]; grid 256 blocks.
#define LN_SMEMB (768 * 33 * 4 + 256)

__global__ __launch_bounds__(256)
void ln_kernel(const float* __restrict__ x,
               const float* __restrict__ gamma,
               const float* __restrict__ beta)
{
    extern __shared__ float lsm[];
    float* st = lsm;                 // [768][33]
    float* mu = lsm + 768 * 33;      // [32]
    float* rs = mu + 32;             // [32]

    const int tid = threadIdx.x;
    const int b   = blockIdx.x >> 5;
    const int t0  = (blockIdx.x & 31) * 32;
    const float* xp = x + (size_t)b * D * T + t0;

    float gm[3], bt[3];
    #pragma unroll
    for (int j = 0; j < 3; ++j) {
        gm[j] = gamma[j * 256 + tid];
        bt[j] = beta [j * 256 + tid];
    }

    #pragma unroll 4
    for (int i = 0; i < 96; ++i) {
        const int idx = i * 256 + tid;
        const int c   = idx >> 5;
        const int tt  = idx & 31;
        st[c * 33 + tt] = xp[(size_t)c * T + tt];
    }
    __syncthreads();

    const int wid = tid >> 5, lane = tid & 31;
    #pragma unroll
    for (int rep = 0; rep < 4; ++rep) {
        const int tt = wid + rep * 8;
        float s = 0.f, ss = 0.f;
        #pragma unroll
        for (int j = 0; j < 24; ++j) {
            const float v = st[(lane + 32 * j) * 33 + tt];
            s += v; ss += v * v;
        }
        #pragma unroll
        for (int o = 16; o > 0; o >>= 1) {
            s  += __shfl_xor_sync(0xffffffffu, s,  o);
            ss += __shfl_xor_sync(0xffffffffu, ss, o);
        }
        if (lane == 0) {
            const float m = s * (1.0f / (float)D);
            const float var = ss * (1.0f / (float)D) - m * m;
            mu[tt] = m;
            rs[tt] = rsqrtf(var + 1e-5f);
        }
    }
    __syncthreads();

    for (int tt = 0; tt < 32; ++tt) {
        const float m = mu[tt], r = rs[tt];
        __half* o = g_xn + (size_t)(b * T + t0 + tt) * D;
        #pragma unroll
        for (int j = 0; j < 3; ++j) {
            const int c = j * 256 + tid;
            o[c] = __float2half_rn((st[c * 33 + tt] - m) * r * gm[j] + bt[j]);
        }
    }
}

// ---------------- fp16 tensor-core GEMM (2-pass, BK=32, 3-stage) --------------
// C = A(MxK)*W(NxK)^T + bias. A fp16 single, W fp16 (hi,lo).
struct GemmArgs {
    const __half* Bh[4];
    const __half* Bl[4];
    const float* bias[4];
    float*       C[4];
};

#define URO   20          // uints per smem row (16 data + 4 pad)
#define CROWB 80          // bytes per row
#define CSTGB 10240       // bytes per component (128*80)
#define STGB  30720       // bytes per stage (3 components)
#define GSTAGES 3

template<int MODE>
__global__ __launch_bounds__(256, 2)
void gemm_mma(const __half* __restrict__ Ag, GemmArgs args)
{
    extern __shared__ unsigned smu[];
    const int tid = threadIdx.x;
    const int m0  = blockIdx.y * 128;

    int region, nloc0;
    if (MODE == 0) { region = blockIdx.x / 6; nloc0 = (blockIdx.x % 6) * 128; }
    else           { region = 0;              nloc0 = blockIdx.x * 128; }
    const __half* Bh = args.Bh[region];
    const __half* Bl = args.Bl[region];
    const float* bias = args.bias[region];
    float*       C    = args.C[region];

    // loader: row = tid>>1, two 16B chunks at ch0
    const int rw  = tid >> 1;
    const int ch0 = (tid & 1) * 16;       // halves
    const __half* pA  = Ag + (size_t)(m0 + rw) * D + ch0;
    const __half* pBh = Bh + (size_t)(nloc0 + rw) * D + ch0;
    const __half* pBl = Bl + (size_t)(nloc0 + rw) * D + ch0;
    const unsigned sbase = (unsigned)__cvta_generic_to_shared(smu);
    const unsigned soff  = (unsigned)(rw * CROWB + ch0 * 2);

    auto load_stage = [&](int kt, int buf) {   // kt in halves
        const unsigned b0 = sbase + (unsigned)buf * STGB + soff;
        CPASYNC(b0,              pA  + kt);
        CPASYNC(b0 + 16u,        pA  + kt + 8);
        CPASYNC(b0 + CSTGB,      pBh + kt);
        CPASYNC(b0 + CSTGB + 16u,pBh + kt + 8);
        CPASYNC(b0 + 2*CSTGB,      pBl + kt);
        CPASYNC(b0 + 2*CSTGB + 16u,pBl + kt + 8);
        CP_COMMIT();
    };

    const int w    = tid >> 5;
    const int lane = tid & 31;
    const int wm   = w >> 2;
    const int wn   = w & 3;
    const int lr   = lane >> 2;
    const int lc   = lane & 3;

    const int aRow  = (lane & 7) + ((lane & 8) ? 8 : 0);
    const int aColU = (lane & 16) ? 4 : 0;
    const int bRow  = (lane & 7) + ((lane & 16) ? 8 : 0);
    const int bColU = (lane & 8) ? 4 : 0;
    const unsigned aOff = (unsigned)(((wm * 64 + aRow) * URO + aColU) * 4);
    const unsigned bOff = (unsigned)(((wn * 32 + bRow) * URO + bColU) * 4);

    float acc[4][4][4];
    #pragma unroll
    for (int i = 0; i < 4; i++)
        #pragma unroll
        for (int j = 0; j < 4; j++)
            #pragma unroll
            for (int q = 0; q < 4; q++) acc[i][j][q] = 0.f;

    const int NIT = D / 32;   // 24
    load_stage(0, 0);
    load_stage(32, 1);

    for (int it = 0; it < NIT; ++it) {
        if (it + 1 < NIT) { CP_WAIT(1); } else { CP_WAIT(0); }
        __syncthreads();
        if (it + 2 < NIT) load_stage((it + 2) * 32, (it + 2) % GSTAGES);

        const unsigned stgb = sbase + (unsigned)((it % GSTAGES) * STGB);

        #pragma unroll
        for (int ks = 0; ks < 2; ++ks) {
            const unsigned ko = (unsigned)(ks * 32);  // 8 uints
            const unsigned aA = stgb + aOff + ko;
            const unsigned bH = stgb + CSTGB + bOff + ko;
            const unsigned bL = stgb + 2 * CSTGB + bOff + ko;

            unsigned ah[4][4];
            #pragma unroll
            for (int mt = 0; mt < 4; ++mt)
                LDSM4(ah[mt][0], ah[mt][1], ah[mt][2], ah[mt][3],
                      aA + (unsigned)(mt * 16 * URO * 4));

            unsigned bh[4][2];
            {
                unsigned r0, r1, r2, r3;
                LDSM4(r0, r1, r2, r3, bH);
                bh[0][0] = r0; bh[0][1] = r1; bh[1][0] = r2; bh[1][1] = r3;
                LDSM4(r0, r1, r2, r3, bH + (unsigned)(16 * URO * 4));
                bh[2][0] = r0; bh[2][1] = r1; bh[3][0] = r2; bh[3][1] = r3;
            }
            #pragma unroll
            for (int mt = 0; mt < 4; ++mt)
                #pragma unroll
                for (int nt = 0; nt < 4; ++nt)
                    mma_f16(acc[mt][nt], ah[mt], bh[nt]);

            unsigned bl[4][2];
            {
                unsigned r0, r1, r2, r3;
                LDSM4(r0, r1, r2, r3, bL);
                bl[0][0] = r0; bl[0][1] = r1; bl[1][0] = r2; bl[1][1] = r3;
                LDSM4(r0, r1, r2, r3, bL + (unsigned)(16 * URO * 4));
                bl[2][0] = r0; bl[2][1] = r1; bl[3][0] = r2; bl[3][1] = r3;
            }
            #pragma unroll
            for (int mt = 0; mt < 4; ++mt)
                #pragma unroll
                for (int nt = 0; nt < 4; ++nt)
                    mma_f16(acc[mt][nt], ah[mt], bl[nt]);
        }
    }

    #pragma unroll
    for (int mt = 0; mt < 4; ++mt) {
        const int r = m0 + wm * 64 + mt * 16 + lr;
        #pragma unroll
        for (int nt = 0; nt < 4; ++nt) {
            const int n = nloc0 + wn * 32 + nt * 8 + lc * 2;
            float v00 = acc[mt][nt][0] + bias[n];
            float v01 = acc[mt][nt][1] + bias[n + 1];
            float v10 = acc[mt][nt][2] + bias[n];
            float v11 = acc[mt][nt][3] + bias[n + 1];
            if (MODE == 0) {
                const int head = n >> 6, wi = n & 63;
                if (region == 0) {
                    // q: fp16 hi/lo, 1/8 folded in
                    const float a00 = v00 * 0.125f, a01 = v01 * 0.125f;
                    const float a10 = v10 * 0.125f, a11 = v11 * 0.125f;
                    const __half h00 = __float2half_rn(a00);
                    const __half h01 = __float2half_rn(a01);
                    const __half h10 = __float2half_rn(a10);
                    const __half h11 = __float2half_rn(a11);
                    const size_t b0 = ((size_t)r * NH + head) * 128 + wi;
                    const size_t b1 = ((size_t)(r + 8) * NH + head) * 128 + wi;
                    *(__half2*)(g_q16 + b0)      = __halves2half2(h00, h01);
                    *(__half2*)(g_q16 + b0 + 64) = __halves2half2(
                        __float2half_rn(a00 - __half2float(h00)),
                        __float2half_rn(a01 - __half2float(h01)));
                    *(__half2*)(g_q16 + b1)      = __halves2half2(h10, h11);
                    *(__half2*)(g_q16 + b1 + 64) = __halves2half2(
                        __float2half_rn(a10 - __half2float(h10)),
                        __float2half_rn(a11 - __half2float(h11)));
                } else if (region < 3) {
                    // k/v: single fp16
                    __half* dst = (region == 1) ? g_k16 : g_v16;
                    const size_t b0 = ((size_t)r * NH + head) * 64 + wi;
                    const size_t b1 = ((size_t)(r + 8) * NH + head) * 64 + wi;
                    *(__half2*)(dst + b0) = __floats2half2_rn(v00, v01);
                    *(__half2*)(dst + b1) = __floats2half2_rn(v10, v11);
                } else {
                    v00 = 1.0f / (1.0f + __expf(-v00));
                    v01 = 1.0f / (1.0f + __expf(-v01));
                    v10 = 1.0f / (1.0f + __expf(-v10));
                    v11 = 1.0f / (1.0f + __expf(-v11));
                    *(float2*)(C + (size_t)r * D + n)       = make_float2(v00, v01);
                    *(float2*)(C + (size_t)(r + 8) * D + n) = make_float2(v10, v11);
                }
            } else {
                const int b = r >> 10, t = r & 1023;
                C[((size_t)b * D + n    ) * T + t    ] = v00;
                C[((size_t)b * D + n + 1) * T + t    ] = v01;
                C[((size_t)b * D + n    ) * T + t + 8] = v10;
                C[((size_t)b * D + n + 1) * T + t + 8] = v11;
            }
        }
    }
}

// ---------------- fp16 tensor-core flash attention ----------------------------
// QK = qh*kh + ql*kh ; PV = p*vh. K/V single fp16 (32 tok x 64+8pad halves).
#define KT      32
#define NITER   (T/KT)
#define KVROWH  72         // halves per K/V smem row
#define STG_B   9216       // bytes per stage (K 4608 + V 4608)
#define ATTN_SMEMB (3 * STG_B)

__global__ __launch_bounds__(256, 2)
void attn_mma()
{
    extern __shared__ __half smh[];
    const int tid  = threadIdx.x;
    const int w    = tid >> 5;
    const int lane = tid & 31;
    const int lr   = lane >> 2;
    const int lc   = lane & 3;

    const int qt = blockIdx.x;
    const int h  = blockIdx.y;
    const int b  = blockIdx.z;
    const int row0 = b * T + qt * 128;
    const unsigned sb = (unsigned)__cvta_generic_to_shared(smh);

    auto load_kv = [&](int kt, int stg) {
        const int tk = tid >> 3;               // 0..31
        const int c  = (tid & 7) * 8;          // halves
        const size_t g = ((size_t)(b * T + kt * KT + tk) * NH + h) * 64 + c;
        const unsigned d = sb + (unsigned)(stg * STG_B) +
                           (unsigned)((tk * KVROWH + c) * 2);
        CPASYNC(d,        g_k16 + g);
        CPASYNC(d + 4608, g_v16 + g);
        CP_COMMIT();
    };
    load_kv(0, 0);
    load_kv(1, 1);

    unsigned qh[4][4], ql[4][4];
    {
        const __half* r0p = g_q16 + ((size_t)(row0 + w * 16 + lr) * NH + h) * 128;
        const __half* r1p = r0p + (size_t)8 * NH * 128;
        #pragma unroll
        for (int ks = 0; ks < 4; ++ks) {
            const int c = ks * 16 + 2 * lc;
            qh[ks][0] = *(const unsigned*)(r0p + c);
            qh[ks][1] = *(const unsigned*)(r1p + c);
            qh[ks][2] = *(const unsigned*)(r0p + c + 8);
            qh[ks][3] = *(const unsigned*)(r1p + c + 8);
            ql[ks][0] = *(const unsigned*)(r0p + c + 64);
            ql[ks][1] = *(const unsigned*)(r1p + c + 64);
            ql[ks][2] = *(const unsigned*)(r0p + c + 72);
            ql[ks][3] = *(const unsigned*)(r1p + c + 72);
        }
    }

    float Oa[8][4];
    #pragma unroll
    for (int nt = 0; nt < 8; ++nt)
        #pragma unroll
        for (int q = 0; q < 4; q++) Oa[nt][q] = 0.f;
    float m0 = -1e30f, m1 = -1e30f, l0 = 0.f, l1 = 0.f;

    const int kRow  = (lane & 7) + ((lane & 16) ? 8 : 0);
    const int kColH = (lane & 8) ? 8 : 0;
    const int vRow  = (lane & 7) + ((lane & 8) ? 8 : 0);
    const int vColH = (lane & 16) ? 8 : 0;

    for (int kt = 0; kt < NITER; ++kt) {
        if (kt + 1 < NITER) { CP_WAIT(1); } else { CP_WAIT(0); }
        __syncthreads();
        if (kt + 2 < NITER) load_kv(kt + 2, (kt + 2) % 3);

        const unsigned sK = sb + (unsigned)((kt % 3) * STG_B);
        const unsigned sV = sK + 4608;

        float sacc[4][4];
        #pragma unroll
        for (int nt = 0; nt < 4; ++nt)
            #pragma unroll
            for (int q = 0; q < 4; q++) sacc[nt][q] = 0.f;

        #pragma unroll
        for (int ks = 0; ks < 4; ++ks) {
            unsigned kh[4][2];
            {
                const unsigned a0 = sK +
                    (unsigned)((kRow * KVROWH + ks * 16 + kColH) * 2);
                unsigned r0, r1, r2, r3;
                LDSM4(r0, r1, r2, r3, a0);
                kh[0][0] = r0; kh[0][1] = r1; kh[1][0] = r2; kh[1][1] = r3;
                LDSM4(r0, r1, r2, r3, a0 + (unsigned)(16 * KVROWH * 2));
                kh[2][0] = r0; kh[2][1] = r1; kh[3][0] = r2; kh[3][1] = r3;
            }
            #pragma unroll
            for (int nt = 0; nt < 4; ++nt) {
                mma_f16(sacc[nt], qh[ks], kh[nt]);
                mma_f16(sacc[nt], ql[ks], kh[nt]);
            }
        }

        float tmax0 = -1e30f, tmax1 = -1e30f;
        #pragma unroll
        for (int nt = 0; nt < 4; ++nt) {
            tmax0 = fmaxf(tmax0, fmaxf(sacc[nt][0], sacc[nt][1]));
            tmax1 = fmaxf(tmax1, fmaxf(sacc[nt][2], sacc[nt][3]));
        }
        tmax0 = fmaxf(tmax0, __shfl_xor_sync(0xffffffffu, tmax0, 1));
        tmax0 = fmaxf(tmax0, __shfl_xor_sync(0xffffffffu, tmax0, 2));
        tmax1 = fmaxf(tmax1, __shfl_xor_sync(0xffffffffu, tmax1, 1));
        tmax1 = fmaxf(tmax1, __shfl_xor_sync(0xffffffffu, tmax1, 2));

        const float mn0 = fmaxf(m0, tmax0);
        const float mn1 = fmaxf(m1, tmax1);
        const float c0 = __expf(m0 - mn0);
        const float c1 = __expf(m1 - mn1);
        l0 *= c0; l1 *= c1;
        #pragma unroll
        for (int nt = 0; nt < 8; ++nt) {
            Oa[nt][0] *= c0; Oa[nt][1] *= c0;
            Oa[nt][2] *= c1; Oa[nt][3] *= c1;
        }

        float ls0 = 0.f, ls1 = 0.f;
        #pragma unroll
        for (int nt = 0; nt < 4; ++nt) {
            sacc[nt][0] = __expf(sacc[nt][0] - mn0);
            sacc[nt][1] = __expf(sacc[nt][1] - mn0);
            sacc[nt][2] = __expf(sacc[nt][2] - mn1);
            sacc[nt][3] = __expf(sacc[nt][3] - mn1);
            ls0 += sacc[nt][0] + sacc[nt][1];
            ls1 += sacc[nt][2] + sacc[nt][3];
        }
        ls0 += __shfl_xor_sync(0xffffffffu, ls0, 1);
        ls0 += __shfl_xor_sync(0xffffffffu, ls0, 2);
        ls1 += __shfl_xor_sync(0xffffffffu, ls1, 1);
        ls1 += __shfl_xor_sync(0xffffffffu, ls1, 2);
        l0 += ls0; l1 += ls1;
        m0 = mn0; m1 = mn1;

        #pragma unroll
        for (int g = 0; g < 2; ++g) {
            unsigned pa[4];
            pa[0] = pack_h2(sacc[2*g][0],   sacc[2*g][1]);
            pa[1] = pack_h2(sacc[2*g][2],   sacc[2*g][3]);
            pa[2] = pack_h2(sacc[2*g+1][0], sacc[2*g+1][1]);
            pa[3] = pack_h2(sacc[2*g+1][2], sacc[2*g+1][3]);
            #pragma unroll
            for (int p = 0; p < 4; ++p) {
                const unsigned a0 = sV +
                    (unsigned)(((g * 16 + vRow) * KVROWH + p * 16 + vColH) * 2);
                unsigned vh[2][2];
                unsigned r0, r1, r2, r3;
                LDSM4T(r0, r1, r2, r3, a0);
                vh[0][0] = r0; vh[0][1] = r1; vh[1][0] = r2; vh[1][1] = r3;
                mma_f16(Oa[2*p],     pa, vh[0]);
                mma_f16(Oa[2*p + 1], pa, vh[1]);
            }
        }
    }

    // epilogue: /l, gate, fp16 store (single plane)
    const float inv0 = 1.0f / l0;
    const float inv1 = 1.0f / l1;
    const int gr0 = row0 + w * 16 + lr;
    const int gr1 = gr0 + 8;
    const int col0 = h * DH;
    #pragma unroll
    for (int nt = 0; nt < 8; ++nt) {
        const int c = col0 + nt * 8 + 2 * lc;
        const float2 ga = *(const float2*)(g_g + (size_t)gr0 * D + c);
        const float2 gb = *(const float2*)(g_g + (size_t)gr1 * D + c);
        *(__half2*)(g_y16 + (size_t)gr0 * D + c) =
            __floats2half2_rn(Oa[nt][0] * inv0 * ga.x, Oa[nt][1] * inv0 * ga.y);
        *(__half2*)(g_y16 + (size_t)gr1 * D + c) =
            __floats2half2_rn(Oa[nt][2] * inv1 * gb.x, Oa[nt][3] * inv1 * gb.y);
    }
}

// ---------------- launch --------------------------------------------------------
extern "C" void kernel_launch(void* const* d_in, const int* in_sizes, int n_in,
                              void* d_out, int out_size)
{
    const float* x     = (const float*)d_in[0];
    const float* Wq    = (const float*)d_in[1];
    const float* bq    = (const float*)d_in[2];
    const float* Wk    = (const float*)d_in[3];
    const float* bk    = (const float*)d_in[4];
    const float* Wv    = (const float*)d_in[5];
    const float* bv    = (const float*)d_in[6];
    const float* Wo    = (const float*)d_in[7];
    const float* bo    = (const float*)d_in[8];
    const float* Wg    = (const float*)d_in[9];
    const float* bg    = (const float*)d_in[10];
    const float* gamma = (const float*)d_in[11];
    const float* beta  = (const float*)d_in[12];
    float* out = (float*)d_out;

    void *p;
    __half *xn, *y16;
    __half *wqh,*wql,*wkh,*wkl,*wvh,*wvl,*wgh,*wgl,*woh,*wol;
    float *gb_;
    cudaGetSymbolAddress(&p, g_xn);    xn = (__half*)p;
    cudaGetSymbolAddress(&p, g_y16);  y16 = (__half*)p;
    cudaGetSymbolAddress(&p, g_g);    gb_ = (float*)p;
    cudaGetSymbolAddress(&p, g_wq_hi); wqh = (__half*)p;
    cudaGetSymbolAddress(&p, g_wq_lo); wql = (__half*)p;
    cudaGetSymbolAddress(&p, g_wk_hi); wkh = (__half*)p;
    cudaGetSymbolAddress(&p, g_wk_lo); wkl = (__half*)p;
    cudaGetSymbolAddress(&p, g_wv_hi); wvh = (__half*)p;
    cudaGetSymbolAddress(&p, g_wv_lo); wvl = (__half*)p;
    cudaGetSymbolAddress(&p, g_wg_hi); wgh = (__half*)p;
    cudaGetSymbolAddress(&p, g_wg_lo); wgl = (__half*)p;
    cudaGetSymbolAddress(&p, g_wo_hi); woh = (__half*)p;
    cudaGetSymbolAddress(&p, g_wo_lo); wol = (__half*)p;

    const int gemm_smem = GSTAGES * STGB;   // 92160
    cudaFuncSetAttribute(gemm_mma<0>, cudaFuncAttributeMaxDynamicSharedMemorySize, gemm_smem);
    cudaFuncSetAttribute(gemm_mma<1>, cudaFuncAttributeMaxDynamicSharedMemorySize, gemm_smem);
    cudaFuncSetAttribute(attn_mma, cudaFuncAttributeMaxDynamicSharedMemorySize, ATTN_SMEMB);
    cudaFuncSetAttribute(ln_kernel, cudaFuncAttributeMaxDynamicSharedMemorySize, LN_SMEMB);

    const int wblocks = (D * D + 255) / 256;
    {
        SplitArgs sa;
        sa.w[0] = Wq; sa.h[0] = wqh; sa.l[0] = wql;
        sa.w[1] = Wk; sa.h[1] = wkh; sa.l[1] = wkl;
        sa.w[2] = Wv; sa.h[2] = wvh; sa.l[2] = wvl;
        sa.w[3] = Wg; sa.h[3] = wgh; sa.l[3] = wgl;
        sa.w[4] = Wo; sa.h[4] = woh; sa.l[4] = wol;
        split5<<<dim3(wblocks, 5), 256>>>(sa);
    }

    ln_kernel<<<256, 256, LN_SMEMB>>>(x, gamma, beta);

    {
        GemmArgs a;
        a.Bh[0] = wqh; a.Bl[0] = wql; a.bias[0] = bq; a.C[0] = nullptr;
        a.Bh[1] = wkh; a.Bl[1] = wkl; a.bias[1] = bk; a.C[1] = nullptr;
        a.Bh[2] = wvh; a.Bl[2] = wvl; a.bias[2] = bv; a.C[2] = nullptr;
        a.Bh[3] = wgh; a.Bl[3] = wgl; a.bias[3] = bg; a.C[3] = gb_;
        gemm_mma<0><<<dim3(24, 64), 256, gemm_smem>>>(xn, a);
    }

    attn_mma<<<dim3(8, NH, BATCH), 256, ATTN_SMEMB>>>();

    {
        GemmArgs a;
        a.Bh[0] = woh; a.Bl[0] = wol; a.bias[0] = bo; a.C[0] = out;
        a.Bh[1] = a.Bh[2] = a.Bh[3] = woh;
        a.Bl[1] = a.Bl[2] = a.Bl[3] = wol;
        a.bias[1] = a.bias[2] = a.bias[3] = bo;
        a.C[1] = a.C[2] = a.C[3] = out;
        gemm_mma<1><<<dim3(6, 64), 256, gemm_smem>>>(y16, a);
    }
}

// round 10
// speedup vs baseline: 7.4204x; 1.0474x over previous
#include <cuda_runtime.h>
#include <cuda_fp16.h>
#include <math.h>

#define D      768
#define T      1024
#define BATCH  8
#define M_TOT  (BATCH*T)   // 8192
#define NH     12
#define DH     64

// ---------------- scratch (device globals: alloc-free rule) ----------------
__device__ __half g_xn [(size_t)M_TOT * D];            // fp16 single
__device__ __half g_q16[(size_t)M_TOT * NH * 128];     // [tok][head][64 hi | 64 lo]
__device__ __half g_k16[(size_t)M_TOT * NH * 64];      // [tok][head][64] single
__device__ __half g_v16[(size_t)M_TOT * NH * 64];      // [tok][head][64] single
__device__ float  g_g  [(size_t)M_TOT * D];
__device__ __half g_y16[(size_t)M_TOT * D];            // fp16 single
__device__ __half g_wq_hi[D*D], g_wq_lo[D*D];
__device__ __half g_wk_hi[D*D], g_wk_lo[D*D];
__device__ __half g_wv_hi[D*D], g_wv_lo[D*D];
__device__ __half g_wg_hi[D*D], g_wg_lo[D*D];
__device__ __half g_wo_hi[D*D], g_wo_lo[D*D];

// 0.125 * log2(e): fold attention scale + exp2 conversion into Q
#define QSCALE 0.18033688011112042f

// ---------------- PTX helpers -----------------------------------------------
#define CPASYNC(dst, src) \
    asm volatile("cp.async.cg.shared.global [%0], [%1], 16;" :: "r"(dst), "l"(src) : "memory")
#define CP_COMMIT() asm volatile("cp.async.commit_group;" ::: "memory")
#define CP_WAIT(n)  asm volatile("cp.async.wait_group %0;" :: "n"(n) : "memory")
#define LDSM4(R0,R1,R2,R3,A) \
    asm volatile("ldmatrix.sync.aligned.m8n8.x4.shared.b16 {%0,%1,%2,%3}, [%4];" \
                 : "=r"(R0), "=r"(R1), "=r"(R2), "=r"(R3) : "r"(A))
#define LDSM4T(R0,R1,R2,R3,A) \
    asm volatile("ldmatrix.sync.aligned.m8n8.x4.trans.shared.b16 {%0,%1,%2,%3}, [%4];" \
                 : "=r"(R0), "=r"(R1), "=r"(R2), "=r"(R3) : "r"(A))

__device__ __forceinline__ void mma_f16(float* d, const unsigned* a, const unsigned* b) {
    asm volatile(
        "mma.sync.aligned.m16n8k16.row.col.f32.f16.f16.f32 "
        "{%0,%1,%2,%3}, {%4,%5,%6,%7}, {%8,%9}, {%0,%1,%2,%3};"
        : "+f"(d[0]), "+f"(d[1]), "+f"(d[2]), "+f"(d[3])
        : "r"(a[0]), "r"(a[1]), "r"(a[2]), "r"(a[3]), "r"(b[0]), "r"(b[1]));
}

// p16 = 2^(f16x2(a,b)) : cvt + ex2.approx.f16x2
__device__ __forceinline__ unsigned exp2_f16x2(float a, float b) {
    unsigned r;
    asm volatile("{\n\t.reg .b32 t;\n\t"
                 "cvt.rn.f16x2.f32 t, %2, %1;\n\t"
                 "ex2.approx.f16x2 %0, t;\n\t}"
                 : "=r"(r) : "f"(a), "f"(b));
    return r;
}
__device__ __forceinline__ unsigned hadd2u(unsigned a, unsigned b) {
    unsigned r;
    asm volatile("add.f16x2 %0, %1, %2;" : "=r"(r) : "r"(a), "r"(b));
    return r;
}

// ---------------- weight splits (fp16 hi/lo, all 5 weights) -------------------
struct SplitArgs {
    const float* w[5];
    __half* h[5];
    __half* l[5];
};

__global__ __launch_bounds__(256)
void split5(SplitArgs a)
{
    const int i = blockIdx.x * 256 + threadIdx.x;
    if (i >= D * D) return;
    const int m = blockIdx.y;
    const float v = a.w[m][i];
    const __half h = __float2half_rn(v);
    a.h[m][i] = h;
    a.l[m][i] = __float2half_rn(v - __half2float(h));
}

// ---------------- LayerNorm: coalesced transpose-tile ------------------------
#define LN_SMEMB (768 * 33 * 4 + 256)

__global__ __launch_bounds__(256)
void ln_kernel(const float* __restrict__ x,
               const float* __restrict__ gamma,
               const float* __restrict__ beta)
{
    extern __shared__ float lsm[];
    float* st = lsm;
    float* mu = lsm + 768 * 33;
    float* rs = mu + 32;

    const int tid = threadIdx.x;
    const int b   = blockIdx.x >> 5;
    const int t0  = (blockIdx.x & 31) * 32;
    const float* xp = x + (size_t)b * D * T + t0;

    float gm[3], bt[3];
    #pragma unroll
    for (int j = 0; j < 3; ++j) {
        gm[j] = gamma[j * 256 + tid];
        bt[j] = beta [j * 256 + tid];
    }

    #pragma unroll 4
    for (int i = 0; i < 96; ++i) {
        const int idx = i * 256 + tid;
        const int c   = idx >> 5;
        const int tt  = idx & 31;
        st[c * 33 + tt] = xp[(size_t)c * T + tt];
    }
    __syncthreads();

    const int wid = tid >> 5, lane = tid & 31;
    #pragma unroll
    for (int rep = 0; rep < 4; ++rep) {
        const int tt = wid + rep * 8;
        float s = 0.f, ss = 0.f;
        #pragma unroll
        for (int j = 0; j < 24; ++j) {
            const float v = st[(lane + 32 * j) * 33 + tt];
            s += v; ss += v * v;
        }
        #pragma unroll
        for (int o = 16; o > 0; o >>= 1) {
            s  += __shfl_xor_sync(0xffffffffu, s,  o);
            ss += __shfl_xor_sync(0xffffffffu, ss, o);
        }
        if (lane == 0) {
            const float m = s * (1.0f / (float)D);
            const float var = ss * (1.0f / (float)D) - m * m;
            mu[tt] = m;
            rs[tt] = rsqrtf(var + 1e-5f);
        }
    }
    __syncthreads();

    for (int tt = 0; tt < 32; ++tt) {
        const float m = mu[tt], r = rs[tt];
        __half* o = g_xn + (size_t)(b * T + t0 + tt) * D;
        #pragma unroll
        for (int j = 0; j < 3; ++j) {
            const int c = j * 256 + tid;
            o[c] = __float2half_rn((st[c * 33 + tt] - m) * r * gm[j] + bt[j]);
        }
    }
}

// ---------------- fp16 tensor-core GEMM (2-pass, BK=32, 3-stage) --------------
struct GemmArgs {
    const __half* Bh[4];
    const __half* Bl[4];
    const float* bias[4];
    float*       C[4];
};

#define URO   20
#define CROWB 80
#define CSTGB 10240
#define STGB  30720
#define GSTAGES 3

template<int MODE>
__global__ __launch_bounds__(256, 2)
void gemm_mma(const __half* __restrict__ Ag, GemmArgs args)
{
    extern __shared__ unsigned smu[];
    const int tid = threadIdx.x;
    const int m0  = blockIdx.y * 128;

    int region, nloc0;
    if (MODE == 0) { region = blockIdx.x / 6; nloc0 = (blockIdx.x % 6) * 128; }
    else           { region = 0;              nloc0 = blockIdx.x * 128; }
    const __half* Bh = args.Bh[region];
    const __half* Bl = args.Bl[region];
    const float* bias = args.bias[region];
    float*       C    = args.C[region];

    const int rw  = tid >> 1;
    const int ch0 = (tid & 1) * 16;
    const __half* pA  = Ag + (size_t)(m0 + rw) * D + ch0;
    const __half* pBh = Bh + (size_t)(nloc0 + rw) * D + ch0;
    const __half* pBl = Bl + (size_t)(nloc0 + rw) * D + ch0;
    const unsigned sbase = (unsigned)__cvta_generic_to_shared(smu);
    const unsigned soff  = (unsigned)(rw * CROWB + ch0 * 2);

    auto load_stage = [&](int kt, int buf) {
        const unsigned b0 = sbase + (unsigned)buf * STGB + soff;
        CPASYNC(b0,              pA  + kt);
        CPASYNC(b0 + 16u,        pA  + kt + 8);
        CPASYNC(b0 + CSTGB,      pBh + kt);
        CPASYNC(b0 + CSTGB + 16u,pBh + kt + 8);
        CPASYNC(b0 + 2*CSTGB,      pBl + kt);
        CPASYNC(b0 + 2*CSTGB + 16u,pBl + kt + 8);
        CP_COMMIT();
    };

    const int w    = tid >> 5;
    const int lane = tid & 31;
    const int wm   = w >> 2;
    const int wn   = w & 3;
    const int lr   = lane >> 2;
    const int lc   = lane & 3;

    const int aRow  = (lane & 7) + ((lane & 8) ? 8 : 0);
    const int aColU = (lane & 16) ? 4 : 0;
    const int bRow  = (lane & 7) + ((lane & 16) ? 8 : 0);
    const int bColU = (lane & 8) ? 4 : 0;
    const unsigned aOff = (unsigned)(((wm * 64 + aRow) * URO + aColU) * 4);
    const unsigned bOff = (unsigned)(((wn * 32 + bRow) * URO + bColU) * 4);

    float acc[4][4][4];
    #pragma unroll
    for (int i = 0; i < 4; i++)
        #pragma unroll
        for (int j = 0; j < 4; j++)
            #pragma unroll
            for (int q = 0; q < 4; q++) acc[i][j][q] = 0.f;

    const int NIT = D / 32;
    load_stage(0, 0);
    load_stage(32, 1);

    for (int it = 0; it < NIT; ++it) {
        if (it + 1 < NIT) { CP_WAIT(1); } else { CP_WAIT(0); }
        __syncthreads();
        if (it + 2 < NIT) load_stage((it + 2) * 32, (it + 2) % GSTAGES);

        const unsigned stgb = sbase + (unsigned)((it % GSTAGES) * STGB);

        #pragma unroll
        for (int ks = 0; ks < 2; ++ks) {
            const unsigned ko = (unsigned)(ks * 32);
            const unsigned aA = stgb + aOff + ko;
            const unsigned bH = stgb + CSTGB + bOff + ko;
            const unsigned bL = stgb + 2 * CSTGB + bOff + ko;

            unsigned ah[4][4];
            #pragma unroll
            for (int mt = 0; mt < 4; ++mt)
                LDSM4(ah[mt][0], ah[mt][1], ah[mt][2], ah[mt][3],
                      aA + (unsigned)(mt * 16 * URO * 4));

            unsigned bh[4][2];
            {
                unsigned r0, r1, r2, r3;
                LDSM4(r0, r1, r2, r3, bH);
                bh[0][0] = r0; bh[0][1] = r1; bh[1][0] = r2; bh[1][1] = r3;
                LDSM4(r0, r1, r2, r3, bH + (unsigned)(16 * URO * 4));
                bh[2][0] = r0; bh[2][1] = r1; bh[3][0] = r2; bh[3][1] = r3;
            }
            #pragma unroll
            for (int mt = 0; mt < 4; ++mt)
                #pragma unroll
                for (int nt = 0; nt < 4; ++nt)
                    mma_f16(acc[mt][nt], ah[mt], bh[nt]);

            unsigned bl[4][2];
            {
                unsigned r0, r1, r2, r3;
                LDSM4(r0, r1, r2, r3, bL);
                bl[0][0] = r0; bl[0][1] = r1; bl[1][0] = r2; bl[1][1] = r3;
                LDSM4(r0, r1, r2, r3, bL + (unsigned)(16 * URO * 4));
                bl[2][0] = r0; bl[2][1] = r1; bl[3][0] = r2; bl[3][1] = r3;
            }
            #pragma unroll
            for (int mt = 0; mt < 4; ++mt)
                #pragma unroll
                for (int nt = 0; nt < 4; ++nt)
                    mma_f16(acc[mt][nt], ah[mt], bl[nt]);
        }
    }

    if (MODE == 0) {
        #pragma unroll
        for (int mt = 0; mt < 4; ++mt) {
            const int r = m0 + wm * 64 + mt * 16 + lr;
            #pragma unroll
            for (int nt = 0; nt < 4; ++nt) {
                const int n = nloc0 + wn * 32 + nt * 8 + lc * 2;
                float v00 = acc[mt][nt][0] + bias[n];
                float v01 = acc[mt][nt][1] + bias[n + 1];
                float v10 = acc[mt][nt][2] + bias[n];
                float v11 = acc[mt][nt][3] + bias[n + 1];
                const int head = n >> 6, wi = n & 63;
                if (region == 0) {
                    // q: fp16 hi/lo, 0.125*log2e folded in
                    const float a00 = v00 * QSCALE, a01 = v01 * QSCALE;
                    const float a10 = v10 * QSCALE, a11 = v11 * QSCALE;
                    const __half h00 = __float2half_rn(a00);
                    const __half h01 = __float2half_rn(a01);
                    const __half h10 = __float2half_rn(a10);
                    const __half h11 = __float2half_rn(a11);
                    const size_t b0 = ((size_t)r * NH + head) * 128 + wi;
                    const size_t b1 = ((size_t)(r + 8) * NH + head) * 128 + wi;
                    *(__half2*)(g_q16 + b0)      = __halves2half2(h00, h01);
                    *(__half2*)(g_q16 + b0 + 64) = __halves2half2(
                        __float2half_rn(a00 - __half2float(h00)),
                        __float2half_rn(a01 - __half2float(h01)));
                    *(__half2*)(g_q16 + b1)      = __halves2half2(h10, h11);
                    *(__half2*)(g_q16 + b1 + 64) = __halves2half2(
                        __float2half_rn(a10 - __half2float(h10)),
                        __float2half_rn(a11 - __half2float(h11)));
                } else if (region < 3) {
                    __half* dst = (region == 1) ? g_k16 : g_v16;
                    const size_t b0 = ((size_t)r * NH + head) * 64 + wi;
                    const size_t b1 = ((size_t)(r + 8) * NH + head) * 64 + wi;
                    *(__half2*)(dst + b0) = __floats2half2_rn(v00, v01);
                    *(__half2*)(dst + b1) = __floats2half2_rn(v10, v11);
                } else {
                    v00 = 1.0f / (1.0f + __expf(-v00));
                    v01 = 1.0f / (1.0f + __expf(-v01));
                    v10 = 1.0f / (1.0f + __expf(-v10));
                    v11 = 1.0f / (1.0f + __expf(-v11));
                    *(float2*)(C + (size_t)r * D + n)       = make_float2(v00, v01);
                    *(float2*)(C + (size_t)(r + 8) * D + n) = make_float2(v10, v11);
                }
            }
        }
    } else {
        // coalesced output transpose via smem (stride 132, conflict-free)
        __syncthreads();
        float* sC = (float*)smu;
        #pragma unroll
        for (int mt = 0; mt < 4; ++mt) {
            const int tloc = wm * 64 + mt * 16 + lr;
            #pragma unroll
            for (int nt = 0; nt < 4; ++nt) {
                const int nl = wn * 32 + nt * 8 + lc * 2;
                sC[(size_t)nl * 132 + tloc]           = acc[mt][nt][0] + bias[nloc0 + nl];
                sC[(size_t)(nl + 1) * 132 + tloc]     = acc[mt][nt][1] + bias[nloc0 + nl + 1];
                sC[(size_t)nl * 132 + tloc + 8]       = acc[mt][nt][2] + bias[nloc0 + nl];
                sC[(size_t)(nl + 1) * 132 + tloc + 8] = acc[mt][nt][3] + bias[nloc0 + nl + 1];
            }
        }
        __syncthreads();
        const int b = m0 >> 10, t0 = m0 & 1023;
        #pragma unroll
        for (int i = 0; i < 16; ++i) {
            const int idx = tid + i * 256;     // 0..4095
            const int nl  = idx >> 5;
            const int tc  = (idx & 31) * 4;
            const float4 v = *(const float4*)&sC[(size_t)nl * 132 + tc];
            *(float4*)(C + ((size_t)b * D + nloc0 + nl) * T + t0 + tc) = v;
        }
    }
}

// ---------------- fp16 flash attention, fixed-base softmax (exp2/f16x2) -------
#define KT      32
#define NITER   (T/KT)
#define KVROWH  72
#define STG_B   9216
#define ATTN_SMEMB (3 * STG_B)

__global__ __launch_bounds__(256, 2)
void attn_mma()
{
    extern __shared__ __half smh[];
    const int tid  = threadIdx.x;
    const int w    = tid >> 5;
    const int lane = tid & 31;
    const int lr   = lane >> 2;
    const int lc   = lane & 3;

    const int qt = blockIdx.x;
    const int h  = blockIdx.y;
    const int b  = blockIdx.z;
    const int row0 = b * T + qt * 128;
    const unsigned sb = (unsigned)__cvta_generic_to_shared(smh);

    auto load_kv = [&](int kt, int stg) {
        const int tk = tid >> 3;
        const int c  = (tid & 7) * 8;
        const size_t g = ((size_t)(b * T + kt * KT + tk) * NH + h) * 64 + c;
        const unsigned d = sb + (unsigned)(stg * STG_B) +
                           (unsigned)((tk * KVROWH + c) * 2);
        CPASYNC(d,        g_k16 + g);
        CPASYNC(d + 4608, g_v16 + g);
        CP_COMMIT();
    };
    load_kv(0, 0);
    load_kv(1, 1);

    unsigned qh[4][4], ql[4][4];
    {
        const __half* r0p = g_q16 + ((size_t)(row0 + w * 16 + lr) * NH + h) * 128;
        const __half* r1p = r0p + (size_t)8 * NH * 128;
        #pragma unroll
        for (int ks = 0; ks < 4; ++ks) {
            const int c = ks * 16 + 2 * lc;
            qh[ks][0] = *(const unsigned*)(r0p + c);
            qh[ks][1] = *(const unsigned*)(r1p + c);
            qh[ks][2] = *(const unsigned*)(r0p + c + 8);
            qh[ks][3] = *(const unsigned*)(r1p + c + 8);
            ql[ks][0] = *(const unsigned*)(r0p + c + 64);
            ql[ks][1] = *(const unsigned*)(r1p + c + 64);
            ql[ks][2] = *(const unsigned*)(r0p + c + 72);
            ql[ks][3] = *(const unsigned*)(r1p + c + 72);
        }
    }

    float Oa[8][4];
    #pragma unroll
    for (int nt = 0; nt < 8; ++nt)
        #pragma unroll
        for (int q = 0; q < 4; q++) Oa[nt][q] = 0.f;
    float l0 = 0.f, l1 = 0.f;

    const int kRow  = (lane & 7) + ((lane & 16) ? 8 : 0);
    const int kColH = (lane & 8) ? 8 : 0;
    const int vRow  = (lane & 7) + ((lane & 8) ? 8 : 0);
    const int vColH = (lane & 16) ? 8 : 0;

    for (int kt = 0; kt < NITER; ++kt) {
        if (kt + 1 < NITER) { CP_WAIT(1); } else { CP_WAIT(0); }
        __syncthreads();
        if (kt + 2 < NITER) load_kv(kt + 2, (kt + 2) % 3);

        const unsigned sK = sb + (unsigned)((kt % 3) * STG_B);
        const unsigned sV = sK + 4608;

        float sacc[4][4];
        #pragma unroll
        for (int nt = 0; nt < 4; ++nt)
            #pragma unroll
            for (int q = 0; q < 4; q++) sacc[nt][q] = 0.f;

        #pragma unroll
        for (int ks = 0; ks < 4; ++ks) {
            unsigned kh[4][2];
            {
                const unsigned a0 = sK +
                    (unsigned)((kRow * KVROWH + ks * 16 + kColH) * 2);
                unsigned r0, r1, r2, r3;
                LDSM4(r0, r1, r2, r3, a0);
                kh[0][0] = r0; kh[0][1] = r1; kh[1][0] = r2; kh[1][1] = r3;
                LDSM4(r0, r1, r2, r3, a0 + (unsigned)(16 * KVROWH * 2));
                kh[2][0] = r0; kh[2][1] = r1; kh[3][0] = r2; kh[3][1] = r3;
            }
            #pragma unroll
            for (int nt = 0; nt < 4; ++nt) {
                mma_f16(sacc[nt], qh[ks], kh[nt]);
                mma_f16(sacc[nt], ql[ks], kh[nt]);
            }
        }

        // ---- fixed-base softmax: p = 2^s2 directly in fp16x2 ----
        // p16[g][j]: PV A-fragments. j0/j2 = row lr, j1/j3 = row lr+8.
        unsigned p16[2][4];
        #pragma unroll
        for (int nt = 0; nt < 4; ++nt) {
            p16[nt >> 1][(nt & 1) * 2]     = exp2_f16x2(sacc[nt][0], sacc[nt][1]);
            p16[nt >> 1][(nt & 1) * 2 + 1] = exp2_f16x2(sacc[nt][2], sacc[nt][3]);
        }
        // l partial sums (one hadd2 level, then f32)
        {
            const unsigned s0a = hadd2u(p16[0][0], p16[0][2]);
            const unsigned s0b = hadd2u(p16[1][0], p16[1][2]);
            const unsigned s1a = hadd2u(p16[0][1], p16[0][3]);
            const unsigned s1b = hadd2u(p16[1][1], p16[1][3]);
            const float2 f0a = __half22float2(*(const __half2*)&s0a);
            const float2 f0b = __half22float2(*(const __half2*)&s0b);
            const float2 f1a = __half22float2(*(const __half2*)&s1a);
            const float2 f1b = __half22float2(*(const __half2*)&s1b);
            l0 += (f0a.x + f0a.y) + (f0b.x + f0b.y);
            l1 += (f1a.x + f1a.y) + (f1b.x + f1b.y);
        }

        // ---- O += P V ----
        #pragma unroll
        for (int g = 0; g < 2; ++g) {
            #pragma unroll
            for (int p = 0; p < 4; ++p) {
                const unsigned a0 = sV +
                    (unsigned)(((g * 16 + vRow) * KVROWH + p * 16 + vColH) * 2);
                unsigned vh[2][2];
                unsigned r0, r1, r2, r3;
                LDSM4T(r0, r1, r2, r3, a0);
                vh[0][0] = r0; vh[0][1] = r1; vh[1][0] = r2; vh[1][1] = r3;
                mma_f16(Oa[2*p],     p16[g], vh[0]);
                mma_f16(Oa[2*p + 1], p16[g], vh[1]);
            }
        }
    }

    // final l reduction across quad
    l0 += __shfl_xor_sync(0xffffffffu, l0, 1);
    l0 += __shfl_xor_sync(0xffffffffu, l0, 2);
    l1 += __shfl_xor_sync(0xffffffffu, l1, 1);
    l1 += __shfl_xor_sync(0xffffffffu, l1, 2);

    const float inv0 = 1.0f / l0;
    const float inv1 = 1.0f / l1;
    const int gr0 = row0 + w * 16 + lr;
    const int gr1 = gr0 + 8;
    const int col0 = h * DH;
    #pragma unroll
    for (int nt = 0; nt < 8; ++nt) {
        const int c = col0 + nt * 8 + 2 * lc;
        const float2 ga = *(const float2*)(g_g + (size_t)gr0 * D + c);
        const float2 gb = *(const float2*)(g_g + (size_t)gr1 * D + c);
        *(__half2*)(g_y16 + (size_t)gr0 * D + c) =
            __floats2half2_rn(Oa[nt][0] * inv0 * ga.x, Oa[nt][1] * inv0 * ga.y);
        *(__half2*)(g_y16 + (size_t)gr1 * D + c) =
            __floats2half2_rn(Oa[nt][2] * inv1 * gb.x, Oa[nt][3] * inv1 * gb.y);
    }
}

// ---------------- launch --------------------------------------------------------
extern "C" void kernel_launch(void* const* d_in, const int* in_sizes, int n_in,
                              void* d_out, int out_size)
{
    const float* x     = (const float*)d_in[0];
    const float* Wq    = (const float*)d_in[1];
    const float* bq    = (const float*)d_in[2];
    const float* Wk    = (const float*)d_in[3];
    const float* bk    = (const float*)d_in[4];
    const float* Wv    = (const float*)d_in[5];
    const float* bv    = (const float*)d_in[6];
    const float* Wo    = (const float*)d_in[7];
    const float* bo    = (const float*)d_in[8];
    const float* Wg    = (const float*)d_in[9];
    const float* bg    = (const float*)d_in[10];
    const float* gamma = (const float*)d_in[11];
    const float* beta  = (const float*)d_in[12];
    float* out = (float*)d_out;

    void *p;
    __half *xn, *y16;
    __half *wqh,*wql,*wkh,*wkl,*wvh,*wvl,*wgh,*wgl,*woh,*wol;
    float *gb_;
    cudaGetSymbolAddress(&p, g_xn);    xn = (__half*)p;
    cudaGetSymbolAddress(&p, g_y16);  y16 = (__half*)p;
    cudaGetSymbolAddress(&p, g_g);    gb_ = (float*)p;
    cudaGetSymbolAddress(&p, g_wq_hi); wqh = (__half*)p;
    cudaGetSymbolAddress(&p, g_wq_lo); wql = (__half*)p;
    cudaGetSymbolAddress(&p, g_wk_hi); wkh = (__half*)p;
    cudaGetSymbolAddress(&p, g_wk_lo); wkl = (__half*)p;
    cudaGetSymbolAddress(&p, g_wv_hi); wvh = (__half*)p;
    cudaGetSymbolAddress(&p, g_wv_lo); wvl = (__half*)p;
    cudaGetSymbolAddress(&p, g_wg_hi); wgh = (__half*)p;
    cudaGetSymbolAddress(&p, g_wg_lo); wgl = (__half*)p;
    cudaGetSymbolAddress(&p, g_wo_hi); woh = (__half*)p;
    cudaGetSymbolAddress(&p, g_wo_lo); wol = (__half*)p;

    const int gemm_smem = GSTAGES * STGB;   // 92160 (also covers 128x132 f32 sC)
    cudaFuncSetAttribute(gemm_mma<0>, cudaFuncAttributeMaxDynamicSharedMemorySize, gemm_smem);
    cudaFuncSetAttribute(gemm_mma<1>, cudaFuncAttributeMaxDynamicSharedMemorySize, gemm_smem);
    cudaFuncSetAttribute(attn_mma, cudaFuncAttributeMaxDynamicSharedMemorySize, ATTN_SMEMB);
    cudaFuncSetAttribute(ln_kernel, cudaFuncAttributeMaxDynamicSharedMemorySize, LN_SMEMB);

    const int wblocks = (D * D + 255) / 256;
    {
        SplitArgs sa;
        sa.w[0] = Wq; sa.h[0] = wqh; sa.l[0] = wql;
        sa.w[1] = Wk; sa.h[1] = wkh; sa.l[1] = wkl;
        sa.w[2] = Wv; sa.h[2] = wvh; sa.l[2] = wvl;
        sa.w[3] = Wg; sa.h[3] = wgh; sa.l[3] = wgl;
        sa.w[4] = Wo; sa.h[4] = woh; sa.l[4] = wol;
        split5<<<dim3(wblocks, 5), 256>>>(sa);
    }

    ln_kernel<<<256, 256, LN_SMEMB>>>(x, gamma, beta);

    {
        GemmArgs a;
        a.Bh[0] = wqh; a.Bl[0] = wql; a.bias[0] = bq; a.C[0] = nullptr;
        a.Bh[1] = wkh; a.Bl[1] = wkl; a.bias[1] = bk; a.C[1] = nullptr;
        a.Bh[2] = wvh; a.Bl[2] = wvl; a.bias[2] = bv; a.C[2] = nullptr;
        a.Bh[3] = wgh; a.Bl[3] = wgl; a.bias[3] = bg; a.C[3] = gb_;
        gemm_mma<0><<<dim3(24, 64), 256, gemm_smem>>>(xn, a);
    }

    attn_mma<<<dim3(8, NH, BATCH), 256, ATTN_SMEMB>>>();

    {
        GemmArgs a;
        a.Bh[0] = woh; a.Bl[0] = wol; a.bias[0] = bo; a.C[0] = out;
        a.Bh[1] = a.Bh[2] = a.Bh[3] = woh;
        a.Bl[1] = a.Bl[2] = a.Bl[3] = wol;
        a.bias[1] = a.bias[2] = a.bias[3] = bo;
        a.C[1] = a.C[2] = a.C[3] = out;
        gemm_mma<1><<<dim3(6, 64), 256, gemm_smem>>>(y16, a);
    }
}

// round 11
// speedup vs baseline: 8.4669x; 1.1410x over previous
#include <cuda_runtime.h>
#include <cuda_fp16.h>
#include <math.h>

#define D      768
#define T      1024
#define BATCH  8
#define M_TOT  (BATCH*T)   // 8192
#define NH     12
#define DH     64

// ---------------- scratch (device globals: alloc-free rule) ----------------
__device__ __half g_xn [(size_t)M_TOT * D];            // fp16 single
__device__ __half g_q16[(size_t)M_TOT * NH * 128];     // [tok][head][64 hi | 64 lo]
__device__ __half g_k16[(size_t)M_TOT * NH * 64];      // [tok][head][64] single
__device__ __half g_v16[(size_t)M_TOT * NH * 64];      // [tok][head][64] single
__device__ float  g_g  [(size_t)M_TOT * D];
__device__ __half g_y16[(size_t)M_TOT * D];            // fp16 single
__device__ __half g_wq_hi[D*D], g_wq_lo[D*D];
__device__ __half g_wk_hi[D*D];
__device__ __half g_wv_hi[D*D];
__device__ __half g_wg_hi[D*D];
__device__ __half g_wo_hi[D*D], g_wo_lo[D*D];

// 0.125 * log2(e): fold attention scale + exp2 conversion into Q
#define QSCALE 0.18033688011112042f

// ---------------- PTX helpers -----------------------------------------------
#define CPASYNC(dst, src) \
    asm volatile("cp.async.cg.shared.global [%0], [%1], 16;" :: "r"(dst), "l"(src) : "memory")
#define CP_COMMIT() asm volatile("cp.async.commit_group;" ::: "memory")
#define CP_WAIT(n)  asm volatile("cp.async.wait_group %0;" :: "n"(n) : "memory")
#define LDSM4(R0,R1,R2,R3,A) \
    asm volatile("ldmatrix.sync.aligned.m8n8.x4.shared.b16 {%0,%1,%2,%3}, [%4];" \
                 : "=r"(R0), "=r"(R1), "=r"(R2), "=r"(R3) : "r"(A))
#define LDSM4T(R0,R1,R2,R3,A) \
    asm volatile("ldmatrix.sync.aligned.m8n8.x4.trans.shared.b16 {%0,%1,%2,%3}, [%4];" \
                 : "=r"(R0), "=r"(R1), "=r"(R2), "=r"(R3) : "r"(A))

__device__ __forceinline__ void mma_f16(float* d, const unsigned* a, const unsigned* b) {
    asm volatile(
        "mma.sync.aligned.m16n8k16.row.col.f32.f16.f16.f32 "
        "{%0,%1,%2,%3}, {%4,%5,%6,%7}, {%8,%9}, {%0,%1,%2,%3};"
        : "+f"(d[0]), "+f"(d[1]), "+f"(d[2]), "+f"(d[3])
        : "r"(a[0]), "r"(a[1]), "r"(a[2]), "r"(a[3]), "r"(b[0]), "r"(b[1]));
}

__device__ __forceinline__ unsigned exp2_f16x2(float a, float b) {
    unsigned r;
    asm volatile("{\n\t.reg .b32 t;\n\t"
                 "cvt.rn.f16x2.f32 t, %2, %1;\n\t"
                 "ex2.approx.f16x2 %0, t;\n\t}"
                 : "=r"(r) : "f"(a), "f"(b));
    return r;
}
__device__ __forceinline__ unsigned hadd2u(unsigned a, unsigned b) {
    unsigned r;
    asm volatile("add.f16x2 %0, %1, %2;" : "=r"(r) : "r"(a), "r"(b));
    return r;
}

// ---------------- weight prep: q/Wo split hi/lo; k/v/g hi only ----------------
struct SplitArgs {
    const float* w[5];
    __half* h[5];
    __half* l[5];      // null semantics: only 0 and 4 used
};

__global__ __launch_bounds__(256)
void split5(SplitArgs a)
{
    const int i = blockIdx.x * 256 + threadIdx.x;
    if (i >= D * D) return;
    const int m = blockIdx.y;
    const float v = a.w[m][i];
    const __half h = __float2half_rn(v);
    a.h[m][i] = h;
    if (m == 0 || m == 4)
        a.l[m][i] = __float2half_rn(v - __half2float(h));
}

// ---------------- LayerNorm: coalesced transpose-tile ------------------------
#define LN_SMEMB (768 * 33 * 4 + 256)

__global__ __launch_bounds__(256)
void ln_kernel(const float* __restrict__ x,
               const float* __restrict__ gamma,
               const float* __restrict__ beta)
{
    extern __shared__ float lsm[];
    float* st = lsm;
    float* mu = lsm + 768 * 33;
    float* rs = mu + 32;

    const int tid = threadIdx.x;
    const int b   = blockIdx.x >> 5;
    const int t0  = (blockIdx.x & 31) * 32;
    const float* xp = x + (size_t)b * D * T + t0;

    float gm[3], bt[3];
    #pragma unroll
    for (int j = 0; j < 3; ++j) {
        gm[j] = gamma[j * 256 + tid];
        bt[j] = beta [j * 256 + tid];
    }

    #pragma unroll 4
    for (int i = 0; i < 96; ++i) {
        const int idx = i * 256 + tid;
        const int c   = idx >> 5;
        const int tt  = idx & 31;
        st[c * 33 + tt] = xp[(size_t)c * T + tt];
    }
    __syncthreads();

    const int wid = tid >> 5, lane = tid & 31;
    #pragma unroll
    for (int rep = 0; rep < 4; ++rep) {
        const int tt = wid + rep * 8;
        float s = 0.f, ss = 0.f;
        #pragma unroll
        for (int j = 0; j < 24; ++j) {
            const float v = st[(lane + 32 * j) * 33 + tt];
            s += v; ss += v * v;
        }
        #pragma unroll
        for (int o = 16; o > 0; o >>= 1) {
            s  += __shfl_xor_sync(0xffffffffu, s,  o);
            ss += __shfl_xor_sync(0xffffffffu, ss, o);
        }
        if (lane == 0) {
            const float m = s * (1.0f / (float)D);
            const float var = ss * (1.0f / (float)D) - m * m;
            mu[tt] = m;
            rs[tt] = rsqrtf(var + 1e-5f);
        }
    }
    __syncthreads();

    for (int tt = 0; tt < 32; ++tt) {
        const float m = mu[tt], r = rs[tt];
        __half* o = g_xn + (size_t)(b * T + t0 + tt) * D;
        #pragma unroll
        for (int j = 0; j < 3; ++j) {
            const int c = j * 256 + tid;
            o[c] = __float2half_rn((st[c * 33 + tt] - m) * r * gm[j] + bt[j]);
        }
    }
}

// ---------------- fp16 tensor-core GEMM (1 or 2 pass, BK=32, 3-stage) ---------
struct GemmArgs {
    const __half* Bh[4];
    const __half* Bl[4];       // used only when region is 2-pass
    const float* bias[4];
    float*       C[4];
};

#define URO   20
#define CROWB 80
#define CSTGB 10240
#define STGB  30720
#define GSTAGES 3

template<int MODE>
__global__ __launch_bounds__(256, 2)
void gemm_mma(const __half* __restrict__ Ag, GemmArgs args)
{
    extern __shared__ unsigned smu[];
    const int tid = threadIdx.x;
    const int m0  = blockIdx.y * 128;

    int region, nloc0;
    if (MODE == 0) { region = blockIdx.x / 6; nloc0 = (blockIdx.x % 6) * 128; }
    else           { region = 0;              nloc0 = blockIdx.x * 128; }
    const bool twopass = (MODE == 1) || (region == 0);
    const __half* Bh = args.Bh[region];
    const __half* Bl = args.Bl[region];
    const float* bias = args.bias[region];
    float*       C    = args.C[region];

    const int rw  = tid >> 1;
    const int ch0 = (tid & 1) * 16;
    const __half* pA  = Ag + (size_t)(m0 + rw) * D + ch0;
    const __half* pBh = Bh + (size_t)(nloc0 + rw) * D + ch0;
    const __half* pBl = Bl + (size_t)(nloc0 + rw) * D + ch0;
    const unsigned sbase = (unsigned)__cvta_generic_to_shared(smu);
    const unsigned soff  = (unsigned)(rw * CROWB + ch0 * 2);

    auto load_stage = [&](int kt, int buf) {
        const unsigned b0 = sbase + (unsigned)buf * STGB + soff;
        CPASYNC(b0,              pA  + kt);
        CPASYNC(b0 + 16u,        pA  + kt + 8);
        CPASYNC(b0 + CSTGB,      pBh + kt);
        CPASYNC(b0 + CSTGB + 16u,pBh + kt + 8);
        if (twopass) {
            CPASYNC(b0 + 2*CSTGB,      pBl + kt);
            CPASYNC(b0 + 2*CSTGB + 16u,pBl + kt + 8);
        }
        CP_COMMIT();
    };

    const int w    = tid >> 5;
    const int lane = tid & 31;
    const int wm   = w >> 2;
    const int wn   = w & 3;
    const int lr   = lane >> 2;
    const int lc   = lane & 3;

    const int aRow  = (lane & 7) + ((lane & 8) ? 8 : 0);
    const int aColU = (lane & 16) ? 4 : 0;
    const int bRow  = (lane & 7) + ((lane & 16) ? 8 : 0);
    const int bColU = (lane & 8) ? 4 : 0;
    const unsigned aOff = (unsigned)(((wm * 64 + aRow) * URO + aColU) * 4);
    const unsigned bOff = (unsigned)(((wn * 32 + bRow) * URO + bColU) * 4);

    float acc[4][4][4];
    #pragma unroll
    for (int i = 0; i < 4; i++)
        #pragma unroll
        for (int j = 0; j < 4; j++)
            #pragma unroll
            for (int q = 0; q < 4; q++) acc[i][j][q] = 0.f;

    const int NIT = D / 32;
    load_stage(0, 0);
    load_stage(32, 1);

    for (int it = 0; it < NIT; ++it) {
        if (it + 1 < NIT) { CP_WAIT(1); } else { CP_WAIT(0); }
        __syncthreads();
        if (it + 2 < NIT) load_stage((it + 2) * 32, (it + 2) % GSTAGES);

        const unsigned stgb = sbase + (unsigned)((it % GSTAGES) * STGB);

        #pragma unroll
        for (int ks = 0; ks < 2; ++ks) {
            const unsigned ko = (unsigned)(ks * 32);
            const unsigned aA = stgb + aOff + ko;
            const unsigned bH = stgb + CSTGB + bOff + ko;
            const unsigned bL = stgb + 2 * CSTGB + bOff + ko;

            unsigned ah[4][4];
            #pragma unroll
            for (int mt = 0; mt < 4; ++mt)
                LDSM4(ah[mt][0], ah[mt][1], ah[mt][2], ah[mt][3],
                      aA + (unsigned)(mt * 16 * URO * 4));

            unsigned bh[4][2];
            {
                unsigned r0, r1, r2, r3;
                LDSM4(r0, r1, r2, r3, bH);
                bh[0][0] = r0; bh[0][1] = r1; bh[1][0] = r2; bh[1][1] = r3;
                LDSM4(r0, r1, r2, r3, bH + (unsigned)(16 * URO * 4));
                bh[2][0] = r0; bh[2][1] = r1; bh[3][0] = r2; bh[3][1] = r3;
            }
            #pragma unroll
            for (int mt = 0; mt < 4; ++mt)
                #pragma unroll
                for (int nt = 0; nt < 4; ++nt)
                    mma_f16(acc[mt][nt], ah[mt], bh[nt]);

            if (twopass) {
                unsigned bl[4][2];
                unsigned r0, r1, r2, r3;
                LDSM4(r0, r1, r2, r3, bL);
                bl[0][0] = r0; bl[0][1] = r1; bl[1][0] = r2; bl[1][1] = r3;
                LDSM4(r0, r1, r2, r3, bL + (unsigned)(16 * URO * 4));
                bl[2][0] = r0; bl[2][1] = r1; bl[3][0] = r2; bl[3][1] = r3;
                #pragma unroll
                for (int mt = 0; mt < 4; ++mt)
                    #pragma unroll
                    for (int nt = 0; nt < 4; ++nt)
                        mma_f16(acc[mt][nt], ah[mt], bl[nt]);
            }
        }
    }

    if (MODE == 0) {
        #pragma unroll
        for (int mt = 0; mt < 4; ++mt) {
            const int r = m0 + wm * 64 + mt * 16 + lr;
            #pragma unroll
            for (int nt = 0; nt < 4; ++nt) {
                const int n = nloc0 + wn * 32 + nt * 8 + lc * 2;
                float v00 = acc[mt][nt][0] + bias[n];
                float v01 = acc[mt][nt][1] + bias[n + 1];
                float v10 = acc[mt][nt][2] + bias[n];
                float v11 = acc[mt][nt][3] + bias[n + 1];
                const int head = n >> 6, wi = n & 63;
                if (region == 0) {
                    const float a00 = v00 * QSCALE, a01 = v01 * QSCALE;
                    const float a10 = v10 * QSCALE, a11 = v11 * QSCALE;
                    const __half h00 = __float2half_rn(a00);
                    const __half h01 = __float2half_rn(a01);
                    const __half h10 = __float2half_rn(a10);
                    const __half h11 = __float2half_rn(a11);
                    const size_t b0 = ((size_t)r * NH + head) * 128 + wi;
                    const size_t b1 = ((size_t)(r + 8) * NH + head) * 128 + wi;
                    *(__half2*)(g_q16 + b0)      = __halves2half2(h00, h01);
                    *(__half2*)(g_q16 + b0 + 64) = __halves2half2(
                        __float2half_rn(a00 - __half2float(h00)),
                        __float2half_rn(a01 - __half2float(h01)));
                    *(__half2*)(g_q16 + b1)      = __halves2half2(h10, h11);
                    *(__half2*)(g_q16 + b1 + 64) = __halves2half2(
                        __float2half_rn(a10 - __half2float(h10)),
                        __float2half_rn(a11 - __half2float(h11)));
                } else if (region < 3) {
                    __half* dst = (region == 1) ? g_k16 : g_v16;
                    const size_t b0 = ((size_t)r * NH + head) * 64 + wi;
                    const size_t b1 = ((size_t)(r + 8) * NH + head) * 64 + wi;
                    *(__half2*)(dst + b0) = __floats2half2_rn(v00, v01);
                    *(__half2*)(dst + b1) = __floats2half2_rn(v10, v11);
                } else {
                    v00 = 1.0f / (1.0f + __expf(-v00));
                    v01 = 1.0f / (1.0f + __expf(-v01));
                    v10 = 1.0f / (1.0f + __expf(-v10));
                    v11 = 1.0f / (1.0f + __expf(-v11));
                    *(float2*)(C + (size_t)r * D + n)       = make_float2(v00, v01);
                    *(float2*)(C + (size_t)(r + 8) * D + n) = make_float2(v10, v11);
                }
            }
        }
    } else {
        // coalesced output transpose via smem (stride 132, conflict-free)
        __syncthreads();
        float* sC = (float*)smu;
        #pragma unroll
        for (int mt = 0; mt < 4; ++mt) {
            const int tloc = wm * 64 + mt * 16 + lr;
            #pragma unroll
            for (int nt = 0; nt < 4; ++nt) {
                const int nl = wn * 32 + nt * 8 + lc * 2;
                sC[(size_t)nl * 132 + tloc]           = acc[mt][nt][0] + bias[nloc0 + nl];
                sC[(size_t)(nl + 1) * 132 + tloc]     = acc[mt][nt][1] + bias[nloc0 + nl + 1];
                sC[(size_t)nl * 132 + tloc + 8]       = acc[mt][nt][2] + bias[nloc0 + nl];
                sC[(size_t)(nl + 1) * 132 + tloc + 8] = acc[mt][nt][3] + bias[nloc0 + nl + 1];
            }
        }
        __syncthreads();
        const int b = m0 >> 10, t0 = m0 & 1023;
        #pragma unroll
        for (int i = 0; i < 16; ++i) {
            const int idx = tid + i * 256;
            const int nl  = idx >> 5;
            const int tc  = (idx & 31) * 4;
            const float4 v = *(const float4*)&sC[(size_t)nl * 132 + tc];
            *(float4*)(C + ((size_t)b * D + nloc0 + nl) * T + t0 + tc) = v;
        }
    }
}

// ---------------- fp16 flash attention, fixed-base softmax (exp2/f16x2) -------
#define KT      32
#define NITER   (T/KT)
#define KVROWH  72
#define STG_B   9216
#define ATTN_SMEMB (3 * STG_B)

__global__ __launch_bounds__(256, 2)
void attn_mma()
{
    extern __shared__ __half smh[];
    const int tid  = threadIdx.x;
    const int w    = tid >> 5;
    const int lane = tid & 31;
    const int lr   = lane >> 2;
    const int lc   = lane & 3;

    const int qt = blockIdx.x;
    const int h  = blockIdx.y;
    const int b  = blockIdx.z;
    const int row0 = b * T + qt * 128;
    const unsigned sb = (unsigned)__cvta_generic_to_shared(smh);

    auto load_kv = [&](int kt, int stg) {
        const int tk = tid >> 3;
        const int c  = (tid & 7) * 8;
        const size_t g = ((size_t)(b * T + kt * KT + tk) * NH + h) * 64 + c;
        const unsigned d = sb + (unsigned)(stg * STG_B) +
                           (unsigned)((tk * KVROWH + c) * 2);
        CPASYNC(d,        g_k16 + g);
        CPASYNC(d + 4608, g_v16 + g);
        CP_COMMIT();
    };
    load_kv(0, 0);
    load_kv(1, 1);

    unsigned qh[4][4], ql[4][4];
    {
        const __half* r0p = g_q16 + ((size_t)(row0 + w * 16 + lr) * NH + h) * 128;
        const __half* r1p = r0p + (size_t)8 * NH * 128;
        #pragma unroll
        for (int ks = 0; ks < 4; ++ks) {
            const int c = ks * 16 + 2 * lc;
            qh[ks][0] = *(const unsigned*)(r0p + c);
            qh[ks][1] = *(const unsigned*)(r1p + c);
            qh[ks][2] = *(const unsigned*)(r0p + c + 8);
            qh[ks][3] = *(const unsigned*)(r1p + c + 8);
            ql[ks][0] = *(const unsigned*)(r0p + c + 64);
            ql[ks][1] = *(const unsigned*)(r1p + c + 64);
            ql[ks][2] = *(const unsigned*)(r0p + c + 72);
            ql[ks][3] = *(const unsigned*)(r1p + c + 72);
        }
    }

    float Oa[8][4];
    #pragma unroll
    for (int nt = 0; nt < 8; ++nt)
        #pragma unroll
        for (int q = 0; q < 4; q++) Oa[nt][q] = 0.f;
    float l0 = 0.f, l1 = 0.f;

    const int kRow  = (lane & 7) + ((lane & 16) ? 8 : 0);
    const int kColH = (lane & 8) ? 8 : 0;
    const int vRow  = (lane & 7) + ((lane & 8) ? 8 : 0);
    const int vColH = (lane & 16) ? 8 : 0;

    for (int kt = 0; kt < NITER; ++kt) {
        if (kt + 1 < NITER) { CP_WAIT(1); } else { CP_WAIT(0); }
        __syncthreads();
        if (kt + 2 < NITER) load_kv(kt + 2, (kt + 2) % 3);

        const unsigned sK = sb + (unsigned)((kt % 3) * STG_B);
        const unsigned sV = sK + 4608;

        float sacc[4][4];
        #pragma unroll
        for (int nt = 0; nt < 4; ++nt)
            #pragma unroll
            for (int q = 0; q < 4; q++) sacc[nt][q] = 0.f;

        #pragma unroll
        for (int ks = 0; ks < 4; ++ks) {
            unsigned kh[4][2];
            {
                const unsigned a0 = sK +
                    (unsigned)((kRow * KVROWH + ks * 16 + kColH) * 2);
                unsigned r0, r1, r2, r3;
                LDSM4(r0, r1, r2, r3, a0);
                kh[0][0] = r0; kh[0][1] = r1; kh[1][0] = r2; kh[1][1] = r3;
                LDSM4(r0, r1, r2, r3, a0 + (unsigned)(16 * KVROWH * 2));
                kh[2][0] = r0; kh[2][1] = r1; kh[3][0] = r2; kh[3][1] = r3;
            }
            #pragma unroll
            for (int nt = 0; nt < 4; ++nt) {
                mma_f16(sacc[nt], qh[ks], kh[nt]);
                mma_f16(sacc[nt], ql[ks], kh[nt]);
            }
        }

        unsigned p16[2][4];
        #pragma unroll
        for (int nt = 0; nt < 4; ++nt) {
            p16[nt >> 1][(nt & 1) * 2]     = exp2_f16x2(sacc[nt][0], sacc[nt][1]);
            p16[nt >> 1][(nt & 1) * 2 + 1] = exp2_f16x2(sacc[nt][2], sacc[nt][3]);
        }
        {
            const unsigned s0a = hadd2u(p16[0][0], p16[0][2]);
            const unsigned s0b = hadd2u(p16[1][0], p16[1][2]);
            const unsigned s1a = hadd2u(p16[0][1], p16[0][3]);
            const unsigned s1b = hadd2u(p16[1][1], p16[1][3]);
            const float2 f0a = __half22float2(*(const __half2*)&s0a);
            const float2 f0b = __half22float2(*(const __half2*)&s0b);
            const float2 f1a = __half22float2(*(const __half2*)&s1a);
            const float2 f1b = __half22float2(*(const __half2*)&s1b);
            l0 += (f0a.x + f0a.y) + (f0b.x + f0b.y);
            l1 += (f1a.x + f1a.y) + (f1b.x + f1b.y);
        }

        #pragma unroll
        for (int g = 0; g < 2; ++g) {
            #pragma unroll
            for (int p = 0; p < 4; ++p) {
                const unsigned a0 = sV +
                    (unsigned)(((g * 16 + vRow) * KVROWH + p * 16 + vColH) * 2);
                unsigned vh[2][2];
                unsigned r0, r1, r2, r3;
                LDSM4T(r0, r1, r2, r3, a0);
                vh[0][0] = r0; vh[0][1] = r1; vh[1][0] = r2; vh[1][1] = r3;
                mma_f16(Oa[2*p],     p16[g], vh[0]);
                mma_f16(Oa[2*p + 1], p16[g], vh[1]);
            }
        }
    }

    l0 += __shfl_xor_sync(0xffffffffu, l0, 1);
    l0 += __shfl_xor_sync(0xffffffffu, l0, 2);
    l1 += __shfl_xor_sync(0xffffffffu, l1, 1);
    l1 += __shfl_xor_sync(0xffffffffu, l1, 2);

    const float inv0 = 1.0f / l0;
    const float inv1 = 1.0f / l1;
    const int gr0 = row0 + w * 16 + lr;
    const int gr1 = gr0 + 8;
    const int col0 = h * DH;
    #pragma unroll
    for (int nt = 0; nt < 8; ++nt) {
        const int c = col0 + nt * 8 + 2 * lc;
        const float2 ga = *(const float2*)(g_g + (size_t)gr0 * D + c);
        const float2 gb = *(const float2*)(g_g + (size_t)gr1 * D + c);
        *(__half2*)(g_y16 + (size_t)gr0 * D + c) =
            __floats2half2_rn(Oa[nt][0] * inv0 * ga.x, Oa[nt][1] * inv0 * ga.y);
        *(__half2*)(g_y16 + (size_t)gr1 * D + c) =
            __floats2half2_rn(Oa[nt][2] * inv1 * gb.x, Oa[nt][3] * inv1 * gb.y);
    }
}

// ---------------- launch --------------------------------------------------------
extern "C" void kernel_launch(void* const* d_in, const int* in_sizes, int n_in,
                              void* d_out, int out_size)
{
    const float* x     = (const float*)d_in[0];
    const float* Wq    = (const float*)d_in[1];
    const float* bq    = (const float*)d_in[2];
    const float* Wk    = (const float*)d_in[3];
    const float* bk    = (const float*)d_in[4];
    const float* Wv    = (const float*)d_in[5];
    const float* bv    = (const float*)d_in[6];
    const float* Wo    = (const float*)d_in[7];
    const float* bo    = (const float*)d_in[8];
    const float* Wg    = (const float*)d_in[9];
    const float* bg    = (const float*)d_in[10];
    const float* gamma = (const float*)d_in[11];
    const float* beta  = (const float*)d_in[12];
    float* out = (float*)d_out;

    void *p;
    __half *xn, *y16;
    __half *wqh,*wql,*wkh,*wvh,*wgh,*woh,*wol;
    float *gb_;
    cudaGetSymbolAddress(&p, g_xn);    xn = (__half*)p;
    cudaGetSymbolAddress(&p, g_y16);  y16 = (__half*)p;
    cudaGetSymbolAddress(&p, g_g);    gb_ = (float*)p;
    cudaGetSymbolAddress(&p, g_wq_hi); wqh = (__half*)p;
    cudaGetSymbolAddress(&p, g_wq_lo); wql = (__half*)p;
    cudaGetSymbolAddress(&p, g_wk_hi); wkh = (__half*)p;
    cudaGetSymbolAddress(&p, g_wv_hi); wvh = (__half*)p;
    cudaGetSymbolAddress(&p, g_wg_hi); wgh = (__half*)p;
    cudaGetSymbolAddress(&p, g_wo_hi); woh = (__half*)p;
    cudaGetSymbolAddress(&p, g_wo_lo); wol = (__half*)p;

    const int gemm_smem = GSTAGES * STGB;   // 92160
    cudaFuncSetAttribute(gemm_mma<0>, cudaFuncAttributeMaxDynamicSharedMemorySize, gemm_smem);
    cudaFuncSetAttribute(gemm_mma<1>, cudaFuncAttributeMaxDynamicSharedMemorySize, gemm_smem);
    cudaFuncSetAttribute(attn_mma, cudaFuncAttributeMaxDynamicSharedMemorySize, ATTN_SMEMB);
    cudaFuncSetAttribute(ln_kernel, cudaFuncAttributeMaxDynamicSharedMemorySize, LN_SMEMB);

    const int wblocks = (D * D + 255) / 256;
    {
        SplitArgs sa;
        sa.w[0] = Wq; sa.h[0] = wqh; sa.l[0] = wql;
        sa.w[1] = Wk; sa.h[1] = wkh; sa.l[1] = wkh;   // l unused
        sa.w[2] = Wv; sa.h[2] = wvh; sa.l[2] = wvh;   // l unused
        sa.w[3] = Wg; sa.h[3] = wgh; sa.l[3] = wgh;   // l unused
        sa.w[4] = Wo; sa.h[4] = woh; sa.l[4] = wol;
        split5<<<dim3(wblocks, 5), 256>>>(sa);
    }

    ln_kernel<<<256, 256, LN_SMEMB>>>(x, gamma, beta);

    {
        GemmArgs a;
        a.Bh[0] = wqh; a.Bl[0] = wql; a.bias[0] = bq; a.C[0] = nullptr;
        a.Bh[1] = wkh; a.Bl[1] = wkh; a.bias[1] = bk; a.C[1] = nullptr;
        a.Bh[2] = wvh; a.Bl[2] = wvh; a.bias[2] = bv; a.C[2] = nullptr;
        a.Bh[3] = wgh; a.Bl[3] = wgh; a.bias[3] = bg; a.C[3] = gb_;
        gemm_mma<0><<<dim3(24, 64), 256, gemm_smem>>>(xn, a);
    }

    attn_mma<<<dim3(8, NH, BATCH), 256, ATTN_SMEMB>>>();

    {
        GemmArgs a;
        a.Bh[0] = woh; a.Bl[0] = wol; a.bias[0] = bo; a.C[0] = out;
        a.Bh[1] = a.Bh[2] = a.Bh[3] = woh;
        a.Bl[1] = a.Bl[2] = a.Bl[3] = wol;
        a.bias[1] = a.bias[2] = a.bias[3] = bo;
        a.C[1] = a.C[2] = a.C[3] = out;
        gemm_mma<1><<<dim3(6, 64), 256, gemm_smem>>>(y16, a);
    }
}

// round 12
// speedup vs baseline: 10.1065x; 1.1937x over previous
#include <cuda_runtime.h>
#include <cuda_fp16.h>
#include <math.h>

#define D      768
#define T      1024
#define BATCH  8
#define M_TOT  (BATCH*T)   // 8192
#define NH     12
#define DH     64

// ---------------- scratch (device globals: alloc-free rule) ----------------
__device__ __half g_xn [(size_t)M_TOT * D];            // fp16 single
__device__ __half g_q16[(size_t)M_TOT * NH * 64];      // [tok][head][64] single, QSCALE folded
__device__ __half g_k16[(size_t)M_TOT * NH * 64];      // [tok][head][64] single
__device__ __half g_v16[(size_t)M_TOT * NH * 64];      // [tok][head][64] single
__device__ float  g_g  [(size_t)M_TOT * D];
__device__ __half g_y16[(size_t)M_TOT * D];            // fp16 single
__device__ __half g_wq_hi[D*D];
__device__ __half g_wk_hi[D*D];
__device__ __half g_wv_hi[D*D];
__device__ __half g_wg_hi[D*D];
__device__ __half g_wo_hi[D*D], g_wo_lo[D*D];

// 0.125 * log2(e): fold attention scale + exp2 conversion into Q
#define QSCALE 0.18033688011112042f

// ---------------- PTX helpers -----------------------------------------------
#define CPASYNC(dst, src) \
    asm volatile("cp.async.cg.shared.global [%0], [%1], 16;" :: "r"(dst), "l"(src) : "memory")
#define CP_COMMIT() asm volatile("cp.async.commit_group;" ::: "memory")
#define CP_WAIT(n)  asm volatile("cp.async.wait_group %0;" :: "n"(n) : "memory")
#define LDSM4(R0,R1,R2,R3,A) \
    asm volatile("ldmatrix.sync.aligned.m8n8.x4.shared.b16 {%0,%1,%2,%3}, [%4];" \
                 : "=r"(R0), "=r"(R1), "=r"(R2), "=r"(R3) : "r"(A))
#define LDSM4T(R0,R1,R2,R3,A) \
    asm volatile("ldmatrix.sync.aligned.m8n8.x4.trans.shared.b16 {%0,%1,%2,%3}, [%4];" \
                 : "=r"(R0), "=r"(R1), "=r"(R2), "=r"(R3) : "r"(A))

__device__ __forceinline__ void mma_f16(float* d, const unsigned* a, const unsigned* b) {
    asm volatile(
        "mma.sync.aligned.m16n8k16.row.col.f32.f16.f16.f32 "
        "{%0,%1,%2,%3}, {%4,%5,%6,%7}, {%8,%9}, {%0,%1,%2,%3};"
        : "+f"(d[0]), "+f"(d[1]), "+f"(d[2]), "+f"(d[3])
        : "r"(a[0]), "r"(a[1]), "r"(a[2]), "r"(a[3]), "r"(b[0]), "r"(b[1]));
}

__device__ __forceinline__ unsigned exp2_f16x2(float a, float b) {
    unsigned r;
    asm volatile("{\n\t.reg .b32 t;\n\t"
                 "cvt.rn.f16x2.f32 t, %2, %1;\n\t"
                 "ex2.approx.f16x2 %0, t;\n\t}"
                 : "=r"(r) : "f"(a), "f"(b));
    return r;
}
__device__ __forceinline__ unsigned hadd2u(unsigned a, unsigned b) {
    unsigned r;
    asm volatile("add.f16x2 %0, %1, %2;" : "=r"(r) : "r"(a), "r"(b));
    return r;
}

// ---------------- weight prep: Wo split hi/lo; q/k/v/g hi only ----------------
struct SplitArgs {
    const float* w[5];
    __half* h[5];
    __half* l[5];
};

__global__ __launch_bounds__(256)
void split5(SplitArgs a)
{
    const int i = blockIdx.x * 256 + threadIdx.x;
    if (i >= D * D) return;
    const int m = blockIdx.y;
    const float v = a.w[m][i];
    const __half h = __float2half_rn(v);
    a.h[m][i] = h;
    if (m == 4)
        a.l[m][i] = __float2half_rn(v - __half2float(h));
}

// ---------------- LayerNorm: coalesced transpose-tile ------------------------
#define LN_SMEMB (768 * 33 * 4 + 256)

__global__ __launch_bounds__(256)
void ln_kernel(const float* __restrict__ x,
               const float* __restrict__ gamma,
               const float* __restrict__ beta)
{
    extern __shared__ float lsm[];
    float* st = lsm;
    float* mu = lsm + 768 * 33;
    float* rs = mu + 32;

    const int tid = threadIdx.x;
    const int b   = blockIdx.x >> 5;
    const int t0  = (blockIdx.x & 31) * 32;
    const float* xp = x + (size_t)b * D * T + t0;

    float gm[3], bt[3];
    #pragma unroll
    for (int j = 0; j < 3; ++j) {
        gm[j] = gamma[j * 256 + tid];
        bt[j] = beta [j * 256 + tid];
    }

    #pragma unroll 4
    for (int i = 0; i < 96; ++i) {
        const int idx = i * 256 + tid;
        const int c   = idx >> 5;
        const int tt  = idx & 31;
        st[c * 33 + tt] = xp[(size_t)c * T + tt];
    }
    __syncthreads();

    const int wid = tid >> 5, lane = tid & 31;
    #pragma unroll
    for (int rep = 0; rep < 4; ++rep) {
        const int tt = wid + rep * 8;
        float s = 0.f, ss = 0.f;
        #pragma unroll
        for (int j = 0; j < 24; ++j) {
            const float v = st[(lane + 32 * j) * 33 + tt];
            s += v; ss += v * v;
        }
        #pragma unroll
        for (int o = 16; o > 0; o >>= 1) {
            s  += __shfl_xor_sync(0xffffffffu, s,  o);
            ss += __shfl_xor_sync(0xffffffffu, ss, o);
        }
        if (lane == 0) {
            const float m = s * (1.0f / (float)D);
            const float var = ss * (1.0f / (float)D) - m * m;
            mu[tt] = m;
            rs[tt] = rsqrtf(var + 1e-5f);
        }
    }
    __syncthreads();

    for (int tt = 0; tt < 32; ++tt) {
        const float m = mu[tt], r = rs[tt];
        __half* o = g_xn + (size_t)(b * T + t0 + tt) * D;
        #pragma unroll
        for (int j = 0; j < 3; ++j) {
            const int c = j * 256 + tid;
            o[c] = __float2half_rn((st[c * 33 + tt] - m) * r * gm[j] + bt[j]);
        }
    }
}

// ---------------- fp16 tensor-core GEMM (BK=32, 3-stage) ----------------------
// MODE 0: 1-pass (qkvg).  MODE 1: 2-pass hi/lo (Wo) + transposed output.
struct GemmArgs {
    const __half* Bh[4];
    const __half* Bl[4];
    const float* bias[4];
    float*       C[4];
};

#define URO   20
#define CROWB 80
#define CSTGB 10240
#define STGB  30720
#define GSTAGES 3

template<int MODE>
__global__ __launch_bounds__(256, 2)
void gemm_mma(const __half* __restrict__ Ag, GemmArgs args)
{
    extern __shared__ unsigned smu[];
    const int tid = threadIdx.x;
    const int m0  = blockIdx.y * 128;

    int region, nloc0;
    if (MODE == 0) { region = blockIdx.x / 6; nloc0 = (blockIdx.x % 6) * 128; }
    else           { region = 0;              nloc0 = blockIdx.x * 128; }
    const __half* Bh = args.Bh[region];
    const __half* Bl = args.Bl[region];
    const float* bias = args.bias[region];
    float*       C    = args.C[region];

    const int rw  = tid >> 1;
    const int ch0 = (tid & 1) * 16;
    const __half* pA  = Ag + (size_t)(m0 + rw) * D + ch0;
    const __half* pBh = Bh + (size_t)(nloc0 + rw) * D + ch0;
    const __half* pBl = Bl + (size_t)(nloc0 + rw) * D + ch0;
    const unsigned sbase = (unsigned)__cvta_generic_to_shared(smu);
    const unsigned soff  = (unsigned)(rw * CROWB + ch0 * 2);

    auto load_stage = [&](int kt, int buf) {
        const unsigned b0 = sbase + (unsigned)buf * STGB + soff;
        CPASYNC(b0,              pA  + kt);
        CPASYNC(b0 + 16u,        pA  + kt + 8);
        CPASYNC(b0 + CSTGB,      pBh + kt);
        CPASYNC(b0 + CSTGB + 16u,pBh + kt + 8);
        if (MODE == 1) {
            CPASYNC(b0 + 2*CSTGB,      pBl + kt);
            CPASYNC(b0 + 2*CSTGB + 16u,pBl + kt + 8);
        }
        CP_COMMIT();
    };

    const int w    = tid >> 5;
    const int lane = tid & 31;
    const int wm   = w >> 2;
    const int wn   = w & 3;
    const int lr   = lane >> 2;
    const int lc   = lane & 3;

    const int aRow  = (lane & 7) + ((lane & 8) ? 8 : 0);
    const int aColU = (lane & 16) ? 4 : 0;
    const int bRow  = (lane & 7) + ((lane & 16) ? 8 : 0);
    const int bColU = (lane & 8) ? 4 : 0;
    const unsigned aOff = (unsigned)(((wm * 64 + aRow) * URO + aColU) * 4);
    const unsigned bOff = (unsigned)(((wn * 32 + bRow) * URO + bColU) * 4);

    float acc[4][4][4];
    #pragma unroll
    for (int i = 0; i < 4; i++)
        #pragma unroll
        for (int j = 0; j < 4; j++)
            #pragma unroll
            for (int q = 0; q < 4; q++) acc[i][j][q] = 0.f;

    const int NIT = D / 32;
    load_stage(0, 0);
    load_stage(32, 1);

    for (int it = 0; it < NIT; ++it) {
        if (it + 1 < NIT) { CP_WAIT(1); } else { CP_WAIT(0); }
        __syncthreads();
        if (it + 2 < NIT) load_stage((it + 2) * 32, (it + 2) % GSTAGES);

        const unsigned stgb = sbase + (unsigned)((it % GSTAGES) * STGB);

        #pragma unroll
        for (int ks = 0; ks < 2; ++ks) {
            const unsigned ko = (unsigned)(ks * 32);
            const unsigned aA = stgb + aOff + ko;
            const unsigned bH = stgb + CSTGB + bOff + ko;
            const unsigned bL = stgb + 2 * CSTGB + bOff + ko;

            unsigned ah[4][4];
            #pragma unroll
            for (int mt = 0; mt < 4; ++mt)
                LDSM4(ah[mt][0], ah[mt][1], ah[mt][2], ah[mt][3],
                      aA + (unsigned)(mt * 16 * URO * 4));

            unsigned bh[4][2];
            {
                unsigned r0, r1, r2, r3;
                LDSM4(r0, r1, r2, r3, bH);
                bh[0][0] = r0; bh[0][1] = r1; bh[1][0] = r2; bh[1][1] = r3;
                LDSM4(r0, r1, r2, r3, bH + (unsigned)(16 * URO * 4));
                bh[2][0] = r0; bh[2][1] = r1; bh[3][0] = r2; bh[3][1] = r3;
            }
            #pragma unroll
            for (int mt = 0; mt < 4; ++mt)
                #pragma unroll
                for (int nt = 0; nt < 4; ++nt)
                    mma_f16(acc[mt][nt], ah[mt], bh[nt]);

            if (MODE == 1) {
                unsigned bl[4][2];
                unsigned r0, r1, r2, r3;
                LDSM4(r0, r1, r2, r3, bL);
                bl[0][0] = r0; bl[0][1] = r1; bl[1][0] = r2; bl[1][1] = r3;
                LDSM4(r0, r1, r2, r3, bL + (unsigned)(16 * URO * 4));
                bl[2][0] = r0; bl[2][1] = r1; bl[3][0] = r2; bl[3][1] = r3;
                #pragma unroll
                for (int mt = 0; mt < 4; ++mt)
                    #pragma unroll
                    for (int nt = 0; nt < 4; ++nt)
                        mma_f16(acc[mt][nt], ah[mt], bl[nt]);
            }
        }
    }

    if (MODE == 0) {
        #pragma unroll
        for (int mt = 0; mt < 4; ++mt) {
            const int r = m0 + wm * 64 + mt * 16 + lr;
            #pragma unroll
            for (int nt = 0; nt < 4; ++nt) {
                const int n = nloc0 + wn * 32 + nt * 8 + lc * 2;
                float v00 = acc[mt][nt][0] + bias[n];
                float v01 = acc[mt][nt][1] + bias[n + 1];
                float v10 = acc[mt][nt][2] + bias[n];
                float v11 = acc[mt][nt][3] + bias[n + 1];
                const int head = n >> 6, wi = n & 63;
                if (region < 3) {
                    __half* dst = (region == 0) ? g_q16 : (region == 1) ? g_k16 : g_v16;
                    const float sc = (region == 0) ? QSCALE : 1.0f;
                    const size_t b0 = ((size_t)r * NH + head) * 64 + wi;
                    const size_t b1 = ((size_t)(r + 8) * NH + head) * 64 + wi;
                    *(__half2*)(dst + b0) = __floats2half2_rn(v00 * sc, v01 * sc);
                    *(__half2*)(dst + b1) = __floats2half2_rn(v10 * sc, v11 * sc);
                } else {
                    v00 = 1.0f / (1.0f + __expf(-v00));
                    v01 = 1.0f / (1.0f + __expf(-v01));
                    v10 = 1.0f / (1.0f + __expf(-v10));
                    v11 = 1.0f / (1.0f + __expf(-v11));
                    *(float2*)(C + (size_t)r * D + n)       = make_float2(v00, v01);
                    *(float2*)(C + (size_t)(r + 8) * D + n) = make_float2(v10, v11);
                }
            }
        }
    } else {
        // coalesced output transpose via smem (stride 132, conflict-free)
        __syncthreads();
        float* sC = (float*)smu;
        #pragma unroll
        for (int mt = 0; mt < 4; ++mt) {
            const int tloc = wm * 64 + mt * 16 + lr;
            #pragma unroll
            for (int nt = 0; nt < 4; ++nt) {
                const int nl = wn * 32 + nt * 8 + lc * 2;
                sC[(size_t)nl * 132 + tloc]           = acc[mt][nt][0] + bias[nloc0 + nl];
                sC[(size_t)(nl + 1) * 132 + tloc]     = acc[mt][nt][1] + bias[nloc0 + nl + 1];
                sC[(size_t)nl * 132 + tloc + 8]       = acc[mt][nt][2] + bias[nloc0 + nl];
                sC[(size_t)(nl + 1) * 132 + tloc + 8] = acc[mt][nt][3] + bias[nloc0 + nl + 1];
            }
        }
        __syncthreads();
        const int b = m0 >> 10, t0 = m0 & 1023;
        #pragma unroll
        for (int i = 0; i < 16; ++i) {
            const int idx = tid + i * 256;
            const int nl  = idx >> 5;
            const int tc  = (idx & 31) * 4;
            const float4 v = *(const float4*)&sC[(size_t)nl * 132 + tc];
            *(float4*)(C + ((size_t)b * D + nloc0 + nl) * T + t0 + tc) = v;
        }
    }
}

// ---------------- fp16 flash attention, 1-pass QK, fixed-base softmax ---------
#define KT      32
#define NITER   (T/KT)
#define KVROWH  72
#define STG_B   9216
#define ATTN_SMEMB (3 * STG_B)

__global__ __launch_bounds__(256, 2)
void attn_mma()
{
    extern __shared__ __half smh[];
    const int tid  = threadIdx.x;
    const int w    = tid >> 5;
    const int lane = tid & 31;
    const int lr   = lane >> 2;
    const int lc   = lane & 3;

    const int qt = blockIdx.x;
    const int h  = blockIdx.y;
    const int b  = blockIdx.z;
    const int row0 = b * T + qt * 128;
    const unsigned sb = (unsigned)__cvta_generic_to_shared(smh);

    auto load_kv = [&](int kt, int stg) {
        const int tk = tid >> 3;
        const int c  = (tid & 7) * 8;
        const size_t g = ((size_t)(b * T + kt * KT + tk) * NH + h) * 64 + c;
        const unsigned d = sb + (unsigned)(stg * STG_B) +
                           (unsigned)((tk * KVROWH + c) * 2);
        CPASYNC(d,        g_k16 + g);
        CPASYNC(d + 4608, g_v16 + g);
        CP_COMMIT();
    };
    load_kv(0, 0);
    load_kv(1, 1);

    unsigned qh[4][4];
    {
        const __half* r0p = g_q16 + ((size_t)(row0 + w * 16 + lr) * NH + h) * 64;
        const __half* r1p = r0p + (size_t)8 * NH * 64;
        #pragma unroll
        for (int ks = 0; ks < 4; ++ks) {
            const int c = ks * 16 + 2 * lc;
            qh[ks][0] = *(const unsigned*)(r0p + c);
            qh[ks][1] = *(const unsigned*)(r1p + c);
            qh[ks][2] = *(const unsigned*)(r0p + c + 8);
            qh[ks][3] = *(const unsigned*)(r1p + c + 8);
        }
    }

    float Oa[8][4];
    #pragma unroll
    for (int nt = 0; nt < 8; ++nt)
        #pragma unroll
        for (int q = 0; q < 4; q++) Oa[nt][q] = 0.f;
    float l0 = 0.f, l1 = 0.f;

    const int kRow  = (lane & 7) + ((lane & 16) ? 8 : 0);
    const int kColH = (lane & 8) ? 8 : 0;
    const int vRow  = (lane & 7) + ((lane & 8) ? 8 : 0);
    const int vColH = (lane & 16) ? 8 : 0;

    for (int kt = 0; kt < NITER; ++kt) {
        if (kt + 1 < NITER) { CP_WAIT(1); } else { CP_WAIT(0); }
        __syncthreads();
        if (kt + 2 < NITER) load_kv(kt + 2, (kt + 2) % 3);

        const unsigned sK = sb + (unsigned)((kt % 3) * STG_B);
        const unsigned sV = sK + 4608;

        float sacc[4][4];
        #pragma unroll
        for (int nt = 0; nt < 4; ++nt)
            #pragma unroll
            for (int q = 0; q < 4; q++) sacc[nt][q] = 0.f;

        #pragma unroll
        for (int ks = 0; ks < 4; ++ks) {
            unsigned kh[4][2];
            {
                const unsigned a0 = sK +
                    (unsigned)((kRow * KVROWH + ks * 16 + kColH) * 2);
                unsigned r0, r1, r2, r3;
                LDSM4(r0, r1, r2, r3, a0);
                kh[0][0] = r0; kh[0][1] = r1; kh[1][0] = r2; kh[1][1] = r3;
                LDSM4(r0, r1, r2, r3, a0 + (unsigned)(16 * KVROWH * 2));
                kh[2][0] = r0; kh[2][1] = r1; kh[3][0] = r2; kh[3][1] = r3;
            }
            #pragma unroll
            for (int nt = 0; nt < 4; ++nt)
                mma_f16(sacc[nt], qh[ks], kh[nt]);
        }

        unsigned p16[2][4];
        #pragma unroll
        for (int nt = 0; nt < 4; ++nt) {
            p16[nt >> 1][(nt & 1) * 2]     = exp2_f16x2(sacc[nt][0], sacc[nt][1]);
            p16[nt >> 1][(nt & 1) * 2 + 1] = exp2_f16x2(sacc[nt][2], sacc[nt][3]);
        }
        {
            const unsigned s0a = hadd2u(p16[0][0], p16[0][2]);
            const unsigned s0b = hadd2u(p16[1][0], p16[1][2]);
            const unsigned s1a = hadd2u(p16[0][1], p16[0][3]);
            const unsigned s1b = hadd2u(p16[1][1], p16[1][3]);
            const float2 f0a = __half22float2(*(const __half2*)&s0a);
            const float2 f0b = __half22float2(*(const __half2*)&s0b);
            const float2 f1a = __half22float2(*(const __half2*)&s1a);
            const float2 f1b = __half22float2(*(const __half2*)&s1b);
            l0 += (f0a.x + f0a.y) + (f0b.x + f0b.y);
            l1 += (f1a.x + f1a.y) + (f1b.x + f1b.y);
        }

        #pragma unroll
        for (int g = 0; g < 2; ++g) {
            #pragma unroll
            for (int p = 0; p < 4; ++p) {
                const unsigned a0 = sV +
                    (unsigned)(((g * 16 + vRow) * KVROWH + p * 16 + vColH) * 2);
                unsigned vh[2][2];
                unsigned r0, r1, r2, r3;
                LDSM4T(r0, r1, r2, r3, a0);
                vh[0][0] = r0; vh[0][1] = r1; vh[1][0] = r2; vh[1][1] = r3;
                mma_f16(Oa[2*p],     p16[g], vh[0]);
                mma_f16(Oa[2*p + 1], p16[g], vh[1]);
            }
        }
    }

    l0 += __shfl_xor_sync(0xffffffffu, l0, 1);
    l0 += __shfl_xor_sync(0xffffffffu, l0, 2);
    l1 += __shfl_xor_sync(0xffffffffu, l1, 1);
    l1 += __shfl_xor_sync(0xffffffffu, l1, 2);

    const float inv0 = 1.0f / l0;
    const float inv1 = 1.0f / l1;
    const int gr0 = row0 + w * 16 + lr;
    const int gr1 = gr0 + 8;
    const int col0 = h * DH;
    #pragma unroll
    for (int nt = 0; nt < 8; ++nt) {
        const int c = col0 + nt * 8 + 2 * lc;
        const float2 ga = *(const float2*)(g_g + (size_t)gr0 * D + c);
        const float2 gb = *(const float2*)(g_g + (size_t)gr1 * D + c);
        *(__half2*)(g_y16 + (size_t)gr0 * D + c) =
            __floats2half2_rn(Oa[nt][0] * inv0 * ga.x, Oa[nt][1] * inv0 * ga.y);
        *(__half2*)(g_y16 + (size_t)gr1 * D + c) =
            __floats2half2_rn(Oa[nt][2] * inv1 * gb.x, Oa[nt][3] * inv1 * gb.y);
    }
}

// ---------------- launch --------------------------------------------------------
extern "C" void kernel_launch(void* const* d_in, const int* in_sizes, int n_in,
                              void* d_out, int out_size)
{
    const float* x     = (const float*)d_in[0];
    const float* Wq    = (const float*)d_in[1];
    const float* bq    = (const float*)d_in[2];
    const float* Wk    = (const float*)d_in[3];
    const float* bk    = (const float*)d_in[4];
    const float* Wv    = (const float*)d_in[5];
    const float* bv    = (const float*)d_in[6];
    const float* Wo    = (const float*)d_in[7];
    const float* bo    = (const float*)d_in[8];
    const float* Wg    = (const float*)d_in[9];
    const float* bg    = (const float*)d_in[10];
    const float* gamma = (const float*)d_in[11];
    const float* beta  = (const float*)d_in[12];
    float* out = (float*)d_out;

    void *p;
    __half *xn, *y16;
    __half *wqh,*wkh,*wvh,*wgh,*woh,*wol;
    float *gb_;
    cudaGetSymbolAddress(&p, g_xn);    xn = (__half*)p;
    cudaGetSymbolAddress(&p, g_y16);  y16 = (__half*)p;
    cudaGetSymbolAddress(&p, g_g);    gb_ = (float*)p;
    cudaGetSymbolAddress(&p, g_wq_hi); wqh = (__half*)p;
    cudaGetSymbolAddress(&p, g_wk_hi); wkh = (__half*)p;
    cudaGetSymbolAddress(&p, g_wv_hi); wvh = (__half*)p;
    cudaGetSymbolAddress(&p, g_wg_hi); wgh = (__half*)p;
    cudaGetSymbolAddress(&p, g_wo_hi); woh = (__half*)p;
    cudaGetSymbolAddress(&p, g_wo_lo); wol = (__half*)p;

    const int gemm_smem = GSTAGES * STGB;   // 92160
    cudaFuncSetAttribute(gemm_mma<0>, cudaFuncAttributeMaxDynamicSharedMemorySize, gemm_smem);
    cudaFuncSetAttribute(gemm_mma<1>, cudaFuncAttributeMaxDynamicSharedMemorySize, gemm_smem);
    cudaFuncSetAttribute(attn_mma, cudaFuncAttributeMaxDynamicSharedMemorySize, ATTN_SMEMB);
    cudaFuncSetAttribute(ln_kernel, cudaFuncAttributeMaxDynamicSharedMemorySize, LN_SMEMB);

    const int wblocks = (D * D + 255) / 256;
    {
        SplitArgs sa;
        sa.w[0] = Wq; sa.h[0] = wqh; sa.l[0] = wqh;   // l unused
        sa.w[1] = Wk; sa.h[1] = wkh; sa.l[1] = wkh;   // l unused
        sa.w[2] = Wv; sa.h[2] = wvh; sa.l[2] = wvh;   // l unused
        sa.w[3] = Wg; sa.h[3] = wgh; sa.l[3] = wgh;   // l unused
        sa.w[4] = Wo; sa.h[4] = woh; sa.l[4] = wol;
        split5<<<dim3(wblocks, 5), 256>>>(sa);
    }

    ln_kernel<<<256, 256, LN_SMEMB>>>(x, gamma, beta);

    {
        GemmArgs a;
        a.Bh[0] = wqh; a.Bl[0] = wqh; a.bias[0] = bq; a.C[0] = nullptr;
        a.Bh[1] = wkh; a.Bl[1] = wkh; a.bias[1] = bk; a.C[1] = nullptr;
        a.Bh[2] = wvh; a.Bl[2] = wvh; a.bias[2] = bv; a.C[2] = nullptr;
        a.Bh[3] = wgh; a.Bl[3] = wgh; a.bias[3] = bg; a.C[3] = gb_;
        gemm_mma<0><<<dim3(24, 64), 256, gemm_smem>>>(xn, a);
    }

    attn_mma<<<dim3(8, NH, BATCH), 256, ATTN_SMEMB>>>();

    {
        GemmArgs a;
        a.Bh[0] = woh; a.Bl[0] = wol; a.bias[0] = bo; a.C[0] = out;
        a.Bh[1] = a.Bh[2] = a.Bh[3] = woh;
        a.Bl[1] = a.Bl[2] = a.Bl[3] = wol;
        a.bias[1] = a.bias[2] = a.bias[3] = bo;
        a.C[1] = a.C[2] = a.C[3] = out;
        gemm_mma<1><<<dim3(6, 64), 256, gemm_smem>>>(y16, a);
    }
}